// round 11
// baseline (speedup 1.0000x reference)
#include <cuda_runtime.h>
#include <math.h>
#include <stdint.h>

// Dims (CLEVR-scale, fixed)
#define B_   128
#define N_   36
#define DF_  512
#define DE_  256
#define DV_  512
#define H_   256
#define NC_  28
#define L_   5
#define ROWS_PER_B (N_*N_)          // 1296
#define NODE_ROWS  (B_*N_)          // 4608
#define EDGE_ROWS  (B_*ROWS_PER_B)  // 165888
#define SCALE_ 0.04419417382415922f // 1/sqrt(512)
#define BK_ 16

// Feature gate: tcgen05 exists only in arch-specific (sm_103a / sm_100a) passes.
#if defined(__CUDA_ARCH_FEAT_SM103_ALL) || defined(__CUDA_ARCH_FEAT_SM100_ALL) || defined(__CUDA_ARCH_FEAT_SM101_ALL)
#define HAS_TC 1
#else
#define HAS_TC 0
#endif

// ------------------------- device scratch (no cudaMalloc allowed) -----------
// NOTE: these symbols are ONLY referenced inside device code. Passing them as
// host-side kernel arguments passes the host shadow address (the rounds 5-10
// bug) and traps.
__device__ float g_hn[NODE_ROWS * H_];
__device__ float g_q[B_ * 4 * DV_];
__device__ float g_u3[B_ * H_];
__device__ float g_u1[B_ * H_];
__device__ float g_v [B_ * H_];
__device__ float g_c3[B_];
__device__ float g_c1[B_];
__device__ float g_ce[B_];
__device__ float g_a1  [NODE_ROWS];
__device__ float g_sig1[NODE_ROWS];
__device__ float g_weit[EDGE_ROWS];
__device__ float g_ph[B_ * H_];
__device__ float g_S [B_];
__device__ float g_We1T[H_ * DE_];   // We1 transposed: [n][k]
__device__ float g_gbuf[B_ * DV_];
__device__ float g_obuf[B_ * DV_];
__device__ float g_h2  [B_ * H_];

__device__ __forceinline__ float sigmoidf_(float x) { return 1.0f / (1.0f + expf(-x)); }
__device__ __forceinline__ unsigned f2tf32(float x) {
    unsigned u; asm("cvt.rna.tf32.f32 %0, %1;" : "=r"(u) : "f"(x)); return u;
}
__device__ __forceinline__ void mma_tf32(float c[4], const unsigned a[4], const unsigned b[2]) {
    asm volatile("mma.sync.aligned.m16n8k8.row.col.f32.tf32.tf32.f32 "
        "{%0,%1,%2,%3}, {%4,%5,%6,%7}, {%8,%9}, {%0,%1,%2,%3};"
        : "+f"(c[0]), "+f"(c[1]), "+f"(c[2]), "+f"(c[3])
        : "r"(a[0]), "r"(a[1]), "r"(a[2]), "r"(a[3]), "r"(b[0]), "r"(b[1]));
}

// ------------------------- tcgen05 helpers ----------------------------------
__device__ __forceinline__ uint32_t smem_u32(const void* p) {
    uint32_t a;
    asm("{ .reg .u64 t; cvta.to.shared.u64 t, %1; cvt.u32.u64 %0, t; }" : "=r"(a) : "l"(p));
    return a;
}
__device__ __forceinline__ uint32_t elect_one_pred() {
    uint32_t pred;
    asm volatile("{\n\t.reg .pred p;\n\telect.sync _|p, 0xFFFFFFFF;\n\t"
                 "selp.b32 %0, 1, 0, p;\n\t}" : "=r"(pred));
    return pred;
}
static __device__ constexpr uint64_t SMEM_DESC_BASE_SW128 =
    (uint64_t(2)  << 61) | (uint64_t(1) << 46) | (uint64_t(64) << 32) | (uint64_t(1) << 16);
__device__ __forceinline__ uint64_t make_desc(uint32_t addr) {
    return SMEM_DESC_BASE_SW128 | ((uint64_t)(addr >> 4) & 0x3FFF);
}
// tf32 SS idesc: dtype=F32(1<<4), a/btype=TF32(2<<7,2<<10), N/8<<17, M/16<<24
#define EDGE_IDESC 0x8400910u

#if HAS_TC
__device__ __forceinline__ void tc_mma_tf32_ss(uint32_t d_tmem, uint64_t a_desc,
                                               uint64_t b_desc, uint32_t idesc, bool accum) {
    uint32_t en = accum ? 1u : 0u;
    asm volatile(
        "{\n\t.reg .pred p;\n\t"
        "setp.ne.u32 p, %5, 0;\n\t"
        "tcgen05.mma.cta_group::1.kind::tf32 [%0], %1, %2, %3, {%4, %4, %4, %4}, p;\n\t}"
        :: "r"(d_tmem), "l"(a_desc), "l"(b_desc), "r"(idesc), "r"(0u), "r"(en)
        : "memory");
}
#define TC_ALLOC(smem_addr, n) \
    asm volatile("tcgen05.alloc.cta_group::1.sync.aligned.shared::cta.b32 [%0], %1;" \
                 :: "r"((uint32_t)(smem_addr)), "r"((uint32_t)(n)) : "memory")
#define TC_DEALLOC(tmem, n) \
    asm volatile("tcgen05.dealloc.cta_group::1.sync.aligned.b32 %0, %1;" :: "r"(tmem), "r"((uint32_t)(n)))
#define TC_RELINQ() asm volatile("tcgen05.relinquish_alloc_permit.cta_group::1.sync.aligned;")
#define TC_COMMIT(mbar) \
    asm volatile("tcgen05.commit.cta_group::1.mbarrier::arrive::one.shared::cluster.b64 [%0];" \
                 :: "r"((uint32_t)(mbar)) : "memory")
#define TC_FENCE_AFTER()  asm volatile("tcgen05.fence::after_thread_sync;" ::: "memory")
#define TC_WAIT_LD()      asm volatile("tcgen05.wait::ld.sync.aligned;" ::: "memory")
#define MBAR_INIT(addr, cnt) \
    asm volatile("mbarrier.init.shared.b64 [%0], %1;" :: "r"((uint32_t)(addr)), "r"((uint32_t)(cnt)) : "memory")
#define MBAR_INVAL(addr) \
    asm volatile("mbarrier.inval.shared.b64 [%0];" :: "r"((uint32_t)(addr)) : "memory")
#define FENCE_PROXY_ASYNC() asm volatile("fence.proxy.async.shared::cta;" ::: "memory")
__device__ __forceinline__ void mbar_wait_parity(uint32_t addr, uint32_t parity) {
    asm volatile(
        "{\n\t.reg .pred P1;\n\t"
        "WAIT_%=:\n\t"
        "mbarrier.try_wait.parity.acquire.cta.shared::cta.b64 P1, [%0], %1, 0x989680;\n\t"
        "@P1 bra.uni DONE_%=;\n\t"
        "bra.uni WAIT_%=;\n\t"
        "DONE_%=:\n\t}"
        :: "r"(addr), "r"(parity) : "memory");
}
#define LDTM_X32(r, addr) \
    asm volatile( \
        "tcgen05.ld.sync.aligned.32x32b.x32.b32 " \
        "{%0, %1, %2, %3, %4, %5, %6, %7, " \
        " %8, %9, %10, %11, %12, %13, %14, %15, " \
        " %16, %17, %18, %19, %20, %21, %22, %23, " \
        " %24, %25, %26, %27, %28, %29, %30, %31}, [%32];" \
        : "=r"((r)[0]),  "=r"((r)[1]),  "=r"((r)[2]),  "=r"((r)[3]), \
          "=r"((r)[4]),  "=r"((r)[5]),  "=r"((r)[6]),  "=r"((r)[7]), \
          "=r"((r)[8]),  "=r"((r)[9]),  "=r"((r)[10]), "=r"((r)[11]), \
          "=r"((r)[12]), "=r"((r)[13]), "=r"((r)[14]), "=r"((r)[15]), \
          "=r"((r)[16]), "=r"((r)[17]), "=r"((r)[18]), "=r"((r)[19]), \
          "=r"((r)[20]), "=r"((r)[21]), "=r"((r)[22]), "=r"((r)[23]), \
          "=r"((r)[24]), "=r"((r)[25]), "=r"((r)[26]), "=r"((r)[27]), \
          "=r"((r)[28]), "=r"((r)[29]), "=r"((r)[30]), "=r"((r)[31]) \
        : "r"(addr))
#endif // HAS_TC

// ------------------------- K0: transpose We1 (round-4 verbatim) -------------
__global__ void transpose_We1_kernel(const float* __restrict__ We1) {
    __shared__ float t[32][33];
    int bx = blockIdx.x * 32;   // n block
    int by = blockIdx.y * 32;   // k block
    t[threadIdx.y][threadIdx.x] = We1[(size_t)(by + threadIdx.y) * H_ + bx + threadIdx.x];
    __syncthreads();
    g_We1T[(size_t)(bx + threadIdx.y) * DE_ + by + threadIdx.x] = t[threadIdx.x][threadIdx.y];
}

// ------------------------- K1: gather q -------------------------------------
__global__ void gather_q_kernel(const float* __restrict__ word_emb,
                                const int* __restrict__ prog_in) {
    int idx = blockIdx.x * 256 + threadIdx.x;
    int d = idx & (DV_ - 1);
    int l = (idx >> 9) & 3;
    int b = idx >> 11;
    int w = prog_in[b * L_ + l];
    g_q[idx] = word_emb[(size_t)w * DV_ + d];
}

// ------------------------- K2a: batched projections u3,u1,v -----------------
// grid (8 bgroups, 2 h-halves, 3 which), block 256. 16 batches per block.
// Only INPUT pointers as args; all globals referenced in device code.
__global__ __launch_bounds__(256) void proj2_kernel(const float* __restrict__ Wn2,
                                                    const float* __restrict__ We2) {
    __shared__ float qs[16][512];
    const int bg = blockIdx.x, hh = blockIdx.y, wh = blockIdx.z;
    const int tid = threadIdx.x, warp = tid >> 5, lane = tid & 31;
    const float* W = (wh < 2) ? Wn2 : We2;
    const int l = (wh == 0) ? 3 : (wh == 1) ? 1 : 2;
    float* U = (wh == 0) ? g_u3 : (wh == 1) ? g_u1 : g_v;

    for (int i = tid; i < 16 * 512 / 4; i += 256) {
        int bl = i >> 7, d4 = (i & 127) * 4;
        ((float4*)&qs[bl][d4])[0] = *(const float4*)(g_q + ((size_t)((bg*16 + bl)*4 + l))*DV_ + d4);
    }
    __syncthreads();

    for (int hi = 0; hi < 128; hi++) {
        int h = hh * 128 + hi;
        const float* wr = W + (size_t)h * DV_;
        float w[16];
        #pragma unroll
        for (int t = 0; t < 16; t++) w[t] = wr[lane + t*32];
        #pragma unroll
        for (int bb = 0; bb < 2; bb++) {
            int bl = warp * 2 + bb;
            float acc = 0.f;
            #pragma unroll
            for (int t = 0; t < 16; t++) acc += w[t] * qs[bl][lane + t*32];
            #pragma unroll
            for (int o = 16; o > 0; o >>= 1) acc += __shfl_xor_sync(0xffffffffu, acc, o);
            if (lane == 0) U[(bg*16 + bl) * H_ + h] = acc;
        }
    }
}

// ------------------------- K2b: scalar dots c3,c1,ce ------------------------
__global__ void scal_kernel(const float* __restrict__ bn2, const float* __restrict__ be2) {
    __shared__ float r3[128], r1[128], re[128];
    int b = blockIdx.x, tid = threadIdx.x;
    float s3 = 0.f, s1 = 0.f, se = 0.f;
    #pragma unroll
    for (int t = 0; t < 4; t++) {
        int d = tid + t*128;
        float bn = bn2[d], be = be2[d];
        s3 += bn * g_q[((size_t)(b*4 + 3))*DV_ + d];
        s1 += bn * g_q[((size_t)(b*4 + 1))*DV_ + d];
        se += be * g_q[((size_t)(b*4 + 2))*DV_ + d];
    }
    r3[tid] = s3; r1[tid] = s1; re[tid] = se;
    __syncthreads();
    for (int o = 64; o > 0; o >>= 1) {
        if (tid < o) { r3[tid] += r3[tid+o]; r1[tid] += r1[tid+o]; re[tid] += re[tid+o]; }
        __syncthreads();
    }
    if (tid == 0) { g_c3[b] = r3[0]; g_c1[b] = r1[0]; g_ce[b] = re[0]; }
}

// ------------------------- K3: node MLP1 (tf32 mma.sync, round-4 verbatim) --
__global__ __launch_bounds__(512, 1) void node_mma_kernel(
        const float* __restrict__ node, const float* __restrict__ Wn1,
        const float* __restrict__ bn1) {
    __shared__ unsigned As[128][20];
    __shared__ unsigned Bs[BK_][264];
    __shared__ float bs[256];

    const int tid  = threadIdx.x;
    const int warp = tid >> 5, lane = tid & 31;
    const int warpM = warp >> 2, warpN = warp & 3;
    const int g = lane >> 2, kq = lane & 3;
    const int row0 = blockIdx.x * 128;

    if (tid < 256) bs[tid] = bn1[tid];

    float acc[2][8][4];
    #pragma unroll
    for (int mt = 0; mt < 2; mt++)
        #pragma unroll
        for (int nt = 0; nt < 8; nt++)
            #pragma unroll
            for (int c = 0; c < 4; c++) acc[mt][nt][c] = 0.f;

    const int ra = tid >> 2, ca = tid & 3;
    const float* Abase = node + (size_t)row0 * DF_;

    float4 pa;
    float4 pb[2];
    {
        pa = *(const float4*)(Abase + (size_t)ra * DF_ + ca*4);
        #pragma unroll
        for (int t = 0; t < 2; t++) {
            int i4 = tid + t*512; int kr = i4 >> 6, c4 = i4 & 63;
            pb[t] = *(const float4*)(Wn1 + (size_t)kr * H_ + c4*4);
        }
    }
    const int S = DF_ / BK_;
    for (int s = 0; s < S; s++) {
        *(uint4*)&As[ra][ca*4] = make_uint4(f2tf32(pa.x), f2tf32(pa.y), f2tf32(pa.z), f2tf32(pa.w));
        #pragma unroll
        for (int t = 0; t < 2; t++) {
            int i4 = tid + t*512; int kr = i4 >> 6, c4 = i4 & 63;
            *(uint4*)&Bs[kr][c4*4] = make_uint4(f2tf32(pb[t].x), f2tf32(pb[t].y), f2tf32(pb[t].z), f2tf32(pb[t].w));
        }
        __syncthreads();
        if (s + 1 < S) {
            int k0 = (s + 1) * BK_;
            pa = *(const float4*)(Abase + (size_t)ra * DF_ + k0 + ca*4);
            #pragma unroll
            for (int t = 0; t < 2; t++) {
                int i4 = tid + t*512; int kr = i4 >> 6, c4 = i4 & 63;
                pb[t] = *(const float4*)(Wn1 + (size_t)(k0 + kr) * H_ + c4*4);
            }
        }
        #pragma unroll
        for (int kk = 0; kk < 2; kk++) {
            unsigned af[2][4], bf[8][2];
            #pragma unroll
            for (int mt = 0; mt < 2; mt++) {
                int r = warpM*32 + mt*16 + g;
                af[mt][0] = As[r    ][kk*8 + kq];
                af[mt][1] = As[r + 8][kk*8 + kq];
                af[mt][2] = As[r    ][kk*8 + kq + 4];
                af[mt][3] = As[r + 8][kk*8 + kq + 4];
            }
            #pragma unroll
            for (int nt = 0; nt < 8; nt++) {
                int n = warpN*64 + nt*8 + g;
                bf[nt][0] = Bs[kk*8 + kq    ][n];
                bf[nt][1] = Bs[kk*8 + kq + 4][n];
            }
            #pragma unroll
            for (int mt = 0; mt < 2; mt++)
                #pragma unroll
                for (int nt = 0; nt < 8; nt++) mma_tf32(acc[mt][nt], af[mt], bf[nt]);
        }
        __syncthreads();
    }
    #pragma unroll
    for (int mt = 0; mt < 2; mt++) {
        int rA = row0 + warpM*32 + mt*16 + g;
        int rB = rA + 8;
        #pragma unroll
        for (int nt = 0; nt < 8; nt++) {
            int n = warpN*64 + nt*8 + kq*2;
            float b0v = bs[n], b1v = bs[n+1];
            float2 v0 = make_float2(fmaxf(acc[mt][nt][0] + b0v, 0.f), fmaxf(acc[mt][nt][1] + b1v, 0.f));
            float2 v1 = make_float2(fmaxf(acc[mt][nt][2] + b0v, 0.f), fmaxf(acc[mt][nt][3] + b1v, 0.f));
            *(float2*)&g_hn[(size_t)rA * H_ + n] = v0;
            *(float2*)&g_hn[(size_t)rB * H_ + n] = v1;
        }
    }
}

// ------------------------- K4: filter scores --------------------------------
__global__ void score_kernel() {
    int gw = (blockIdx.x * 256 + threadIdx.x) >> 5;
    int lane = threadIdx.x & 31;
    if (gw >= NODE_ROWS) return;
    int b = gw / N_;
    const float* h  = g_hn + (size_t)gw * H_;
    const float* u3 = g_u3 + b * H_;
    const float* u1 = g_u1 + b * H_;
    float d3 = 0.f, d1 = 0.f;
    #pragma unroll
    for (int t = 0; t < 8; t++) {
        int d = lane + t*32;
        float hv = h[d];
        d3 += hv * u3[d];
        d1 += hv * u1[d];
    }
    #pragma unroll
    for (int o = 16; o > 0; o >>= 1) {
        d3 += __shfl_xor_sync(0xffffffffu, d3, o);
        d1 += __shfl_xor_sync(0xffffffffu, d1, o);
    }
    if (lane == 0) {
        g_a1[gw]   = sigmoidf_((d3 + g_c3[b]) * SCALE_);
        g_sig1[gw] = sigmoidf_((d1 + g_c1[b]) * SCALE_);
    }
}

// ------------------------- K5a: edge GEMM via tcgen05 (round-4 verbatim) ----
#define EDGE_SMEM_DYN (1024 + 2*16384 + 2*32768)
__global__ __launch_bounds__(256, 1)
void edge_tc_kernel(const float* __restrict__ edge, const float* __restrict__ be1) {
#if HAS_TC
    extern __shared__ char dsm[];
    __shared__ uint32_t sh_tmem;
    __shared__ uint64_t sh_mbar[2];
    __shared__ float bs[256], vs0[256], vs1[256];
    __shared__ float s_part[256];
    __shared__ float ces[2];

    const int tid = threadIdx.x;
    const int warp = tid >> 5, lane = tid & 31;
    const int row0 = blockIdx.x * 128;

    const int b0 = row0 / ROWS_PER_B;
    const int bn_ = (b0 + 1 < B_) ? b0 + 1 : b0;
    const int split = (b0 + 1) * ROWS_PER_B - row0;

    uint32_t dbase = smem_u32(dsm);
    uint32_t aligned = (dbase + 1023u) & ~1023u;
    char* smbase = dsm + (aligned - dbase);
    const uint32_t Aoff[2] = {0u, 16384u};
    const uint32_t Boff[2] = {32768u, 65536u};

    if (warp == 0) { TC_ALLOC(smem_u32(&sh_tmem), 256); TC_RELINQ(); }
    if (tid == 0) {
        MBAR_INIT(smem_u32(&sh_mbar[0]), 1);
        MBAR_INIT(smem_u32(&sh_mbar[1]), 1);
        ces[0] = g_ce[b0]; ces[1] = g_ce[bn_];
    }
    bs[tid]  = be1[tid];
    vs0[tid] = g_v[b0  * H_ + tid];
    vs1[tid] = g_v[bn_ * H_ + tid];
    __syncthreads();

    const uint32_t tmem = sh_tmem;
    const uint32_t mb0 = smem_u32(&sh_mbar[0]);
    const uint32_t mb1 = smem_u32(&sh_mbar[1]);
    const float* Abase = edge + (size_t)row0 * DE_;

    #pragma unroll 1
    for (int c = 0; c < 8; c++) {
        const int buf = c & 1;
        if (c >= 2) {
            uint32_t u = (uint32_t)(c - 2) >> 1;
            mbar_wait_parity(buf ? mb1 : mb0, u & 1u);
        }
        const int k0 = c * 32;
        char* Ab = smbase + Aoff[buf];
        #pragma unroll
        for (int t = 0; t < 4; t++) {
            int i4 = tid + t*256;
            int r = i4 >> 3, c4 = i4 & 7;
            float4 v = *(const float4*)(Abase + (size_t)r * DE_ + k0 + c4*4);
            uint32_t byte = (uint32_t)(r*128 + c4*16);
            uint32_t sw = byte ^ ((byte >> 3) & 0x70u);
            *(uint4*)(Ab + sw) = make_uint4(f2tf32(v.x), f2tf32(v.y), f2tf32(v.z), f2tf32(v.w));
        }
        char* Bb = smbase + Boff[buf];
        #pragma unroll
        for (int t = 0; t < 8; t++) {
            int i4 = tid + t*256;
            int n = i4 >> 3, c4 = i4 & 7;
            float4 v = *(const float4*)(g_We1T + (size_t)n * DE_ + k0 + c4*4);
            uint32_t byte = (uint32_t)(n*128 + c4*16);
            uint32_t sw = byte ^ ((byte >> 3) & 0x70u);
            *(uint4*)(Bb + sw) = make_uint4(f2tf32(v.x), f2tf32(v.y), f2tf32(v.z), f2tf32(v.w));
        }
        FENCE_PROXY_ASYNC();
        __syncthreads();
        if (warp == 0) {
            if (elect_one_pred()) {
                uint64_t ad = make_desc(aligned + Aoff[buf]);
                uint64_t bd = make_desc(aligned + Boff[buf]);
                #pragma unroll
                for (int s = 0; s < 4; s++)
                    tc_mma_tf32_ss(tmem, ad + 2*s, bd + 2*s, EDGE_IDESC, (c > 0) || (s > 0));
                TC_COMMIT(buf ? mb1 : mb0);
            }
        }
    }
    mbar_wait_parity(mb0, 1u);
    mbar_wait_parity(mb1, 1u);
    TC_FENCE_AFTER();

    {
        const int half = warp >> 2;
        const int r = (warp & 3) * 32 + lane;
        const float* vrow = (r < split) ? vs0 : vs1;
        float s = 0.f;
        #pragma unroll
        for (int j = 0; j < 4; j++) {
            uint32_t d[32];
            int cbase = half*128 + j*32;
            LDTM_X32(d, tmem + cbase);
            TC_WAIT_LD();
            #pragma unroll
            for (int cc = 0; cc < 32; cc++) {
                int col = cbase + cc;
                float h = fmaxf(__uint_as_float(d[cc]) + bs[col], 0.f);
                s += h * vrow[col];
            }
        }
        s_part[half*128 + r] = s;
    }
    __syncthreads();
    if (tid < 128) {
        float tot = s_part[tid] + s_part[128 + tid];
        float ce = (tid < split) ? ces[0] : ces[1];
        g_weit[row0 + tid] = sigmoidf_((tot + ce) * SCALE_);
    }
    __syncthreads();
    if (tid == 0) { MBAR_INVAL(mb0); MBAR_INVAL(mb1); }
    if (warp == 0) TC_DEALLOC(tmem, 256);
#else
    (void)edge; (void)be1;
#endif
}

// ------------------------- K5b: edge GEMM via mma.sync (base pass) ----------
__global__ __launch_bounds__(512, 1) void edge_mma_kernel(
        const float* __restrict__ edge, const float* __restrict__ We1,
        const float* __restrict__ be1) {
#if !HAS_TC
    __shared__ unsigned As[128][20];
    __shared__ unsigned Bs[BK_][264];
    __shared__ float s_sh[128];
    __shared__ float bs[256], vs0[256], vs1[256];
    __shared__ float ces[2];

    const int tid  = threadIdx.x;
    const int warp = tid >> 5, lane = tid & 31;
    const int warpM = warp >> 2, warpN = warp & 3;
    const int g = lane >> 2, kq = lane & 3;
    const int row0 = blockIdx.x * 128;

    const int b0 = row0 / ROWS_PER_B;
    const int bn_ = (b0 + 1 < B_) ? b0 + 1 : b0;
    const int split = (b0 + 1) * ROWS_PER_B - row0;

    if (tid < 256) {
        bs[tid]  = be1[tid];
        vs0[tid] = g_v[b0  * H_ + tid];
        vs1[tid] = g_v[bn_ * H_ + tid];
    }
    if (tid < 128) s_sh[tid] = 0.f;
    if (tid == 0) { ces[0] = g_ce[b0]; ces[1] = g_ce[bn_]; }

    float acc[2][8][4];
    #pragma unroll
    for (int mt = 0; mt < 2; mt++)
        #pragma unroll
        for (int nt = 0; nt < 8; nt++)
            #pragma unroll
            for (int c = 0; c < 4; c++) acc[mt][nt][c] = 0.f;

    const int ra = tid >> 2, ca = tid & 3;
    const float* Abase = edge + (size_t)row0 * DE_;

    float4 pa;
    float4 pb[2];
    {
        pa = *(const float4*)(Abase + (size_t)ra * DE_ + ca*4);
        #pragma unroll
        for (int t = 0; t < 2; t++) {
            int i4 = tid + t*512; int kr = i4 >> 6, c4 = i4 & 63;
            pb[t] = *(const float4*)(We1 + (size_t)kr * 256 + c4*4);
        }
    }
    const int S = DE_ / BK_;
    for (int s = 0; s < S; s++) {
        *(uint4*)&As[ra][ca*4] = make_uint4(f2tf32(pa.x), f2tf32(pa.y), f2tf32(pa.z), f2tf32(pa.w));
        #pragma unroll
        for (int t = 0; t < 2; t++) {
            int i4 = tid + t*512; int kr = i4 >> 6, c4 = i4 & 63;
            *(uint4*)&Bs[kr][c4*4] = make_uint4(f2tf32(pb[t].x), f2tf32(pb[t].y), f2tf32(pb[t].z), f2tf32(pb[t].w));
        }
        __syncthreads();
        if (s + 1 < S) {
            int k0 = (s + 1) * BK_;
            pa = *(const float4*)(Abase + (size_t)ra * DE_ + k0 + ca*4);
            #pragma unroll
            for (int t = 0; t < 2; t++) {
                int i4 = tid + t*512; int kr = i4 >> 6, c4 = i4 & 63;
                pb[t] = *(const float4*)(We1 + (size_t)(k0 + kr) * 256 + c4*4);
            }
        }
        #pragma unroll
        for (int kk = 0; kk < 2; kk++) {
            unsigned af[2][4], bf[8][2];
            #pragma unroll
            for (int mt = 0; mt < 2; mt++) {
                int r = warpM*32 + mt*16 + g;
                af[mt][0] = As[r    ][kk*8 + kq];
                af[mt][1] = As[r + 8][kk*8 + kq];
                af[mt][2] = As[r    ][kk*8 + kq + 4];
                af[mt][3] = As[r + 8][kk*8 + kq + 4];
            }
            #pragma unroll
            for (int nt = 0; nt < 8; nt++) {
                int n = warpN*64 + nt*8 + g;
                bf[nt][0] = Bs[kk*8 + kq    ][n];
                bf[nt][1] = Bs[kk*8 + kq + 4][n];
            }
            #pragma unroll
            for (int mt = 0; mt < 2; mt++)
                #pragma unroll
                for (int nt = 0; nt < 8; nt++) mma_tf32(acc[mt][nt], af[mt], bf[nt]);
        }
        __syncthreads();
    }
    #pragma unroll
    for (int mt = 0; mt < 2; mt++) {
        int rA = warpM*32 + mt*16 + g;
        int rB = rA + 8;
        const float* vA = (rA < split) ? vs0 : vs1;
        const float* vB = (rB < split) ? vs0 : vs1;
        float pA = 0.f, pB = 0.f;
        #pragma unroll
        for (int nt = 0; nt < 8; nt++) {
            int n = warpN*64 + nt*8 + kq*2;
            float b0v = bs[n], b1v = bs[n+1];
            pA += fmaxf(acc[mt][nt][0] + b0v, 0.f) * vA[n]
                + fmaxf(acc[mt][nt][1] + b1v, 0.f) * vA[n+1];
            pB += fmaxf(acc[mt][nt][2] + b0v, 0.f) * vB[n]
                + fmaxf(acc[mt][nt][3] + b1v, 0.f) * vB[n+1];
        }
        pA += __shfl_xor_sync(0xffffffffu, pA, 1);
        pA += __shfl_xor_sync(0xffffffffu, pA, 2);
        pB += __shfl_xor_sync(0xffffffffu, pB, 1);
        pB += __shfl_xor_sync(0xffffffffu, pB, 2);
        if (kq == 0) {
            atomicAdd(&s_sh[rA], pA);
            atomicAdd(&s_sh[rB], pB);
        }
    }
    __syncthreads();
    if (tid < 128) {
        float ce = (tid < split) ? ces[0] : ces[1];
        g_weit[row0 + tid] = sigmoidf_((s_sh[tid] + ce) * SCALE_);
    }
#else
    (void)edge; (void)We1; (void)be1;
#endif
}

// ------------------------- K6: attention chain + pooled hidden --------------
__global__ void combine_kernel() {
    int b = blockIdx.x;
    int tid = threadIdx.x;
    __shared__ float a1s[N_];
    __shared__ float a3s[N_];
    __shared__ float sInv, sS;
    if (tid < N_) a1s[tid] = g_a1[b * N_ + tid];
    __syncthreads();
    if (tid < N_) {
        int j = tid;
        float acc = 0.f;
        const float* w = g_weit + (size_t)b * ROWS_PER_B;
        #pragma unroll
        for (int i = 0; i < N_; i++) acc += a1s[i] * w[i * N_ + j];
        acc = fminf(fmaxf(acc, 0.f), 1.f);
        a3s[j] = acc * g_sig1[b * N_ + j];
    }
    __syncthreads();
    if (tid == 0) {
        float s0 = 0.f;
        #pragma unroll
        for (int j = 0; j < N_; j++) s0 += a3s[j];
        float inv = 1.f / (s0 + 1e-8f);
        sInv = inv;
        sS = s0 * inv;
    }
    __syncthreads();
    {
        int h = tid;
        float acc = 0.f;
        #pragma unroll
        for (int j = 0; j < N_; j++)
            acc += a3s[j] * g_hn[((size_t)(b * N_ + j)) * H_ + h];
        g_ph[b * H_ + h] = acc * sInv;
    }
    if (tid == 0) g_S[b] = sS;
}

// ------------------------- K7: final chain, 32x32 tiled GEMM stages ---------
// stage selects A (input) and C (output) from device globals IN DEVICE CODE.
// Only true input pointers (W, bias) and the harness out pointer cross the
// host/device boundary.
// stage 0: g_ph   @ Wn2 -> g_gbuf  [128x512, K=256], epi: (x+S*b)*q0
// stage 1: g_gbuf @ Wq  -> g_obuf  [128x512, K=512], epi: relu(x+b)
// stage 2: g_obuf @ Wc1 -> g_h2    [128x256, K=512], epi: relu(x+b)
// stage 3: g_h2   @ Wc2 -> out     [128x28,  K=256], epi: x+b
__global__ __launch_bounds__(256) void final_mm_kernel(
        int stage, const float* __restrict__ W, const float* __restrict__ bias,
        float* __restrict__ outp) {
    __shared__ float As[32][36];
    __shared__ float Ws[32][32];

    const float* A; float* C; int N, K, mode;
    if (stage == 0)      { A = g_ph;   C = g_gbuf; N = DV_; K = H_;  mode = 1; }
    else if (stage == 1) { A = g_gbuf; C = g_obuf; N = DV_; K = DV_; mode = 0; }
    else if (stage == 2) { A = g_obuf; C = g_h2;   N = H_;  K = DV_; mode = 0; }
    else                 { A = g_h2;   C = outp;   N = NC_; K = H_;  mode = 2; }

    const int tid = threadIdx.x;
    const int m0 = blockIdx.x * 32, n0 = blockIdx.y * 32;
    const int r = tid >> 3, cg = tid & 7;
    float acc[4] = {0.f, 0.f, 0.f, 0.f};

    const int lrow = tid >> 3, lk4 = (tid & 7) * 4;
    for (int k0 = 0; k0 < K; k0 += 32) {
        float4 av = *(const float4*)(A + (size_t)(m0 + lrow) * K + k0 + lk4);
        *(float4*)&As[lrow][lk4] = av;
        #pragma unroll
        for (int u = 0; u < 4; u++) {
            int n = n0 + lk4 + u;
            Ws[lrow][lk4 + u] = (n < N) ? W[(size_t)(k0 + lrow) * N + n] : 0.f;
        }
        __syncthreads();
        #pragma unroll
        for (int k = 0; k < 32; k++) {
            float a = As[r][k];
            float4 w = *(const float4*)&Ws[k][cg*4];
            acc[0] += a * w.x; acc[1] += a * w.y; acc[2] += a * w.z; acc[3] += a * w.w;
        }
        __syncthreads();
    }
    const int row = m0 + r;
    #pragma unroll
    for (int u = 0; u < 4; u++) {
        int n = n0 + cg*4 + u;
        if (n >= N) continue;
        float x = acc[u];
        if (mode == 0)      x = fmaxf(x + bias[n], 0.f);
        else if (mode == 1) x = (x + g_S[row] * bias[n]) * g_q[((size_t)(row*4 + 0))*DV_ + n];
        else                x = x + bias[n];
        C[(size_t)row * N + n] = x;
    }
}

// ------------------------- launch ------------------------------------------
extern "C" void kernel_launch(void* const* d_in, const int* in_sizes, int n_in,
                              void* d_out, int out_size) {
    const float* node     = (const float*)d_in[0];
    const float* edge     = (const float*)d_in[1];
    const float* Wn1      = (const float*)d_in[2];
    const float* bn1      = (const float*)d_in[3];
    const float* Wn2      = (const float*)d_in[4];
    const float* bn2      = (const float*)d_in[5];
    const float* We1      = (const float*)d_in[6];
    const float* be1      = (const float*)d_in[7];
    const float* We2      = (const float*)d_in[8];
    const float* be2      = (const float*)d_in[9];
    const float* Wq       = (const float*)d_in[10];
    const float* bq       = (const float*)d_in[11];
    const float* Wc1      = (const float*)d_in[12];
    const float* bc1      = (const float*)d_in[13];
    const float* Wc2      = (const float*)d_in[14];
    const float* bc2      = (const float*)d_in[15];
    const float* word_emb = (const float*)d_in[16];
    const int* prog_in    = (const int*)d_in[18];
    float* out            = (float*)d_out;

    static int smem_set = 0;
    if (!smem_set) {
        cudaFuncSetAttribute(edge_tc_kernel,
                             cudaFuncAttributeMaxDynamicSharedMemorySize, EDGE_SMEM_DYN);
        smem_set = 1;
    }

    transpose_We1_kernel<<<dim3(8, 8), dim3(32, 32)>>>(We1);
    gather_q_kernel<<<(B_*4*DV_)/256, 256>>>(word_emb, prog_in);
    proj2_kernel<<<dim3(8, 2, 3), 256>>>(Wn2, We2);
    scal_kernel<<<B_, 128>>>(bn2, be2);
    node_mma_kernel<<<NODE_ROWS/128, 512>>>(node, Wn1, bn1);
    score_kernel<<<NODE_ROWS/8, 256>>>();
    edge_tc_kernel<<<EDGE_ROWS/128, 256, EDGE_SMEM_DYN>>>(edge, be1);
    edge_mma_kernel<<<EDGE_ROWS/128, 512>>>(edge, We1, be1);
    combine_kernel<<<B_, 256>>>();

    // final GEMV chain as tiled GEMMs (scratch selected in device code)
    final_mm_kernel<<<dim3(4, 16), 256>>>(0, Wn2, bn2, out);
    final_mm_kernel<<<dim3(4, 16), 256>>>(1, Wq,  bq,  out);
    final_mm_kernel<<<dim3(4, 8),  256>>>(2, Wc1, bc1, out);
    final_mm_kernel<<<dim3(4, 1),  256>>>(3, Wc2, bc2, out);
}

// round 12
// speedup vs baseline: 1.0840x; 1.0840x over previous
#include <cuda_runtime.h>
#include <math.h>
#include <stdint.h>

// Dims (CLEVR-scale, fixed)
#define B_   128
#define N_   36
#define DF_  512
#define DE_  256
#define DV_  512
#define H_   256
#define NC_  28
#define L_   5
#define ROWS_PER_B (N_*N_)          // 1296
#define NODE_ROWS  (B_*N_)          // 4608
#define EDGE_ROWS  (B_*ROWS_PER_B)  // 165888
#define SCALE_ 0.04419417382415922f // 1/sqrt(512)
#define BK_ 16

// Feature gate: tcgen05 exists only in arch-specific (sm_103a / sm_100a) passes.
#if defined(__CUDA_ARCH_FEAT_SM103_ALL) || defined(__CUDA_ARCH_FEAT_SM100_ALL) || defined(__CUDA_ARCH_FEAT_SM101_ALL)
#define HAS_TC 1
#else
#define HAS_TC 0
#endif

// ------------------------- device scratch (no cudaMalloc allowed) -----------
// RULE (rounds 5-10 bug): these symbols are ONLY referenced inside device
// code. Passing them as host-side kernel args passes the host shadow address
// and traps the stream.
__device__ float g_hn[NODE_ROWS * H_];
__device__ float g_q[B_ * 4 * DV_];
__device__ float g_u3[B_ * H_];
__device__ float g_u1[B_ * H_];
__device__ float g_v [B_ * H_];
__device__ float g_c3[B_];
__device__ float g_c1[B_];
__device__ float g_ce[B_];
__device__ float g_a1  [NODE_ROWS];
__device__ float g_sig1[NODE_ROWS];
__device__ float g_weit[EDGE_ROWS];
__device__ float g_ph[B_ * H_];
__device__ float g_S [B_];
__device__ float g_We1T[H_ * DE_];   // We1 transposed: [n][k]
__device__ float g_gbuf[B_ * DV_];
__device__ float g_obuf[B_ * DV_];
__device__ float g_h2  [B_ * H_];

__device__ __forceinline__ float sigmoidf_(float x) { return 1.0f / (1.0f + expf(-x)); }
__device__ __forceinline__ unsigned f2tf32(float x) {
    unsigned u; asm("cvt.rna.tf32.f32 %0, %1;" : "=r"(u) : "f"(x)); return u;
}
__device__ __forceinline__ void mma_tf32(float c[4], const unsigned a[4], const unsigned b[2]) {
    asm volatile("mma.sync.aligned.m16n8k8.row.col.f32.tf32.tf32.f32 "
        "{%0,%1,%2,%3}, {%4,%5,%6,%7}, {%8,%9}, {%0,%1,%2,%3};"
        : "+f"(c[0]), "+f"(c[1]), "+f"(c[2]), "+f"(c[3])
        : "r"(a[0]), "r"(a[1]), "r"(a[2]), "r"(a[3]), "r"(b[0]), "r"(b[1]));
}

// ------------------------- tcgen05 helpers ----------------------------------
__device__ __forceinline__ uint32_t smem_u32(const void* p) {
    uint32_t a;
    asm("{ .reg .u64 t; cvta.to.shared.u64 t, %1; cvt.u32.u64 %0, t; }" : "=r"(a) : "l"(p));
    return a;
}
__device__ __forceinline__ uint32_t elect_one_pred() {
    uint32_t pred;
    asm volatile("{\n\t.reg .pred p;\n\telect.sync _|p, 0xFFFFFFFF;\n\t"
                 "selp.b32 %0, 1, 0, p;\n\t}" : "=r"(pred));
    return pred;
}
static __device__ constexpr uint64_t SMEM_DESC_BASE_SW128 =
    (uint64_t(2)  << 61) | (uint64_t(1) << 46) | (uint64_t(64) << 32) | (uint64_t(1) << 16);
__device__ __forceinline__ uint64_t make_desc(uint32_t addr) {
    return SMEM_DESC_BASE_SW128 | ((uint64_t)(addr >> 4) & 0x3FFF);
}
// tf32 SS idesc: dtype=F32(1<<4), a/btype=TF32(2<<7,2<<10), N/8<<17, M/16<<24
#define EDGE_IDESC 0x8400910u

#if HAS_TC
__device__ __forceinline__ void tc_mma_tf32_ss(uint32_t d_tmem, uint64_t a_desc,
                                               uint64_t b_desc, uint32_t idesc, bool accum) {
    uint32_t en = accum ? 1u : 0u;
    asm volatile(
        "{\n\t.reg .pred p;\n\t"
        "setp.ne.u32 p, %5, 0;\n\t"
        "tcgen05.mma.cta_group::1.kind::tf32 [%0], %1, %2, %3, {%4, %4, %4, %4}, p;\n\t}"
        :: "r"(d_tmem), "l"(a_desc), "l"(b_desc), "r"(idesc), "r"(0u), "r"(en)
        : "memory");
}
#define TC_ALLOC(smem_addr, n) \
    asm volatile("tcgen05.alloc.cta_group::1.sync.aligned.shared::cta.b32 [%0], %1;" \
                 :: "r"((uint32_t)(smem_addr)), "r"((uint32_t)(n)) : "memory")
#define TC_DEALLOC(tmem, n) \
    asm volatile("tcgen05.dealloc.cta_group::1.sync.aligned.b32 %0, %1;" :: "r"(tmem), "r"((uint32_t)(n)))
#define TC_RELINQ() asm volatile("tcgen05.relinquish_alloc_permit.cta_group::1.sync.aligned;")
#define TC_COMMIT(mbar) \
    asm volatile("tcgen05.commit.cta_group::1.mbarrier::arrive::one.shared::cluster.b64 [%0];" \
                 :: "r"((uint32_t)(mbar)) : "memory")
#define TC_FENCE_AFTER()  asm volatile("tcgen05.fence::after_thread_sync;" ::: "memory")
#define TC_WAIT_LD()      asm volatile("tcgen05.wait::ld.sync.aligned;" ::: "memory")
#define MBAR_INIT(addr, cnt) \
    asm volatile("mbarrier.init.shared.b64 [%0], %1;" :: "r"((uint32_t)(addr)), "r"((uint32_t)(cnt)) : "memory")
#define MBAR_INVAL(addr) \
    asm volatile("mbarrier.inval.shared.b64 [%0];" :: "r"((uint32_t)(addr)) : "memory")
#define FENCE_PROXY_ASYNC() asm volatile("fence.proxy.async.shared::cta;" ::: "memory")
__device__ __forceinline__ void mbar_wait_parity(uint32_t addr, uint32_t parity) {
    asm volatile(
        "{\n\t.reg .pred P1;\n\t"
        "WAIT_%=:\n\t"
        "mbarrier.try_wait.parity.acquire.cta.shared::cta.b64 P1, [%0], %1, 0x989680;\n\t"
        "@P1 bra.uni DONE_%=;\n\t"
        "bra.uni WAIT_%=;\n\t"
        "DONE_%=:\n\t}"
        :: "r"(addr), "r"(parity) : "memory");
}
#define LDTM_X32(r, addr) \
    asm volatile( \
        "tcgen05.ld.sync.aligned.32x32b.x32.b32 " \
        "{%0, %1, %2, %3, %4, %5, %6, %7, " \
        " %8, %9, %10, %11, %12, %13, %14, %15, " \
        " %16, %17, %18, %19, %20, %21, %22, %23, " \
        " %24, %25, %26, %27, %28, %29, %30, %31}, [%32];" \
        : "=r"((r)[0]),  "=r"((r)[1]),  "=r"((r)[2]),  "=r"((r)[3]), \
          "=r"((r)[4]),  "=r"((r)[5]),  "=r"((r)[6]),  "=r"((r)[7]), \
          "=r"((r)[8]),  "=r"((r)[9]),  "=r"((r)[10]), "=r"((r)[11]), \
          "=r"((r)[12]), "=r"((r)[13]), "=r"((r)[14]), "=r"((r)[15]), \
          "=r"((r)[16]), "=r"((r)[17]), "=r"((r)[18]), "=r"((r)[19]), \
          "=r"((r)[20]), "=r"((r)[21]), "=r"((r)[22]), "=r"((r)[23]), \
          "=r"((r)[24]), "=r"((r)[25]), "=r"((r)[26]), "=r"((r)[27]), \
          "=r"((r)[28]), "=r"((r)[29]), "=r"((r)[30]), "=r"((r)[31]) \
        : "r"(addr))
#endif // HAS_TC

// ------------------------- K0: transpose We1 --------------------------------
__global__ void transpose_We1_kernel(const float* __restrict__ We1) {
    __shared__ float t[32][33];
    int bx = blockIdx.x * 32;   // n block
    int by = blockIdx.y * 32;   // k block
    t[threadIdx.y][threadIdx.x] = We1[(size_t)(by + threadIdx.y) * H_ + bx + threadIdx.x];
    __syncthreads();
    g_We1T[(size_t)(bx + threadIdx.y) * DE_ + by + threadIdx.x] = t[threadIdx.x][threadIdx.y];
}

// ------------------------- K1: gather q -------------------------------------
__global__ void gather_q_kernel(const float* __restrict__ word_emb,
                                const int* __restrict__ prog_in) {
    int idx = blockIdx.x * 256 + threadIdx.x;
    int d = idx & (DV_ - 1);
    int l = (idx >> 9) & 3;
    int b = idx >> 11;
    int w = prog_in[b * L_ + l];
    g_q[idx] = word_emb[(size_t)w * DV_ + d];
}

// ------------------------- K2a: batched projections u3,u1,v -----------------
__global__ __launch_bounds__(256) void proj2_kernel(const float* __restrict__ Wn2,
                                                    const float* __restrict__ We2) {
    __shared__ float qs[16][512];
    const int bg = blockIdx.x, hh = blockIdx.y, wh = blockIdx.z;
    const int tid = threadIdx.x, warp = tid >> 5, lane = tid & 31;
    const float* W = (wh < 2) ? Wn2 : We2;
    const int l = (wh == 0) ? 3 : (wh == 1) ? 1 : 2;
    float* U = (wh == 0) ? g_u3 : (wh == 1) ? g_u1 : g_v;

    for (int i = tid; i < 16 * 512 / 4; i += 256) {
        int bl = i >> 7, d4 = (i & 127) * 4;
        ((float4*)&qs[bl][d4])[0] = *(const float4*)(g_q + ((size_t)((bg*16 + bl)*4 + l))*DV_ + d4);
    }
    __syncthreads();

    for (int hi = 0; hi < 128; hi++) {
        int h = hh * 128 + hi;
        const float* wr = W + (size_t)h * DV_;
        float w[16];
        #pragma unroll
        for (int t = 0; t < 16; t++) w[t] = wr[lane + t*32];
        #pragma unroll
        for (int bb = 0; bb < 2; bb++) {
            int bl = warp * 2 + bb;
            float acc = 0.f;
            #pragma unroll
            for (int t = 0; t < 16; t++) acc += w[t] * qs[bl][lane + t*32];
            #pragma unroll
            for (int o = 16; o > 0; o >>= 1) acc += __shfl_xor_sync(0xffffffffu, acc, o);
            if (lane == 0) U[(bg*16 + bl) * H_ + h] = acc;
        }
    }
}

// ------------------------- K2b: scalar dots c3,c1,ce ------------------------
__global__ void scal_kernel(const float* __restrict__ bn2, const float* __restrict__ be2) {
    __shared__ float r3[128], r1[128], re[128];
    int b = blockIdx.x, tid = threadIdx.x;
    float s3 = 0.f, s1 = 0.f, se = 0.f;
    #pragma unroll
    for (int t = 0; t < 4; t++) {
        int d = tid + t*128;
        float bn = bn2[d], be = be2[d];
        s3 += bn * g_q[((size_t)(b*4 + 3))*DV_ + d];
        s1 += bn * g_q[((size_t)(b*4 + 1))*DV_ + d];
        se += be * g_q[((size_t)(b*4 + 2))*DV_ + d];
    }
    r3[tid] = s3; r1[tid] = s1; re[tid] = se;
    __syncthreads();
    for (int o = 64; o > 0; o >>= 1) {
        if (tid < o) { r3[tid] += r3[tid+o]; r1[tid] += r1[tid+o]; re[tid] += re[tid+o]; }
        __syncthreads();
    }
    if (tid == 0) { g_c3[b] = r3[0]; g_c1[b] = r1[0]; g_ce[b] = re[0]; }
}

// ------------------------- K3: node MLP1 (tf32 mma.sync) --------------------
__global__ __launch_bounds__(512, 1) void node_mma_kernel(
        const float* __restrict__ node, const float* __restrict__ Wn1,
        const float* __restrict__ bn1) {
    __shared__ unsigned As[128][20];
    __shared__ unsigned Bs[BK_][264];
    __shared__ float bs[256];

    const int tid  = threadIdx.x;
    const int warp = tid >> 5, lane = tid & 31;
    const int warpM = warp >> 2, warpN = warp & 3;
    const int g = lane >> 2, kq = lane & 3;
    const int row0 = blockIdx.x * 128;

    if (tid < 256) bs[tid] = bn1[tid];

    float acc[2][8][4];
    #pragma unroll
    for (int mt = 0; mt < 2; mt++)
        #pragma unroll
        for (int nt = 0; nt < 8; nt++)
            #pragma unroll
            for (int c = 0; c < 4; c++) acc[mt][nt][c] = 0.f;

    const int ra = tid >> 2, ca = tid & 3;
    const float* Abase = node + (size_t)row0 * DF_;

    float4 pa;
    float4 pb[2];
    {
        pa = *(const float4*)(Abase + (size_t)ra * DF_ + ca*4);
        #pragma unroll
        for (int t = 0; t < 2; t++) {
            int i4 = tid + t*512; int kr = i4 >> 6, c4 = i4 & 63;
            pb[t] = *(const float4*)(Wn1 + (size_t)kr * H_ + c4*4);
        }
    }
    const int S = DF_ / BK_;
    for (int s = 0; s < S; s++) {
        *(uint4*)&As[ra][ca*4] = make_uint4(f2tf32(pa.x), f2tf32(pa.y), f2tf32(pa.z), f2tf32(pa.w));
        #pragma unroll
        for (int t = 0; t < 2; t++) {
            int i4 = tid + t*512; int kr = i4 >> 6, c4 = i4 & 63;
            *(uint4*)&Bs[kr][c4*4] = make_uint4(f2tf32(pb[t].x), f2tf32(pb[t].y), f2tf32(pb[t].z), f2tf32(pb[t].w));
        }
        __syncthreads();
        if (s + 1 < S) {
            int k0 = (s + 1) * BK_;
            pa = *(const float4*)(Abase + (size_t)ra * DF_ + k0 + ca*4);
            #pragma unroll
            for (int t = 0; t < 2; t++) {
                int i4 = tid + t*512; int kr = i4 >> 6, c4 = i4 & 63;
                pb[t] = *(const float4*)(Wn1 + (size_t)(k0 + kr) * H_ + c4*4);
            }
        }
        #pragma unroll
        for (int kk = 0; kk < 2; kk++) {
            unsigned af[2][4], bf[8][2];
            #pragma unroll
            for (int mt = 0; mt < 2; mt++) {
                int r = warpM*32 + mt*16 + g;
                af[mt][0] = As[r    ][kk*8 + kq];
                af[mt][1] = As[r + 8][kk*8 + kq];
                af[mt][2] = As[r    ][kk*8 + kq + 4];
                af[mt][3] = As[r + 8][kk*8 + kq + 4];
            }
            #pragma unroll
            for (int nt = 0; nt < 8; nt++) {
                int n = warpN*64 + nt*8 + g;
                bf[nt][0] = Bs[kk*8 + kq    ][n];
                bf[nt][1] = Bs[kk*8 + kq + 4][n];
            }
            #pragma unroll
            for (int mt = 0; mt < 2; mt++)
                #pragma unroll
                for (int nt = 0; nt < 8; nt++) mma_tf32(acc[mt][nt], af[mt], bf[nt]);
        }
        __syncthreads();
    }
    #pragma unroll
    for (int mt = 0; mt < 2; mt++) {
        int rA = row0 + warpM*32 + mt*16 + g;
        int rB = rA + 8;
        #pragma unroll
        for (int nt = 0; nt < 8; nt++) {
            int n = warpN*64 + nt*8 + kq*2;
            float b0v = bs[n], b1v = bs[n+1];
            float2 v0 = make_float2(fmaxf(acc[mt][nt][0] + b0v, 0.f), fmaxf(acc[mt][nt][1] + b1v, 0.f));
            float2 v1 = make_float2(fmaxf(acc[mt][nt][2] + b0v, 0.f), fmaxf(acc[mt][nt][3] + b1v, 0.f));
            *(float2*)&g_hn[(size_t)rA * H_ + n] = v0;
            *(float2*)&g_hn[(size_t)rB * H_ + n] = v1;
        }
    }
}

// ------------------------- K4: filter scores --------------------------------
__global__ void score_kernel() {
    int gw = (blockIdx.x * 256 + threadIdx.x) >> 5;
    int lane = threadIdx.x & 31;
    if (gw >= NODE_ROWS) return;
    int b = gw / N_;
    const float* h  = g_hn + (size_t)gw * H_;
    const float* u3 = g_u3 + b * H_;
    const float* u1 = g_u1 + b * H_;
    float d3 = 0.f, d1 = 0.f;
    #pragma unroll
    for (int t = 0; t < 8; t++) {
        int d = lane + t*32;
        float hv = h[d];
        d3 += hv * u3[d];
        d1 += hv * u1[d];
    }
    #pragma unroll
    for (int o = 16; o > 0; o >>= 1) {
        d3 += __shfl_xor_sync(0xffffffffu, d3, o);
        d1 += __shfl_xor_sync(0xffffffffu, d1, o);
    }
    if (lane == 0) {
        g_a1[gw]   = sigmoidf_((d3 + g_c3[b]) * SCALE_);
        g_sig1[gw] = sigmoidf_((d1 + g_c1[b]) * SCALE_);
    }
}

// ------------------------- K5a: edge GEMM via tcgen05, M=256/CTA ------------
// Two 128-row D tiles share each B chunk. LDG->regs->(rna)STS feed with
// register prefetch of the next chunk overlapping the MMA. 648 CTAs.
#define EDGE_SMEM_DYN (1024 + 2*65536)
__global__ __launch_bounds__(256, 1)
void edge_tc2_kernel(const float* __restrict__ edge, const float* __restrict__ be1) {
#if HAS_TC
    extern __shared__ char dsm[];
    __shared__ uint32_t sh_tmem;
    __shared__ uint64_t sh_mbar[2];
    __shared__ float bs[256], vs0[256], vs1[256];
    __shared__ float ces[2];

    const int tid = threadIdx.x, warp = tid >> 5, lane = tid & 31;
    const int row0 = blockIdx.x * 256;

    const int b0 = row0 / ROWS_PER_B;
    const int bn_ = (b0 + 1 < B_) ? b0 + 1 : b0;
    const int split = (b0 + 1) * ROWS_PER_B - row0;   // local rows >= split -> batch bn_

    uint32_t dbase = smem_u32(dsm);
    uint32_t aligned = (dbase + 1023u) & ~1023u;
    char* smbase = dsm + (aligned - dbase);

    if (warp == 0) { TC_ALLOC(smem_u32(&sh_tmem), 512); TC_RELINQ(); }
    if (tid == 0) {
        MBAR_INIT(smem_u32(&sh_mbar[0]), 1);
        MBAR_INIT(smem_u32(&sh_mbar[1]), 1);
        ces[0] = g_ce[b0]; ces[1] = g_ce[bn_];
    }
    bs[tid]  = be1[tid];
    vs0[tid] = g_v[b0  * H_ + tid];
    vs1[tid] = g_v[bn_ * H_ + tid];
    __syncthreads();

    const uint32_t tmem = sh_tmem;
    uint32_t mb[2] = { smem_u32(&sh_mbar[0]), smem_u32(&sh_mbar[1]) };
    const float* Abase = edge + (size_t)row0 * DE_;

    float4 pa[8], pb[8];
    const int rA = tid >> 3, cA = tid & 7;   // row base (0..31), col group

    // prefetch chunk 0
    #pragma unroll
    for (int t = 0; t < 8; t++)
        pa[t] = *(const float4*)(Abase + (size_t)(rA + t*32) * DE_ + cA*4);
    #pragma unroll
    for (int t = 0; t < 8; t++)
        pb[t] = *(const float4*)(g_We1T + (size_t)(rA + t*32) * DE_ + cA*4);

    #pragma unroll 1
    for (int c = 0; c < 8; c++) {
        const int buf = c & 1;
        if (c >= 2) mbar_wait_parity(mb[buf], (uint32_t)((c - 2) >> 1) & 1u);
        // STS chunk c (A rna-rounded; B pre-rounded at transpose... rounded here too)
        {
            char* st = smbase + (size_t)buf * 65536u;
            #pragma unroll
            for (int t = 0; t < 8; t++) {
                int r = rA + t*32;                       // 0..255
                uint32_t byte = (uint32_t)((r & 127)*128 + cA*16);
                uint32_t off = ((uint32_t)(r >> 7) << 14) + (byte ^ ((byte>>3)&0x70u));
                *(uint4*)(st + off) =
                    make_uint4(f2tf32(pa[t].x), f2tf32(pa[t].y), f2tf32(pa[t].z), f2tf32(pa[t].w));
            }
            #pragma unroll
            for (int t = 0; t < 8; t++) {
                int n = rA + t*32;
                uint32_t byte = (uint32_t)(n*128 + cA*16);
                *(uint4*)(st + 32768u + (byte ^ ((byte>>3)&0x70u))) =
                    make_uint4(f2tf32(pb[t].x), f2tf32(pb[t].y), f2tf32(pb[t].z), f2tf32(pb[t].w));
            }
        }
        // prefetch chunk c+1 (overlaps fence/sync/MMA)
        if (c + 1 < 8) {
            int k0 = (c + 1) * 32;
            #pragma unroll
            for (int t = 0; t < 8; t++)
                pa[t] = *(const float4*)(Abase + (size_t)(rA + t*32) * DE_ + k0 + cA*4);
            #pragma unroll
            for (int t = 0; t < 8; t++)
                pb[t] = *(const float4*)(g_We1T + (size_t)(rA + t*32) * DE_ + k0 + cA*4);
        }
        FENCE_PROXY_ASYNC();
        __syncthreads();
        if (warp == 0) {
            if (elect_one_pred()) {
                uint32_t st = aligned + (uint32_t)buf * 65536u;
                uint64_t ad0 = make_desc(st);
                uint64_t ad1 = make_desc(st + 16384u);
                uint64_t bd  = make_desc(st + 32768u);
                #pragma unroll
                for (int s = 0; s < 4; s++) {
                    bool acc = (c > 0) || (s > 0);
                    tc_mma_tf32_ss(tmem,        ad0 + 2*s, bd + 2*s, EDGE_IDESC, acc);
                    tc_mma_tf32_ss(tmem + 256u, ad1 + 2*s, bd + 2*s, EDGE_IDESC, acc);
                }
                TC_COMMIT(mb[buf]);
            }
        }
    }
    // mb0/mb1 each complete 4 times; in-loop consumed #1..#3; #4 -> parity 1
    mbar_wait_parity(mb[0], 1u);
    mbar_wait_parity(mb[1], 1u);
    TC_FENCE_AFTER();

    // epilogue: warp w -> D tile (w>>2), rows (w&3)*32+lane
    {
        const int half = warp >> 2;
        const int rlocal = half*128 + (warp & 3)*32 + lane;
        const float* vrow = (rlocal < split) ? vs0 : vs1;
        const uint32_t tb = tmem + (uint32_t)(half ? 256 : 0);
        float s = 0.f;
        #pragma unroll
        for (int it = 0; it < 8; it++) {
            uint32_t d[32];
            LDTM_X32(d, tb + it*32);
            TC_WAIT_LD();
            #pragma unroll
            for (int cc = 0; cc < 32; cc++) {
                int n = it*32 + cc;
                float h = fmaxf(__uint_as_float(d[cc]) + bs[n], 0.f);
                s += h * vrow[n];
            }
        }
        float ce = (rlocal < split) ? ces[0] : ces[1];
        g_weit[row0 + rlocal] = sigmoidf_((s + ce) * SCALE_);
    }
    __syncthreads();
    if (tid == 0) { MBAR_INVAL(mb[0]); MBAR_INVAL(mb[1]); }
    if (warp == 0) TC_DEALLOC(tmem, 512);
#else
    (void)edge; (void)be1;
#endif
}

// ------------------------- K5b: edge GEMM via mma.sync (base pass) ----------
__global__ __launch_bounds__(512, 1) void edge_mma_kernel(
        const float* __restrict__ edge, const float* __restrict__ We1,
        const float* __restrict__ be1) {
#if !HAS_TC
    __shared__ unsigned As[128][20];
    __shared__ unsigned Bs[BK_][264];
    __shared__ float s_sh[128];
    __shared__ float bs[256], vs0[256], vs1[256];
    __shared__ float ces[2];

    const int tid  = threadIdx.x;
    const int warp = tid >> 5, lane = tid & 31;
    const int warpM = warp >> 2, warpN = warp & 3;
    const int g = lane >> 2, kq = lane & 3;
    const int row0 = blockIdx.x * 128;

    const int b0 = row0 / ROWS_PER_B;
    const int bn_ = (b0 + 1 < B_) ? b0 + 1 : b0;
    const int split = (b0 + 1) * ROWS_PER_B - row0;

    if (tid < 256) {
        bs[tid]  = be1[tid];
        vs0[tid] = g_v[b0  * H_ + tid];
        vs1[tid] = g_v[bn_ * H_ + tid];
    }
    if (tid < 128) s_sh[tid] = 0.f;
    if (tid == 0) { ces[0] = g_ce[b0]; ces[1] = g_ce[bn_]; }

    float acc[2][8][4];
    #pragma unroll
    for (int mt = 0; mt < 2; mt++)
        #pragma unroll
        for (int nt = 0; nt < 8; nt++)
            #pragma unroll
            for (int c = 0; c < 4; c++) acc[mt][nt][c] = 0.f;

    const int ra = tid >> 2, ca = tid & 3;
    const float* Abase = edge + (size_t)row0 * DE_;

    float4 pa;
    float4 pb[2];
    {
        pa = *(const float4*)(Abase + (size_t)ra * DE_ + ca*4);
        #pragma unroll
        for (int t = 0; t < 2; t++) {
            int i4 = tid + t*512; int kr = i4 >> 6, c4 = i4 & 63;
            pb[t] = *(const float4*)(We1 + (size_t)kr * 256 + c4*4);
        }
    }
    const int S = DE_ / BK_;
    for (int s = 0; s < S; s++) {
        *(uint4*)&As[ra][ca*4] = make_uint4(f2tf32(pa.x), f2tf32(pa.y), f2tf32(pa.z), f2tf32(pa.w));
        #pragma unroll
        for (int t = 0; t < 2; t++) {
            int i4 = tid + t*512; int kr = i4 >> 6, c4 = i4 & 63;
            *(uint4*)&Bs[kr][c4*4] = make_uint4(f2tf32(pb[t].x), f2tf32(pb[t].y), f2tf32(pb[t].z), f2tf32(pb[t].w));
        }
        __syncthreads();
        if (s + 1 < S) {
            int k0 = (s + 1) * BK_;
            pa = *(const float4*)(Abase + (size_t)ra * DE_ + k0 + ca*4);
            #pragma unroll
            for (int t = 0; t < 2; t++) {
                int i4 = tid + t*512; int kr = i4 >> 6, c4 = i4 & 63;
                pb[t] = *(const float4*)(We1 + (size_t)(k0 + kr) * 256 + c4*4);
            }
        }
        #pragma unroll
        for (int kk = 0; kk < 2; kk++) {
            unsigned af[2][4], bf[8][2];
            #pragma unroll
            for (int mt = 0; mt < 2; mt++) {
                int r = warpM*32 + mt*16 + g;
                af[mt][0] = As[r    ][kk*8 + kq];
                af[mt][1] = As[r + 8][kk*8 + kq];
                af[mt][2] = As[r    ][kk*8 + kq + 4];
                af[mt][3] = As[r + 8][kk*8 + kq + 4];
            }
            #pragma unroll
            for (int nt = 0; nt < 8; nt++) {
                int n = warpN*64 + nt*8 + g;
                bf[nt][0] = Bs[kk*8 + kq    ][n];
                bf[nt][1] = Bs[kk*8 + kq + 4][n];
            }
            #pragma unroll
            for (int mt = 0; mt < 2; mt++)
                #pragma unroll
                for (int nt = 0; nt < 8; nt++) mma_tf32(acc[mt][nt], af[mt], bf[nt]);
        }
        __syncthreads();
    }
    #pragma unroll
    for (int mt = 0; mt < 2; mt++) {
        int rA = warpM*32 + mt*16 + g;
        int rB = rA + 8;
        const float* vA = (rA < split) ? vs0 : vs1;
        const float* vB = (rB < split) ? vs0 : vs1;
        float pA = 0.f, pB = 0.f;
        #pragma unroll
        for (int nt = 0; nt < 8; nt++) {
            int n = warpN*64 + nt*8 + kq*2;
            float b0v = bs[n], b1v = bs[n+1];
            pA += fmaxf(acc[mt][nt][0] + b0v, 0.f) * vA[n]
                + fmaxf(acc[mt][nt][1] + b1v, 0.f) * vA[n+1];
            pB += fmaxf(acc[mt][nt][2] + b0v, 0.f) * vB[n]
                + fmaxf(acc[mt][nt][3] + b1v, 0.f) * vB[n+1];
        }
        pA += __shfl_xor_sync(0xffffffffu, pA, 1);
        pA += __shfl_xor_sync(0xffffffffu, pA, 2);
        pB += __shfl_xor_sync(0xffffffffu, pB, 1);
        pB += __shfl_xor_sync(0xffffffffu, pB, 2);
        if (kq == 0) {
            atomicAdd(&s_sh[rA], pA);
            atomicAdd(&s_sh[rB], pB);
        }
    }
    __syncthreads();
    if (tid < 128) {
        float ce = (tid < split) ? ces[0] : ces[1];
        g_weit[row0 + tid] = sigmoidf_((s_sh[tid] + ce) * SCALE_);
    }
#else
    (void)edge; (void)We1; (void)be1;
#endif
}

// ------------------------- K6: attention chain + pooled hidden --------------
__global__ void combine_kernel() {
    int b = blockIdx.x;
    int tid = threadIdx.x;
    __shared__ float a1s[N_];
    __shared__ float a3s[N_];
    __shared__ float sInv, sS;
    if (tid < N_) a1s[tid] = g_a1[b * N_ + tid];
    __syncthreads();
    if (tid < N_) {
        int j = tid;
        float acc = 0.f;
        const float* w = g_weit + (size_t)b * ROWS_PER_B;
        #pragma unroll
        for (int i = 0; i < N_; i++) acc += a1s[i] * w[i * N_ + j];
        acc = fminf(fmaxf(acc, 0.f), 1.f);
        a3s[j] = acc * g_sig1[b * N_ + j];
    }
    __syncthreads();
    if (tid == 0) {
        float s0 = 0.f;
        #pragma unroll
        for (int j = 0; j < N_; j++) s0 += a3s[j];
        float inv = 1.f / (s0 + 1e-8f);
        sInv = inv;
        sS = s0 * inv;
    }
    __syncthreads();
    {
        int h = tid;
        float acc = 0.f;
        #pragma unroll
        for (int j = 0; j < N_; j++)
            acc += a3s[j] * g_hn[((size_t)(b * N_ + j)) * H_ + h];
        g_ph[b * H_ + h] = acc * sInv;
    }
    if (tid == 0) g_S[b] = sS;
}

// ------------------------- K7: final chain, 32x32 tiled GEMM stages ---------
// stage selects A/C from device globals IN DEVICE CODE (host passes only true
// input pointers + the harness out pointer).
__global__ __launch_bounds__(256) void final_mm_kernel(
        int stage, const float* __restrict__ W, const float* __restrict__ bias,
        float* __restrict__ outp) {
    __shared__ float As[32][36];
    __shared__ float Ws[32][32];

    const float* A; float* C; int N, K, mode;
    if (stage == 0)      { A = g_ph;   C = g_gbuf; N = DV_; K = H_;  mode = 1; }
    else if (stage == 1) { A = g_gbuf; C = g_obuf; N = DV_; K = DV_; mode = 0; }
    else if (stage == 2) { A = g_obuf; C = g_h2;   N = H_;  K = DV_; mode = 0; }
    else                 { A = g_h2;   C = outp;   N = NC_; K = H_;  mode = 2; }

    const int tid = threadIdx.x;
    const int m0 = blockIdx.x * 32, n0 = blockIdx.y * 32;
    const int r = tid >> 3, cg = tid & 7;
    float acc[4] = {0.f, 0.f, 0.f, 0.f};

    const int lrow = tid >> 3, lk4 = (tid & 7) * 4;
    for (int k0 = 0; k0 < K; k0 += 32) {
        float4 av = *(const float4*)(A + (size_t)(m0 + lrow) * K + k0 + lk4);
        *(float4*)&As[lrow][lk4] = av;
        #pragma unroll
        for (int u = 0; u < 4; u++) {
            int n = n0 + lk4 + u;
            Ws[lrow][lk4 + u] = (n < N) ? W[(size_t)(k0 + lrow) * N + n] : 0.f;
        }
        __syncthreads();
        #pragma unroll
        for (int k = 0; k < 32; k++) {
            float a = As[r][k];
            float4 w = *(const float4*)&Ws[k][cg*4];
            acc[0] += a * w.x; acc[1] += a * w.y; acc[2] += a * w.z; acc[3] += a * w.w;
        }
        __syncthreads();
    }
    const int row = m0 + r;
    #pragma unroll
    for (int u = 0; u < 4; u++) {
        int n = n0 + cg*4 + u;
        if (n >= N) continue;
        float x = acc[u];
        if (mode == 0)      x = fmaxf(x + bias[n], 0.f);
        else if (mode == 1) x = (x + g_S[row] * bias[n]) * g_q[((size_t)(row*4 + 0))*DV_ + n];
        else                x = x + bias[n];
        C[(size_t)row * N + n] = x;
    }
}

// ------------------------- launch ------------------------------------------
extern "C" void kernel_launch(void* const* d_in, const int* in_sizes, int n_in,
                              void* d_out, int out_size) {
    const float* node     = (const float*)d_in[0];
    const float* edge     = (const float*)d_in[1];
    const float* Wn1      = (const float*)d_in[2];
    const float* bn1      = (const float*)d_in[3];
    const float* Wn2      = (const float*)d_in[4];
    const float* bn2      = (const float*)d_in[5];
    const float* We1      = (const float*)d_in[6];
    const float* be1      = (const float*)d_in[7];
    const float* We2      = (const float*)d_in[8];
    const float* be2      = (const float*)d_in[9];
    const float* Wq       = (const float*)d_in[10];
    const float* bq       = (const float*)d_in[11];
    const float* Wc1      = (const float*)d_in[12];
    const float* bc1      = (const float*)d_in[13];
    const float* Wc2      = (const float*)d_in[14];
    const float* bc2      = (const float*)d_in[15];
    const float* word_emb = (const float*)d_in[16];
    const int* prog_in    = (const int*)d_in[18];
    float* out            = (float*)d_out;

    static int smem_set = 0;
    if (!smem_set) {
        cudaFuncSetAttribute(edge_tc2_kernel,
                             cudaFuncAttributeMaxDynamicSharedMemorySize, EDGE_SMEM_DYN);
        smem_set = 1;
    }

    transpose_We1_kernel<<<dim3(8, 8), dim3(32, 32)>>>(We1);
    gather_q_kernel<<<(B_*4*DV_)/256, 256>>>(word_emb, prog_in);
    proj2_kernel<<<dim3(8, 2, 3), 256>>>(Wn2, We2);
    scal_kernel<<<B_, 128>>>(bn2, be2);
    node_mma_kernel<<<NODE_ROWS/128, 512>>>(node, Wn1, bn1);
    score_kernel<<<NODE_ROWS/8, 256>>>();

    // edge GEMM: M=256/CTA tcgen05 (tc pass) / mma.sync (base pass)
    edge_tc2_kernel<<<EDGE_ROWS/256, 256, EDGE_SMEM_DYN>>>(edge, be1);
    edge_mma_kernel<<<EDGE_ROWS/128, 512>>>(edge, We1, be1);

    combine_kernel<<<B_, 256>>>();

    // final GEMV chain as tiled GEMMs (scratch selected in device code)
    final_mm_kernel<<<dim3(4, 16), 256>>>(0, Wn2, bn2, out);
    final_mm_kernel<<<dim3(4, 16), 256>>>(1, Wq,  bq,  out);
    final_mm_kernel<<<dim3(4, 8),  256>>>(2, Wc1, bc1, out);
    final_mm_kernel<<<dim3(4, 1),  256>>>(3, Wc2, bc2, out);
}

// round 13
// speedup vs baseline: 1.1542x; 1.0648x over previous
#include <cuda_runtime.h>
#include <math.h>
#include <stdint.h>

// Dims (CLEVR-scale, fixed)
#define B_   128
#define N_   36
#define DF_  512
#define DE_  256
#define DV_  512
#define H_   256
#define NC_  28
#define L_   5
#define ROWS_PER_B (N_*N_)          // 1296
#define NODE_ROWS  (B_*N_)          // 4608
#define EDGE_ROWS  (B_*ROWS_PER_B)  // 165888
#define SCALE_ 0.04419417382415922f // 1/sqrt(512)
#define BK_ 16

// Feature gate: tcgen05 exists only in arch-specific (sm_103a / sm_100a) passes.
#if defined(__CUDA_ARCH_FEAT_SM103_ALL) || defined(__CUDA_ARCH_FEAT_SM100_ALL) || defined(__CUDA_ARCH_FEAT_SM101_ALL)
#define HAS_TC 1
#else
#define HAS_TC 0
#endif

// ------------------------- device scratch (no cudaMalloc allowed) -----------
// RULE (rounds 5-10 bug): these symbols are ONLY referenced inside device
// code. Never pass them as host-side kernel args.
__device__ float g_hn[NODE_ROWS * H_];
__device__ float g_q[B_ * 4 * DV_];
__device__ float g_u3[B_ * H_];
__device__ float g_u1[B_ * H_];
__device__ float g_v [B_ * H_];
__device__ float g_c3[B_];
__device__ float g_c1[B_];
__device__ float g_ce[B_];
__device__ float g_a1  [NODE_ROWS];
__device__ float g_sig1[NODE_ROWS];
__device__ float g_weit[EDGE_ROWS];
__device__ float g_ph[B_ * H_];
__device__ float g_S [B_];
__device__ float g_We1T[H_ * DE_];   // We1^T [n][k]
__device__ float g_Wn1T[H_ * DF_];   // Wn1^T [n][k]
__device__ float g_gbuf[B_ * DV_];
__device__ float g_obuf[B_ * DV_];
__device__ float g_h2  [B_ * H_];

__device__ __forceinline__ float sigmoidf_(float x) { return 1.0f / (1.0f + expf(-x)); }
__device__ __forceinline__ unsigned f2tf32(float x) {
    unsigned u; asm("cvt.rna.tf32.f32 %0, %1;" : "=r"(u) : "f"(x)); return u;
}
__device__ __forceinline__ void mma_tf32(float c[4], const unsigned a[4], const unsigned b[2]) {
    asm volatile("mma.sync.aligned.m16n8k8.row.col.f32.tf32.tf32.f32 "
        "{%0,%1,%2,%3}, {%4,%5,%6,%7}, {%8,%9}, {%0,%1,%2,%3};"
        : "+f"(c[0]), "+f"(c[1]), "+f"(c[2]), "+f"(c[3])
        : "r"(a[0]), "r"(a[1]), "r"(a[2]), "r"(a[3]), "r"(b[0]), "r"(b[1]));
}

// ------------------------- tcgen05 helpers ----------------------------------
__device__ __forceinline__ uint32_t smem_u32(const void* p) {
    uint32_t a;
    asm("{ .reg .u64 t; cvta.to.shared.u64 t, %1; cvt.u32.u64 %0, t; }" : "=r"(a) : "l"(p));
    return a;
}
__device__ __forceinline__ uint32_t elect_one_pred() {
    uint32_t pred;
    asm volatile("{\n\t.reg .pred p;\n\telect.sync _|p, 0xFFFFFFFF;\n\t"
                 "selp.b32 %0, 1, 0, p;\n\t}" : "=r"(pred));
    return pred;
}
static __device__ constexpr uint64_t SMEM_DESC_BASE_SW128 =
    (uint64_t(2)  << 61) | (uint64_t(1) << 46) | (uint64_t(64) << 32) | (uint64_t(1) << 16);
__device__ __forceinline__ uint64_t make_desc(uint32_t addr) {
    return SMEM_DESC_BASE_SW128 | ((uint64_t)(addr >> 4) & 0x3FFF);
}
// tf32 SS idesc: dtype=F32(1<<4), a/btype=TF32(2<<7,2<<10), N/8<<17, M/16<<24
#define EDGE_IDESC 0x8400910u

#if HAS_TC
__device__ __forceinline__ void tc_mma_tf32_ss(uint32_t d_tmem, uint64_t a_desc,
                                               uint64_t b_desc, uint32_t idesc, bool accum) {
    uint32_t en = accum ? 1u : 0u;
    asm volatile(
        "{\n\t.reg .pred p;\n\t"
        "setp.ne.u32 p, %5, 0;\n\t"
        "tcgen05.mma.cta_group::1.kind::tf32 [%0], %1, %2, %3, {%4, %4, %4, %4}, p;\n\t}"
        :: "r"(d_tmem), "l"(a_desc), "l"(b_desc), "r"(idesc), "r"(0u), "r"(en)
        : "memory");
}
#define TC_ALLOC(smem_addr, n) \
    asm volatile("tcgen05.alloc.cta_group::1.sync.aligned.shared::cta.b32 [%0], %1;" \
                 :: "r"((uint32_t)(smem_addr)), "r"((uint32_t)(n)) : "memory")
#define TC_DEALLOC(tmem, n) \
    asm volatile("tcgen05.dealloc.cta_group::1.sync.aligned.b32 %0, %1;" :: "r"(tmem), "r"((uint32_t)(n)))
#define TC_RELINQ() asm volatile("tcgen05.relinquish_alloc_permit.cta_group::1.sync.aligned;")
#define TC_COMMIT(mbar) \
    asm volatile("tcgen05.commit.cta_group::1.mbarrier::arrive::one.shared::cluster.b64 [%0];" \
                 :: "r"((uint32_t)(mbar)) : "memory")
#define TC_FENCE_AFTER()  asm volatile("tcgen05.fence::after_thread_sync;" ::: "memory")
#define TC_WAIT_LD()      asm volatile("tcgen05.wait::ld.sync.aligned;" ::: "memory")
#define MBAR_INIT(addr, cnt) \
    asm volatile("mbarrier.init.shared.b64 [%0], %1;" :: "r"((uint32_t)(addr)), "r"((uint32_t)(cnt)) : "memory")
#define MBAR_INVAL(addr) \
    asm volatile("mbarrier.inval.shared.b64 [%0];" :: "r"((uint32_t)(addr)) : "memory")
#define FENCE_PROXY_ASYNC() asm volatile("fence.proxy.async.shared::cta;" ::: "memory")
__device__ __forceinline__ void mbar_wait_parity(uint32_t addr, uint32_t parity) {
    asm volatile(
        "{\n\t.reg .pred P1;\n\t"
        "WAIT_%=:\n\t"
        "mbarrier.try_wait.parity.acquire.cta.shared::cta.b64 P1, [%0], %1, 0x989680;\n\t"
        "@P1 bra.uni DONE_%=;\n\t"
        "bra.uni WAIT_%=;\n\t"
        "DONE_%=:\n\t}"
        :: "r"(addr), "r"(parity) : "memory");
}
#define LDTM_X32(r, addr) \
    asm volatile( \
        "tcgen05.ld.sync.aligned.32x32b.x32.b32 " \
        "{%0, %1, %2, %3, %4, %5, %6, %7, " \
        " %8, %9, %10, %11, %12, %13, %14, %15, " \
        " %16, %17, %18, %19, %20, %21, %22, %23, " \
        " %24, %25, %26, %27, %28, %29, %30, %31}, [%32];" \
        : "=r"((r)[0]),  "=r"((r)[1]),  "=r"((r)[2]),  "=r"((r)[3]), \
          "=r"((r)[4]),  "=r"((r)[5]),  "=r"((r)[6]),  "=r"((r)[7]), \
          "=r"((r)[8]),  "=r"((r)[9]),  "=r"((r)[10]), "=r"((r)[11]), \
          "=r"((r)[12]), "=r"((r)[13]), "=r"((r)[14]), "=r"((r)[15]), \
          "=r"((r)[16]), "=r"((r)[17]), "=r"((r)[18]), "=r"((r)[19]), \
          "=r"((r)[20]), "=r"((r)[21]), "=r"((r)[22]), "=r"((r)[23]), \
          "=r"((r)[24]), "=r"((r)[25]), "=r"((r)[26]), "=r"((r)[27]), \
          "=r"((r)[28]), "=r"((r)[29]), "=r"((r)[30]), "=r"((r)[31]) \
        : "r"(addr))
#endif // HAS_TC

// ------------------------- K0a: transpose We1 -------------------------------
__global__ void transpose_We1_kernel(const float* __restrict__ We1) {
    __shared__ float t[32][33];
    int bx = blockIdx.x * 32;   // n block
    int by = blockIdx.y * 32;   // k block
    t[threadIdx.y][threadIdx.x] = We1[(size_t)(by + threadIdx.y) * H_ + bx + threadIdx.x];
    __syncthreads();
    g_We1T[(size_t)(bx + threadIdx.y) * DE_ + by + threadIdx.x] = t[threadIdx.x][threadIdx.y];
}

// ------------------------- K0b: transpose Wn1 -------------------------------
// Wn1 [DF_=512][H_=256] -> g_Wn1T [256][512]. grid (8, 16), block (32,32).
__global__ void transpose_Wn1_kernel(const float* __restrict__ Wn1) {
    __shared__ float t[32][33];
    int bx = blockIdx.x * 32;   // n block (0..255)
    int by = blockIdx.y * 32;   // k block (0..511)
    t[threadIdx.y][threadIdx.x] = Wn1[(size_t)(by + threadIdx.y) * H_ + bx + threadIdx.x];
    __syncthreads();
    g_Wn1T[(size_t)(bx + threadIdx.y) * DF_ + by + threadIdx.x] = t[threadIdx.x][threadIdx.y];
}

// ------------------------- K1: gather q -------------------------------------
__global__ void gather_q_kernel(const float* __restrict__ word_emb,
                                const int* __restrict__ prog_in) {
    int idx = blockIdx.x * 256 + threadIdx.x;
    int d = idx & (DV_ - 1);
    int l = (idx >> 9) & 3;
    int b = idx >> 11;
    int w = prog_in[b * L_ + l];
    g_q[idx] = word_emb[(size_t)w * DV_ + d];
}

// ------------------------- K2: projections u3,u1,v + scalars c3,c1,ce -------
__global__ __launch_bounds__(256) void proj2_kernel(const float* __restrict__ Wn2,
                                                    const float* __restrict__ We2,
                                                    const float* __restrict__ bn2,
                                                    const float* __restrict__ be2) {
    __shared__ float qs[16][512];
    const int bg = blockIdx.x, hh = blockIdx.y, wh = blockIdx.z;
    const int tid = threadIdx.x, warp = tid >> 5, lane = tid & 31;
    const float* W = (wh < 2) ? Wn2 : We2;
    const int l = (wh == 0) ? 3 : (wh == 1) ? 1 : 2;
    float* U = (wh == 0) ? g_u3 : (wh == 1) ? g_u1 : g_v;

    for (int i = tid; i < 16 * 512 / 4; i += 256) {
        int bl = i >> 7, d4 = (i & 127) * 4;
        ((float4*)&qs[bl][d4])[0] = *(const float4*)(g_q + ((size_t)((bg*16 + bl)*4 + l))*DV_ + d4);
    }
    __syncthreads();

    for (int hi = 0; hi < 128; hi++) {
        int h = hh * 128 + hi;
        const float* wr = W + (size_t)h * DV_;
        float w[16];
        #pragma unroll
        for (int t = 0; t < 16; t++) w[t] = wr[lane + t*32];
        #pragma unroll
        for (int bb = 0; bb < 2; bb++) {
            int bl = warp * 2 + bb;
            float acc = 0.f;
            #pragma unroll
            for (int t = 0; t < 16; t++) acc += w[t] * qs[bl][lane + t*32];
            #pragma unroll
            for (int o = 16; o > 0; o >>= 1) acc += __shfl_xor_sync(0xffffffffu, acc, o);
            if (lane == 0) U[(bg*16 + bl) * H_ + h] = acc;
        }
    }
    // fused scalar dots (once per batch; hh==0 blocks only)
    if (hh == 0) {
        const float* bias = (wh < 2) ? bn2 : be2;
        float* cdst = (wh == 0) ? g_c3 : (wh == 1) ? g_c1 : g_ce;
        #pragma unroll
        for (int bb = 0; bb < 2; bb++) {
            int bl = warp * 2 + bb;
            float acc = 0.f;
            #pragma unroll
            for (int t = 0; t < 16; t++) acc += bias[lane + t*32] * qs[bl][lane + t*32];
            #pragma unroll
            for (int o = 16; o > 0; o >>= 1) acc += __shfl_xor_sync(0xffffffffu, acc, o);
            if (lane == 0) cdst[bg*16 + bl] = acc;
        }
    }
}

// ------------------------- K5a: edge GEMM via tcgen05, M=256/CTA ------------
#define EDGE_SMEM_DYN (1024 + 2*65536)
__global__ __launch_bounds__(256, 1)
void edge_tc2_kernel(const float* __restrict__ edge, const float* __restrict__ be1) {
#if HAS_TC
    extern __shared__ char dsm[];
    __shared__ uint32_t sh_tmem;
    __shared__ uint64_t sh_mbar[2];
    __shared__ float bs[256], vs0[256], vs1[256];
    __shared__ float ces[2];

    const int tid = threadIdx.x, warp = tid >> 5, lane = tid & 31;
    const int row0 = blockIdx.x * 256;

    const int b0 = row0 / ROWS_PER_B;
    const int bn_ = (b0 + 1 < B_) ? b0 + 1 : b0;
    const int split = (b0 + 1) * ROWS_PER_B - row0;

    uint32_t dbase = smem_u32(dsm);
    uint32_t aligned = (dbase + 1023u) & ~1023u;
    char* smbase = dsm + (aligned - dbase);

    if (warp == 0) { TC_ALLOC(smem_u32(&sh_tmem), 512); TC_RELINQ(); }
    if (tid == 0) {
        MBAR_INIT(smem_u32(&sh_mbar[0]), 1);
        MBAR_INIT(smem_u32(&sh_mbar[1]), 1);
        ces[0] = g_ce[b0]; ces[1] = g_ce[bn_];
    }
    bs[tid]  = be1[tid];
    vs0[tid] = g_v[b0  * H_ + tid];
    vs1[tid] = g_v[bn_ * H_ + tid];
    __syncthreads();

    const uint32_t tmem = sh_tmem;
    uint32_t mb[2] = { smem_u32(&sh_mbar[0]), smem_u32(&sh_mbar[1]) };
    const float* Abase = edge + (size_t)row0 * DE_;

    float4 pa[8], pb[8];
    const int rA = tid >> 3, cA = tid & 7;

    #pragma unroll
    for (int t = 0; t < 8; t++)
        pa[t] = *(const float4*)(Abase + (size_t)(rA + t*32) * DE_ + cA*4);
    #pragma unroll
    for (int t = 0; t < 8; t++)
        pb[t] = *(const float4*)(g_We1T + (size_t)(rA + t*32) * DE_ + cA*4);

    #pragma unroll 1
    for (int c = 0; c < 8; c++) {
        const int buf = c & 1;
        if (c >= 2) mbar_wait_parity(mb[buf], (uint32_t)((c - 2) >> 1) & 1u);
        {
            char* st = smbase + (size_t)buf * 65536u;
            #pragma unroll
            for (int t = 0; t < 8; t++) {
                int r = rA + t*32;
                uint32_t byte = (uint32_t)((r & 127)*128 + cA*16);
                uint32_t off = ((uint32_t)(r >> 7) << 14) + (byte ^ ((byte>>3)&0x70u));
                *(uint4*)(st + off) =
                    make_uint4(f2tf32(pa[t].x), f2tf32(pa[t].y), f2tf32(pa[t].z), f2tf32(pa[t].w));
            }
            #pragma unroll
            for (int t = 0; t < 8; t++) {
                int n = rA + t*32;
                uint32_t byte = (uint32_t)(n*128 + cA*16);
                *(uint4*)(st + 32768u + (byte ^ ((byte>>3)&0x70u))) =
                    make_uint4(f2tf32(pb[t].x), f2tf32(pb[t].y), f2tf32(pb[t].z), f2tf32(pb[t].w));
            }
        }
        if (c + 1 < 8) {
            int k0 = (c + 1) * 32;
            #pragma unroll
            for (int t = 0; t < 8; t++)
                pa[t] = *(const float4*)(Abase + (size_t)(rA + t*32) * DE_ + k0 + cA*4);
            #pragma unroll
            for (int t = 0; t < 8; t++)
                pb[t] = *(const float4*)(g_We1T + (size_t)(rA + t*32) * DE_ + k0 + cA*4);
        }
        FENCE_PROXY_ASYNC();
        __syncthreads();
        if (warp == 0) {
            if (elect_one_pred()) {
                uint32_t st = aligned + (uint32_t)buf * 65536u;
                uint64_t ad0 = make_desc(st);
                uint64_t ad1 = make_desc(st + 16384u);
                uint64_t bd  = make_desc(st + 32768u);
                #pragma unroll
                for (int s = 0; s < 4; s++) {
                    bool acc = (c > 0) || (s > 0);
                    tc_mma_tf32_ss(tmem,        ad0 + 2*s, bd + 2*s, EDGE_IDESC, acc);
                    tc_mma_tf32_ss(tmem + 256u, ad1 + 2*s, bd + 2*s, EDGE_IDESC, acc);
                }
                TC_COMMIT(mb[buf]);
            }
        }
    }
    mbar_wait_parity(mb[0], 1u);
    mbar_wait_parity(mb[1], 1u);
    TC_FENCE_AFTER();

    {
        const int half = warp >> 2;
        const int rlocal = half*128 + (warp & 3)*32 + lane;
        const float* vrow = (rlocal < split) ? vs0 : vs1;
        const uint32_t tb = tmem + (uint32_t)(half ? 256 : 0);
        float s = 0.f;
        #pragma unroll
        for (int it = 0; it < 8; it++) {
            uint32_t d[32];
            LDTM_X32(d, tb + it*32);
            TC_WAIT_LD();
            #pragma unroll
            for (int cc = 0; cc < 32; cc++) {
                int n = it*32 + cc;
                float h = fmaxf(__uint_as_float(d[cc]) + bs[n], 0.f);
                s += h * vrow[n];
            }
        }
        float ce = (rlocal < split) ? ces[0] : ces[1];
        g_weit[row0 + rlocal] = sigmoidf_((s + ce) * SCALE_);
    }
    __syncthreads();
    if (tid == 0) { MBAR_INVAL(mb[0]); MBAR_INVAL(mb[1]); }
    if (warp == 0) TC_DEALLOC(tmem, 512);
#else
    (void)edge; (void)be1;
#endif
}

// ------------------------- K5b: edge GEMM via mma.sync (base pass) ----------
__global__ __launch_bounds__(512, 1) void edge_mma_kernel(
        const float* __restrict__ edge, const float* __restrict__ We1,
        const float* __restrict__ be1) {
#if !HAS_TC
    __shared__ unsigned As[128][20];
    __shared__ unsigned Bs[BK_][264];
    __shared__ float s_sh[128];
    __shared__ float bs[256], vs0[256], vs1[256];
    __shared__ float ces[2];

    const int tid  = threadIdx.x;
    const int warp = tid >> 5, lane = tid & 31;
    const int warpM = warp >> 2, warpN = warp & 3;
    const int g = lane >> 2, kq = lane & 3;
    const int row0 = blockIdx.x * 128;

    const int b0 = row0 / ROWS_PER_B;
    const int bn_ = (b0 + 1 < B_) ? b0 + 1 : b0;
    const int split = (b0 + 1) * ROWS_PER_B - row0;

    if (tid < 256) {
        bs[tid]  = be1[tid];
        vs0[tid] = g_v[b0  * H_ + tid];
        vs1[tid] = g_v[bn_ * H_ + tid];
    }
    if (tid < 128) s_sh[tid] = 0.f;
    if (tid == 0) { ces[0] = g_ce[b0]; ces[1] = g_ce[bn_]; }

    float acc[2][8][4];
    #pragma unroll
    for (int mt = 0; mt < 2; mt++)
        #pragma unroll
        for (int nt = 0; nt < 8; nt++)
            #pragma unroll
            for (int c = 0; c < 4; c++) acc[mt][nt][c] = 0.f;

    const int ra = tid >> 2, ca = tid & 3;
    const float* Abase = edge + (size_t)row0 * DE_;

    float4 pa;
    float4 pb[2];
    {
        pa = *(const float4*)(Abase + (size_t)ra * DE_ + ca*4);
        #pragma unroll
        for (int t = 0; t < 2; t++) {
            int i4 = tid + t*512; int kr = i4 >> 6, c4 = i4 & 63;
            pb[t] = *(const float4*)(We1 + (size_t)kr * 256 + c4*4);
        }
    }
    const int S = DE_ / BK_;
    for (int s = 0; s < S; s++) {
        *(uint4*)&As[ra][ca*4] = make_uint4(f2tf32(pa.x), f2tf32(pa.y), f2tf32(pa.z), f2tf32(pa.w));
        #pragma unroll
        for (int t = 0; t < 2; t++) {
            int i4 = tid + t*512; int kr = i4 >> 6, c4 = i4 & 63;
            *(uint4*)&Bs[kr][c4*4] = make_uint4(f2tf32(pb[t].x), f2tf32(pb[t].y), f2tf32(pb[t].z), f2tf32(pb[t].w));
        }
        __syncthreads();
        if (s + 1 < S) {
            int k0 = (s + 1) * BK_;
            pa = *(const float4*)(Abase + (size_t)ra * DE_ + k0 + ca*4);
            #pragma unroll
            for (int t = 0; t < 2; t++) {
                int i4 = tid + t*512; int kr = i4 >> 6, c4 = i4 & 63;
                pb[t] = *(const float4*)(We1 + (size_t)(k0 + kr) * 256 + c4*4);
            }
        }
        #pragma unroll
        for (int kk = 0; kk < 2; kk++) {
            unsigned af[2][4], bf[8][2];
            #pragma unroll
            for (int mt = 0; mt < 2; mt++) {
                int r = warpM*32 + mt*16 + g;
                af[mt][0] = As[r    ][kk*8 + kq];
                af[mt][1] = As[r + 8][kk*8 + kq];
                af[mt][2] = As[r    ][kk*8 + kq + 4];
                af[mt][3] = As[r + 8][kk*8 + kq + 4];
            }
            #pragma unroll
            for (int nt = 0; nt < 8; nt++) {
                int n = warpN*64 + nt*8 + g;
                bf[nt][0] = Bs[kk*8 + kq    ][n];
                bf[nt][1] = Bs[kk*8 + kq + 4][n];
            }
            #pragma unroll
            for (int mt = 0; mt < 2; mt++)
                #pragma unroll
                for (int nt = 0; nt < 8; nt++) mma_tf32(acc[mt][nt], af[mt], bf[nt]);
        }
        __syncthreads();
    }
    #pragma unroll
    for (int mt = 0; mt < 2; mt++) {
        int rA = warpM*32 + mt*16 + g;
        int rB = rA + 8;
        const float* vA = (rA < split) ? vs0 : vs1;
        const float* vB = (rB < split) ? vs0 : vs1;
        float pA = 0.f, pB = 0.f;
        #pragma unroll
        for (int nt = 0; nt < 8; nt++) {
            int n = warpN*64 + nt*8 + kq*2;
            float b0v = bs[n], b1v = bs[n+1];
            pA += fmaxf(acc[mt][nt][0] + b0v, 0.f) * vA[n]
                + fmaxf(acc[mt][nt][1] + b1v, 0.f) * vA[n+1];
            pB += fmaxf(acc[mt][nt][2] + b0v, 0.f) * vB[n]
                + fmaxf(acc[mt][nt][3] + b1v, 0.f) * vB[n+1];
        }
        pA += __shfl_xor_sync(0xffffffffu, pA, 1);
        pA += __shfl_xor_sync(0xffffffffu, pA, 2);
        pB += __shfl_xor_sync(0xffffffffu, pB, 1);
        pB += __shfl_xor_sync(0xffffffffu, pB, 2);
        if (kq == 0) {
            atomicAdd(&s_sh[rA], pA);
            atomicAdd(&s_sh[rB], pB);
        }
    }
    __syncthreads();
    if (tid < 128) {
        float ce = (tid < split) ? ces[0] : ces[1];
        g_weit[row0 + tid] = sigmoidf_((s_sh[tid] + ce) * SCALE_);
    }
#else
    (void)edge; (void)We1; (void)be1;
#endif
}

// ------------------------- K3a: node MLP1 via tcgen05 (tc pass) -------------
// M=128/CTA (36 CTAs), K=512 (16 chunks of 32), N=256.
// Structural clone of the PROVEN edge_tc2: LDG->regs->(rna)STS, 2-buffer,
// register prefetch. Parities: in-loop waits consume completions #1..#7 per
// mbar; final wait = completion #8 -> parity 1.
#define NODE_SMEM_DYN (1024 + 2*49152)
__global__ __launch_bounds__(256, 1)
void node_tc_kernel(const float* __restrict__ node, const float* __restrict__ bn1) {
#if HAS_TC
    extern __shared__ char dsm[];
    __shared__ uint32_t sh_tmem;
    __shared__ uint64_t sh_mbar[2];
    __shared__ float bs[256];

    const int tid = threadIdx.x, warp = tid >> 5, lane = tid & 31;
    const int row0 = blockIdx.x * 128;

    uint32_t dbase = smem_u32(dsm);
    uint32_t aligned = (dbase + 1023u) & ~1023u;
    char* smbase = dsm + (aligned - dbase);

    if (warp == 0) { TC_ALLOC(smem_u32(&sh_tmem), 256); TC_RELINQ(); }
    if (tid == 0) {
        MBAR_INIT(smem_u32(&sh_mbar[0]), 1);
        MBAR_INIT(smem_u32(&sh_mbar[1]), 1);
    }
    bs[tid] = bn1[tid];
    __syncthreads();

    const uint32_t tmem = sh_tmem;
    uint32_t mb[2] = { smem_u32(&sh_mbar[0]), smem_u32(&sh_mbar[1]) };
    const float* Abase = node + (size_t)row0 * DF_;

    float4 pa[4], pb[8];
    const int rA = tid >> 3, cA = tid & 7;

    // prefetch chunk 0
    #pragma unroll
    for (int t = 0; t < 4; t++)
        pa[t] = *(const float4*)(Abase + (size_t)(rA + t*32) * DF_ + cA*4);
    #pragma unroll
    for (int t = 0; t < 8; t++)
        pb[t] = *(const float4*)(g_Wn1T + (size_t)(rA + t*32) * DF_ + cA*4);

    #pragma unroll 1
    for (int c = 0; c < 16; c++) {
        const int buf = c & 1;
        if (c >= 2) mbar_wait_parity(mb[buf], (uint32_t)((c - 2) >> 1) & 1u);
        {
            char* st = smbase + (size_t)buf * 49152u;
            #pragma unroll
            for (int t = 0; t < 4; t++) {
                int r = rA + t*32;                      // 0..127
                uint32_t byte = (uint32_t)(r*128 + cA*16);
                *(uint4*)(st + (byte ^ ((byte>>3)&0x70u))) =
                    make_uint4(f2tf32(pa[t].x), f2tf32(pa[t].y), f2tf32(pa[t].z), f2tf32(pa[t].w));
            }
            #pragma unroll
            for (int t = 0; t < 8; t++) {
                int n = rA + t*32;                      // 0..255
                uint32_t byte = (uint32_t)(n*128 + cA*16);
                *(uint4*)(st + 16384u + (byte ^ ((byte>>3)&0x70u))) =
                    make_uint4(f2tf32(pb[t].x), f2tf32(pb[t].y), f2tf32(pb[t].z), f2tf32(pb[t].w));
            }
        }
        if (c + 1 < 16) {
            int k0 = (c + 1) * 32;
            #pragma unroll
            for (int t = 0; t < 4; t++)
                pa[t] = *(const float4*)(Abase + (size_t)(rA + t*32) * DF_ + k0 + cA*4);
            #pragma unroll
            for (int t = 0; t < 8; t++)
                pb[t] = *(const float4*)(g_Wn1T + (size_t)(rA + t*32) * DF_ + k0 + cA*4);
        }
        FENCE_PROXY_ASYNC();
        __syncthreads();
        if (warp == 0) {
            if (elect_one_pred()) {
                uint32_t st = aligned + (uint32_t)buf * 49152u;
                uint64_t ad = make_desc(st);
                uint64_t bd = make_desc(st + 16384u);
                #pragma unroll
                for (int s = 0; s < 4; s++)
                    tc_mma_tf32_ss(tmem, ad + 2*s, bd + 2*s, EDGE_IDESC, (c > 0) || (s > 0));
                TC_COMMIT(mb[buf]);
            }
        }
    }
    mbar_wait_parity(mb[0], 1u);
    mbar_wait_parity(mb[1], 1u);
    TC_FENCE_AFTER();

    // epilogue: warp w -> rows (w&3)*32+lane, cols (w>>2)*128..+127
    {
        const int colbase = (warp >> 2) * 128;
        const int grow = row0 + (warp & 3) * 32 + lane;
        float* dst = g_hn + (size_t)grow * H_;
        #pragma unroll
        for (int it = 0; it < 4; it++) {
            uint32_t d[32];
            int cb = colbase + it*32;
            LDTM_X32(d, tmem + cb);
            TC_WAIT_LD();
            #pragma unroll
            for (int k = 0; k < 8; k++) {
                int n = cb + k*4;
                float4 o;
                o.x = fmaxf(__uint_as_float(d[k*4+0]) + bs[n+0], 0.f);
                o.y = fmaxf(__uint_as_float(d[k*4+1]) + bs[n+1], 0.f);
                o.z = fmaxf(__uint_as_float(d[k*4+2]) + bs[n+2], 0.f);
                o.w = fmaxf(__uint_as_float(d[k*4+3]) + bs[n+3], 0.f);
                *(float4*)(dst + n) = o;
            }
        }
    }
    __syncthreads();
    if (tid == 0) { MBAR_INVAL(mb[0]); MBAR_INVAL(mb[1]); }
    if (warp == 0) TC_DEALLOC(tmem, 256);
#else
    (void)node; (void)bn1;
#endif
}

// ------------------------- K3b: node MLP1 via mma.sync (base pass) ----------
__global__ __launch_bounds__(512, 1) void node_mma_kernel(
        const float* __restrict__ node, const float* __restrict__ Wn1,
        const float* __restrict__ bn1) {
#if !HAS_TC
    __shared__ unsigned As[128][20];
    __shared__ unsigned Bs[BK_][264];
    __shared__ float bs[256];

    const int tid  = threadIdx.x;
    const int warp = tid >> 5, lane = tid & 31;
    const int warpM = warp >> 2, warpN = warp & 3;
    const int g = lane >> 2, kq = lane & 3;
    const int row0 = blockIdx.x * 128;

    if (tid < 256) bs[tid] = bn1[tid];

    float acc[2][8][4];
    #pragma unroll
    for (int mt = 0; mt < 2; mt++)
        #pragma unroll
        for (int nt = 0; nt < 8; nt++)
            #pragma unroll
            for (int c = 0; c < 4; c++) acc[mt][nt][c] = 0.f;

    const int ra = tid >> 2, ca = tid & 3;
    const float* Abase = node + (size_t)row0 * DF_;

    float4 pa;
    float4 pb[2];
    {
        pa = *(const float4*)(Abase + (size_t)ra * DF_ + ca*4);
        #pragma unroll
        for (int t = 0; t < 2; t++) {
            int i4 = tid + t*512; int kr = i4 >> 6, c4 = i4 & 63;
            pb[t] = *(const float4*)(Wn1 + (size_t)kr * H_ + c4*4);
        }
    }
    const int S = DF_ / BK_;
    for (int s = 0; s < S; s++) {
        *(uint4*)&As[ra][ca*4] = make_uint4(f2tf32(pa.x), f2tf32(pa.y), f2tf32(pa.z), f2tf32(pa.w));
        #pragma unroll
        for (int t = 0; t < 2; t++) {
            int i4 = tid + t*512; int kr = i4 >> 6, c4 = i4 & 63;
            *(uint4*)&Bs[kr][c4*4] = make_uint4(f2tf32(pb[t].x), f2tf32(pb[t].y), f2tf32(pb[t].z), f2tf32(pb[t].w));
        }
        __syncthreads();
        if (s + 1 < S) {
            int k0 = (s + 1) * BK_;
            pa = *(const float4*)(Abase + (size_t)ra * DF_ + k0 + ca*4);
            #pragma unroll
            for (int t = 0; t < 2; t++) {
                int i4 = tid + t*512; int kr = i4 >> 6, c4 = i4 & 63;
                pb[t] = *(const float4*)(Wn1 + (size_t)(k0 + kr) * H_ + c4*4);
            }
        }
        #pragma unroll
        for (int kk = 0; kk < 2; kk++) {
            unsigned af[2][4], bf[8][2];
            #pragma unroll
            for (int mt = 0; mt < 2; mt++) {
                int r = warpM*32 + mt*16 + g;
                af[mt][0] = As[r    ][kk*8 + kq];
                af[mt][1] = As[r + 8][kk*8 + kq];
                af[mt][2] = As[r    ][kk*8 + kq + 4];
                af[mt][3] = As[r + 8][kk*8 + kq + 4];
            }
            #pragma unroll
            for (int nt = 0; nt < 8; nt++) {
                int n = warpN*64 + nt*8 + g;
                bf[nt][0] = Bs[kk*8 + kq    ][n];
                bf[nt][1] = Bs[kk*8 + kq + 4][n];
            }
            #pragma unroll
            for (int mt = 0; mt < 2; mt++)
                #pragma unroll
                for (int nt = 0; nt < 8; nt++) mma_tf32(acc[mt][nt], af[mt], bf[nt]);
        }
        __syncthreads();
    }
    #pragma unroll
    for (int mt = 0; mt < 2; mt++) {
        int rA = row0 + warpM*32 + mt*16 + g;
        int rB = rA + 8;
        #pragma unroll
        for (int nt = 0; nt < 8; nt++) {
            int n = warpN*64 + nt*8 + kq*2;
            float b0v = bs[n], b1v = bs[n+1];
            float2 v0 = make_float2(fmaxf(acc[mt][nt][0] + b0v, 0.f), fmaxf(acc[mt][nt][1] + b1v, 0.f));
            float2 v1 = make_float2(fmaxf(acc[mt][nt][2] + b0v, 0.f), fmaxf(acc[mt][nt][3] + b1v, 0.f));
            *(float2*)&g_hn[(size_t)rA * H_ + n] = v0;
            *(float2*)&g_hn[(size_t)rB * H_ + n] = v1;
        }
    }
#else
    (void)node; (void)Wn1; (void)bn1;
#endif
}

// ------------------------- K4: filter scores --------------------------------
__global__ void score_kernel() {
    int gw = (blockIdx.x * 256 + threadIdx.x) >> 5;
    int lane = threadIdx.x & 31;
    if (gw >= NODE_ROWS) return;
    int b = gw / N_;
    const float* h  = g_hn + (size_t)gw * H_;
    const float* u3 = g_u3 + b * H_;
    const float* u1 = g_u1 + b * H_;
    float d3 = 0.f, d1 = 0.f;
    #pragma unroll
    for (int t = 0; t < 8; t++) {
        int d = lane + t*32;
        float hv = h[d];
        d3 += hv * u3[d];
        d1 += hv * u1[d];
    }
    #pragma unroll
    for (int o = 16; o > 0; o >>= 1) {
        d3 += __shfl_xor_sync(0xffffffffu, d3, o);
        d1 += __shfl_xor_sync(0xffffffffu, d1, o);
    }
    if (lane == 0) {
        g_a1[gw]   = sigmoidf_((d3 + g_c3[b]) * SCALE_);
        g_sig1[gw] = sigmoidf_((d1 + g_c1[b]) * SCALE_);
    }
}

// ------------------------- K6: attention chain + pooled hidden --------------
__global__ void combine_kernel() {
    int b = blockIdx.x;
    int tid = threadIdx.x;
    __shared__ float a1s[N_];
    __shared__ float a3s[N_];
    __shared__ float sInv, sS;
    if (tid < N_) a1s[tid] = g_a1[b * N_ + tid];
    __syncthreads();
    if (tid < N_) {
        int j = tid;
        float acc = 0.f;
        const float* w = g_weit + (size_t)b * ROWS_PER_B;
        #pragma unroll
        for (int i = 0; i < N_; i++) acc += a1s[i] * w[i * N_ + j];
        acc = fminf(fmaxf(acc, 0.f), 1.f);
        a3s[j] = acc * g_sig1[b * N_ + j];
    }
    __syncthreads();
    if (tid == 0) {
        float s0 = 0.f;
        #pragma unroll
        for (int j = 0; j < N_; j++) s0 += a3s[j];
        float inv = 1.f / (s0 + 1e-8f);
        sInv = inv;
        sS = s0 * inv;
    }
    __syncthreads();
    {
        int h = tid;
        float acc = 0.f;
        #pragma unroll
        for (int j = 0; j < N_; j++)
            acc += a3s[j] * g_hn[((size_t)(b * N_ + j)) * H_ + h];
        g_ph[b * H_ + h] = acc * sInv;
    }
    if (tid == 0) g_S[b] = sS;
}

// ------------------------- K7: final chain, 32x32 tiled GEMM stages ---------
__global__ __launch_bounds__(256) void final_mm_kernel(
        int stage, const float* __restrict__ W, const float* __restrict__ bias,
        float* __restrict__ outp) {
    __shared__ float As[32][36];
    __shared__ float Ws[32][32];

    const float* A; float* C; int N, K, mode;
    if (stage == 0)      { A = g_ph;   C = g_gbuf; N = DV_; K = H_;  mode = 1; }
    else if (stage == 1) { A = g_gbuf; C = g_obuf; N = DV_; K = DV_; mode = 0; }
    else if (stage == 2) { A = g_obuf; C = g_h2;   N = H_;  K = DV_; mode = 0; }
    else                 { A = g_h2;   C = outp;   N = NC_; K = H_;  mode = 2; }

    const int tid = threadIdx.x;
    const int m0 = blockIdx.x * 32, n0 = blockIdx.y * 32;
    const int r = tid >> 3, cg = tid & 7;
    float acc[4] = {0.f, 0.f, 0.f, 0.f};

    const int lrow = tid >> 3, lk4 = (tid & 7) * 4;
    for (int k0 = 0; k0 < K; k0 += 32) {
        float4 av = *(const float4*)(A + (size_t)(m0 + lrow) * K + k0 + lk4);
        *(float4*)&As[lrow][lk4] = av;
        #pragma unroll
        for (int u = 0; u < 4; u++) {
            int n = n0 + lk4 + u;
            Ws[lrow][lk4 + u] = (n < N) ? W[(size_t)(k0 + lrow) * N + n] : 0.f;
        }
        __syncthreads();
        #pragma unroll
        for (int k = 0; k < 32; k++) {
            float a = As[r][k];
            float4 w = *(const float4*)&Ws[k][cg*4];
            acc[0] += a * w.x; acc[1] += a * w.y; acc[2] += a * w.z; acc[3] += a * w.w;
        }
        __syncthreads();
    }
    const int row = m0 + r;
    #pragma unroll
    for (int u = 0; u < 4; u++) {
        int n = n0 + cg*4 + u;
        if (n >= N) continue;
        float x = acc[u];
        if (mode == 0)      x = fmaxf(x + bias[n], 0.f);
        else if (mode == 1) x = (x + g_S[row] * bias[n]) * g_q[((size_t)(row*4 + 0))*DV_ + n];
        else                x = x + bias[n];
        C[(size_t)row * N + n] = x;
    }
}

// ------------------------- launch ------------------------------------------
extern "C" void kernel_launch(void* const* d_in, const int* in_sizes, int n_in,
                              void* d_out, int out_size) {
    const float* node     = (const float*)d_in[0];
    const float* edge     = (const float*)d_in[1];
    const float* Wn1      = (const float*)d_in[2];
    const float* bn1      = (const float*)d_in[3];
    const float* Wn2      = (const float*)d_in[4];
    const float* bn2      = (const float*)d_in[5];
    const float* We1      = (const float*)d_in[6];
    const float* be1      = (const float*)d_in[7];
    const float* We2      = (const float*)d_in[8];
    const float* be2      = (const float*)d_in[9];
    const float* Wq       = (const float*)d_in[10];
    const float* bq       = (const float*)d_in[11];
    const float* Wc1      = (const float*)d_in[12];
    const float* bc1      = (const float*)d_in[13];
    const float* Wc2      = (const float*)d_in[14];
    const float* bc2      = (const float*)d_in[15];
    const float* word_emb = (const float*)d_in[16];
    const int* prog_in    = (const int*)d_in[18];
    float* out            = (float*)d_out;

    static int smem_set = 0;
    if (!smem_set) {
        cudaFuncSetAttribute(edge_tc2_kernel,
                             cudaFuncAttributeMaxDynamicSharedMemorySize, EDGE_SMEM_DYN);
        cudaFuncSetAttribute(node_tc_kernel,
                             cudaFuncAttributeMaxDynamicSharedMemorySize, NODE_SMEM_DYN);
        smem_set = 1;
    }

    // index 0..2: edge dependencies
    transpose_We1_kernel<<<dim3(8, 8), dim3(32, 32)>>>(We1);
    gather_q_kernel<<<(B_*4*DV_)/256, 256>>>(word_emb, prog_in);
    proj2_kernel<<<dim3(8, 2, 3), 256>>>(Wn2, We2, bn2, be2);

    // index 3: edge GEMM (tc pass) -- placed here so ncu profiles it
    edge_tc2_kernel<<<EDGE_ROWS/256, 256, EDGE_SMEM_DYN>>>(edge, be1);
    edge_mma_kernel<<<EDGE_ROWS/128, 512>>>(edge, We1, be1);

    // node path
    transpose_Wn1_kernel<<<dim3(8, 16), dim3(32, 32)>>>(Wn1);
    node_tc_kernel<<<NODE_ROWS/128, 256, NODE_SMEM_DYN>>>(node, bn1);
    node_mma_kernel<<<NODE_ROWS/128, 512>>>(node, Wn1, bn1);

    score_kernel<<<NODE_ROWS/8, 256>>>();
    combine_kernel<<<B_, 256>>>();

    // final GEMV chain as tiled GEMMs (scratch selected in device code)
    final_mm_kernel<<<dim3(4, 16), 256>>>(0, Wn2, bn2, out);
    final_mm_kernel<<<dim3(4, 16), 256>>>(1, Wq,  bq,  out);
    final_mm_kernel<<<dim3(4, 8),  256>>>(2, Wc1, bc1, out);
    final_mm_kernel<<<dim3(4, 1),  256>>>(3, Wc2, bc2, out);
}

// round 15
// speedup vs baseline: 1.5721x; 1.3621x over previous
#include <cuda_runtime.h>
#include <math.h>
#include <stdint.h>

// Dims (CLEVR-scale, fixed)
#define B_   128
#define N_   36
#define DF_  512
#define DE_  256
#define DV_  512
#define H_   256
#define NC_  28
#define L_   5
#define ROWS_PER_B (N_*N_)          // 1296
#define NODE_ROWS  (B_*N_)          // 4608
#define EDGE_ROWS  (B_*ROWS_PER_B)  // 165888
#define SCALE_ 0.04419417382415922f // 1/sqrt(512)

// Feature gate: tcgen05 exists only in arch-specific (sm_103a / sm_100a) passes.
#if defined(__CUDA_ARCH_FEAT_SM103_ALL) || defined(__CUDA_ARCH_FEAT_SM100_ALL) || defined(__CUDA_ARCH_FEAT_SM101_ALL)
#define HAS_TC 1
#else
#define HAS_TC 0
#endif

// ------------------------- device scratch (no cudaMalloc allowed) -----------
// RULE (rounds 5-10 bug): these symbols are ONLY referenced inside device
// code. Never pass them as host-side kernel args.
__device__ float g_hn[NODE_ROWS * H_];
__device__ float g_q[B_ * 4 * DV_];
__device__ float g_u3[B_ * H_];
__device__ float g_u1[B_ * H_];
__device__ float g_v [B_ * H_];
__device__ float g_c3[B_];
__device__ float g_c1[B_];
__device__ float g_ce[B_];
__device__ float g_a1  [NODE_ROWS];
__device__ float g_sig1[NODE_ROWS];
__device__ float g_weit[EDGE_ROWS];
__device__ float g_ph[B_ * H_];
__device__ float g_S [B_];
__device__ float g_We1T[H_ * DE_];   // We1^T [n][k], rna tf32 (pre-rounded)
__device__ float g_Wn1T[H_ * DF_];   // Wn1^T [n][k], rna tf32 (pre-rounded)
__device__ float g_gbuf[B_ * DV_];
__device__ float g_obuf[B_ * DV_];
__device__ float g_h2  [B_ * H_];

__device__ __forceinline__ float sigmoidf_(float x) { return 1.0f / (1.0f + expf(-x)); }
__device__ __forceinline__ unsigned f2tf32(float x) {
    unsigned u; asm("cvt.rna.tf32.f32 %0, %1;" : "=r"(u) : "f"(x)); return u;
}
__device__ __forceinline__ void mma_tf32(float c[4], const unsigned a[4], const unsigned b[2]) {
    asm volatile("mma.sync.aligned.m16n8k8.row.col.f32.tf32.tf32.f32 "
        "{%0,%1,%2,%3}, {%4,%5,%6,%7}, {%8,%9}, {%0,%1,%2,%3};"
        : "+f"(c[0]), "+f"(c[1]), "+f"(c[2]), "+f"(c[3])
        : "r"(a[0]), "r"(a[1]), "r"(a[2]), "r"(a[3]), "r"(b[0]), "r"(b[1]));
}

// ------------------------- tcgen05 / async helpers --------------------------
__device__ __forceinline__ uint32_t smem_u32(const void* p) {
    uint32_t a;
    asm("{ .reg .u64 t; cvta.to.shared.u64 t, %1; cvt.u32.u64 %0, t; }" : "=r"(a) : "l"(p));
    return a;
}
__device__ __forceinline__ uint32_t elect_one_pred() {
    uint32_t pred;
    asm volatile("{\n\t.reg .pred p;\n\telect.sync _|p, 0xFFFFFFFF;\n\t"
                 "selp.b32 %0, 1, 0, p;\n\t}" : "=r"(pred));
    return pred;
}
__device__ __forceinline__ void cp16(uint32_t dst, const void* src) {
    asm volatile("cp.async.cg.shared.global [%0], [%1], 16;" :: "r"(dst), "l"(src) : "memory");
}
#define CP_COMMIT() asm volatile("cp.async.commit_group;" ::: "memory")
#define CP_WAIT2()  asm volatile("cp.async.wait_group 2;" ::: "memory")

static __device__ constexpr uint64_t SMEM_DESC_BASE_SW128 =
    (uint64_t(2)  << 61) | (uint64_t(1) << 46) | (uint64_t(64) << 32) | (uint64_t(1) << 16);
__device__ __forceinline__ uint64_t make_desc(uint32_t addr) {
    return SMEM_DESC_BASE_SW128 | ((uint64_t)(addr >> 4) & 0x3FFF);
}
// tf32 SS idesc: dtype=F32(1<<4), a/btype=TF32(2<<7,2<<10), N/8<<17, M/16<<24
#define EDGE_IDESC 0x8400910u

#if HAS_TC
__device__ __forceinline__ void tc_mma_tf32_ss(uint32_t d_tmem, uint64_t a_desc,
                                               uint64_t b_desc, uint32_t idesc, bool accum) {
    uint32_t en = accum ? 1u : 0u;
    asm volatile(
        "{\n\t.reg .pred p;\n\t"
        "setp.ne.u32 p, %5, 0;\n\t"
        "tcgen05.mma.cta_group::1.kind::tf32 [%0], %1, %2, %3, {%4, %4, %4, %4}, p;\n\t}"
        :: "r"(d_tmem), "l"(a_desc), "l"(b_desc), "r"(idesc), "r"(0u), "r"(en)
        : "memory");
}
#define TC_ALLOC(smem_addr, n) \
    asm volatile("tcgen05.alloc.cta_group::1.sync.aligned.shared::cta.b32 [%0], %1;" \
                 :: "r"((uint32_t)(smem_addr)), "r"((uint32_t)(n)) : "memory")
#define TC_DEALLOC(tmem, n) \
    asm volatile("tcgen05.dealloc.cta_group::1.sync.aligned.b32 %0, %1;" :: "r"(tmem), "r"((uint32_t)(n)))
#define TC_RELINQ() asm volatile("tcgen05.relinquish_alloc_permit.cta_group::1.sync.aligned;")
#define TC_COMMIT(mbar) \
    asm volatile("tcgen05.commit.cta_group::1.mbarrier::arrive::one.shared::cluster.b64 [%0];" \
                 :: "r"((uint32_t)(mbar)) : "memory")
#define TC_FENCE_AFTER()  asm volatile("tcgen05.fence::after_thread_sync;" ::: "memory")
#define TC_WAIT_LD()      asm volatile("tcgen05.wait::ld.sync.aligned;" ::: "memory")
#define MBAR_INIT(addr, cnt) \
    asm volatile("mbarrier.init.shared.b64 [%0], %1;" :: "r"((uint32_t)(addr)), "r"((uint32_t)(cnt)) : "memory")
#define MBAR_INVAL(addr) \
    asm volatile("mbarrier.inval.shared.b64 [%0];" :: "r"((uint32_t)(addr)) : "memory")
#define FENCE_PROXY_ASYNC() asm volatile("fence.proxy.async.shared::cta;" ::: "memory")
__device__ __forceinline__ void mbar_wait_parity(uint32_t addr, uint32_t parity) {
    asm volatile(
        "{\n\t.reg .pred P1;\n\t"
        "WAIT_%=:\n\t"
        "mbarrier.try_wait.parity.acquire.cta.shared::cta.b64 P1, [%0], %1, 0x989680;\n\t"
        "@P1 bra.uni DONE_%=;\n\t"
        "bra.uni WAIT_%=;\n\t"
        "DONE_%=:\n\t}"
        :: "r"(addr), "r"(parity) : "memory");
}
#define LDTM_X32(r, addr) \
    asm volatile( \
        "tcgen05.ld.sync.aligned.32x32b.x32.b32 " \
        "{%0, %1, %2, %3, %4, %5, %6, %7, " \
        " %8, %9, %10, %11, %12, %13, %14, %15, " \
        " %16, %17, %18, %19, %20, %21, %22, %23, " \
        " %24, %25, %26, %27, %28, %29, %30, %31}, [%32];" \
        : "=r"((r)[0]),  "=r"((r)[1]),  "=r"((r)[2]),  "=r"((r)[3]), \
          "=r"((r)[4]),  "=r"((r)[5]),  "=r"((r)[6]),  "=r"((r)[7]), \
          "=r"((r)[8]),  "=r"((r)[9]),  "=r"((r)[10]), "=r"((r)[11]), \
          "=r"((r)[12]), "=r"((r)[13]), "=r"((r)[14]), "=r"((r)[15]), \
          "=r"((r)[16]), "=r"((r)[17]), "=r"((r)[18]), "=r"((r)[19]), \
          "=r"((r)[20]), "=r"((r)[21]), "=r"((r)[22]), "=r"((r)[23]), \
          "=r"((r)[24]), "=r"((r)[25]), "=r"((r)[26]), "=r"((r)[27]), \
          "=r"((r)[28]), "=r"((r)[29]), "=r"((r)[30]), "=r"((r)[31]) \
        : "r"(addr))
#endif // HAS_TC

// ------------------------- K0: prep (both transposes, rna-rounded) ----------
// blocks 0..63: We1^T (n 8 x k 8); blocks 64..191: Wn1^T (n 8 x k 16)
__global__ void prep_kernel(const float* __restrict__ We1, const float* __restrict__ Wn1) {
    __shared__ float t[32][33];
    int bz = blockIdx.x;
    if (bz < 64) {
        int bx = (bz & 7) * 32, by = (bz >> 3) * 32;
        t[threadIdx.y][threadIdx.x] = We1[(size_t)(by + threadIdx.y) * H_ + bx + threadIdx.x];
        __syncthreads();
        g_We1T[(size_t)(bx + threadIdx.y) * DE_ + by + threadIdx.x] =
            __uint_as_float(f2tf32(t[threadIdx.x][threadIdx.y]));
    } else {
        int i = bz - 64;
        int bx = (i & 7) * 32, by = (i >> 3) * 32;
        t[threadIdx.y][threadIdx.x] = Wn1[(size_t)(by + threadIdx.y) * H_ + bx + threadIdx.x];
        __syncthreads();
        g_Wn1T[(size_t)(bx + threadIdx.y) * DF_ + by + threadIdx.x] =
            __uint_as_float(f2tf32(t[threadIdx.x][threadIdx.y]));
    }
}

// ------------------------- K1: gather q -------------------------------------
__global__ void gather_q_kernel(const float* __restrict__ word_emb,
                                const int* __restrict__ prog_in) {
    int idx = blockIdx.x * 256 + threadIdx.x;
    int d = idx & (DV_ - 1);
    int l = (idx >> 9) & 3;
    int b = idx >> 11;
    int w = prog_in[b * L_ + l];
    g_q[idx] = word_emb[(size_t)w * DV_ + d];
}

// ------------------------- K2: proj as tiled GEMM + fused scalar dots -------
// U[m][h] = sum_k Q[m][k] * W[h][k]; m rows: 0-127 -> u3(l=3, Wn2),
// 128-255 -> u1(l=1, Wn2), 256-383 -> v(l=2, We2). grid (12, 8), block 256.
__global__ __launch_bounds__(256) void proj_mm_kernel(
        const float* __restrict__ Wn2, const float* __restrict__ We2,
        const float* __restrict__ bn2, const float* __restrict__ be2) {
    __shared__ float As[32][36];
    __shared__ float Ws[32][36];      // stride 36 floats = 144 B: float4-aligned rows
    const int tid = threadIdx.x;
    const int m0 = blockIdx.x * 32, n0 = blockIdx.y * 32;
    const int r = tid >> 3, cg = tid & 7;
    const int lrow = tid >> 3, lk4 = (tid & 7) * 4;
    const int region = m0 >> 7;                       // 0,1 -> Wn2 ; 2 -> We2
    const float* W    = (region < 2) ? Wn2 : We2;
    const float* bias = (region < 2) ? bn2 : be2;
    const int lsel = (region == 0) ? 3 : (region == 1) ? 1 : 2;

    float acc[4] = {0.f, 0.f, 0.f, 0.f};
    float sacc = 0.f;

    for (int k0 = 0; k0 < DV_; k0 += 32) {
        int m = m0 + lrow, b = m & 127;
        float4 av = *(const float4*)(g_q + ((size_t)(b*4 + lsel)) * DV_ + k0 + lk4);
        *(float4*)&As[lrow][lk4] = av;
        float4 wv = *(const float4*)(W + (size_t)(n0 + lrow) * DV_ + k0 + lk4);
        *(float4*)&Ws[lrow][lk4] = wv;
        if (n0 == 0) {
            float4 bv = *(const float4*)(bias + k0 + lk4);
            sacc += av.x*bv.x + av.y*bv.y + av.z*bv.z + av.w*bv.w;
        }
        __syncthreads();
        #pragma unroll
        for (int k = 0; k < 32; k++) {
            float a = As[r][k];
            acc[0] += a * Ws[cg*4+0][k];
            acc[1] += a * Ws[cg*4+1][k];
            acc[2] += a * Ws[cg*4+2][k];
            acc[3] += a * Ws[cg*4+3][k];
        }
        __syncthreads();
    }
    {
        int m = m0 + r, b = m & 127;
        float* U = (region == 0) ? g_u3 : (region == 1) ? g_u1 : g_v;
        #pragma unroll
        for (int u = 0; u < 4; u++) U[b * H_ + n0 + cg*4 + u] = acc[u];
    }
    if (n0 == 0) {
        sacc += __shfl_xor_sync(0xffffffffu, sacc, 1);
        sacc += __shfl_xor_sync(0xffffffffu, sacc, 2);
        sacc += __shfl_xor_sync(0xffffffffu, sacc, 4);
        if ((tid & 7) == 0) {
            float* cd = (region == 0) ? g_c3 : (region == 1) ? g_c1 : g_ce;
            cd[(m0 + lrow) & 127] = sacc;
        }
    }
}

// ------------------------- K3: edge GEMM, tcgen05 + cp.async 3-stage --------
// M=256/CTA (two 128-row D tiles sharing each B chunk), N=256, K=256
// (8 chunks of 32). A raw fp32 (tf32 HW truncation), B pre-rounded rna.
#define EDGE_SMEM_DYN (1024 + 3*65536)
__global__ __launch_bounds__(256, 1)
void edge_tc2_kernel(const float* __restrict__ edge, const float* __restrict__ be1) {
#if HAS_TC
    extern __shared__ char dsm[];
    __shared__ uint32_t sh_tmem;
    __shared__ uint64_t sh_mbar[3];
    __shared__ float bs[256], vs0[256], vs1[256];
    __shared__ float ces[2];

    const int tid = threadIdx.x, warp = tid >> 5, lane = tid & 31;
    const int row0 = blockIdx.x * 256;

    const int b0 = row0 / ROWS_PER_B;
    const int bn_ = (b0 + 1 < B_) ? b0 + 1 : b0;
    const int split = (b0 + 1) * ROWS_PER_B - row0;

    uint32_t dbase = smem_u32(dsm);
    uint32_t aligned = (dbase + 1023u) & ~1023u;

    if (warp == 0) { TC_ALLOC(smem_u32(&sh_tmem), 512); TC_RELINQ(); }
    if (tid == 0) {
        MBAR_INIT(smem_u32(&sh_mbar[0]), 1);
        MBAR_INIT(smem_u32(&sh_mbar[1]), 1);
        MBAR_INIT(smem_u32(&sh_mbar[2]), 1);
        ces[0] = g_ce[b0]; ces[1] = g_ce[bn_];
    }
    bs[tid]  = be1[tid];
    vs0[tid] = g_v[b0  * H_ + tid];
    vs1[tid] = g_v[bn_ * H_ + tid];
    __syncthreads();

    const uint32_t tmem = sh_tmem;
    uint32_t mb[3] = { smem_u32(&sh_mbar[0]), smem_u32(&sh_mbar[1]), smem_u32(&sh_mbar[2]) };
    const float* Abase = edge + (size_t)row0 * DE_;

    const int rA = tid >> 3, cA = tid & 7;

    auto load_chunk = [&](int j, int buf) {
        uint32_t st = aligned + (uint32_t)buf * 65536u;
        int k0 = j * 32;
        #pragma unroll
        for (int t = 0; t < 8; t++) {
            int r = rA + t*32;                           // 0..255
            uint32_t byte = (uint32_t)((r & 127)*128 + cA*16);
            uint32_t off = ((uint32_t)(r >> 7) << 14) + (byte ^ ((byte>>3)&0x70u));
            cp16(st + off, Abase + (size_t)r*DE_ + k0 + cA*4);
        }
        #pragma unroll
        for (int t = 0; t < 8; t++) {
            int n = rA + t*32;
            uint32_t byte = (uint32_t)(n*128 + cA*16);
            cp16(st + 32768u + (byte ^ ((byte>>3)&0x70u)), g_We1T + (size_t)n*DE_ + k0 + cA*4);
        }
        CP_COMMIT();
    };

    load_chunk(0, 0); load_chunk(1, 1); load_chunk(2, 2);

    #pragma unroll 1
    for (int c = 0; c < 8; c++) {
        const int buf = c % 3;
        CP_WAIT2();              // chunk c's group complete (exactly 2 newer pending)
        FENCE_PROXY_ASYNC();
        __syncthreads();
        if (warp == 0) {
            if (elect_one_pred()) {
                uint32_t st = aligned + (uint32_t)buf * 65536u;
                uint64_t ad0 = make_desc(st);
                uint64_t ad1 = make_desc(st + 16384u);
                uint64_t bd  = make_desc(st + 32768u);
                #pragma unroll
                for (int s = 0; s < 4; s++) {
                    bool acc = (c > 0) || (s > 0);
                    tc_mma_tf32_ss(tmem,        ad0 + 2*s, bd + 2*s, EDGE_IDESC, acc);
                    tc_mma_tf32_ss(tmem + 256u, ad1 + 2*s, bd + 2*s, EDGE_IDESC, acc);
                }
                TC_COMMIT(mb[buf]);
            }
        }
        if (c + 3 < 8) {
            mbar_wait_parity(mb[buf], (uint32_t)(c / 3) & 1u);   // MMA(c) done reading buf
            load_chunk(c + 3, buf);
        } else {
            CP_COMMIT();        // empty group keeps wait_group 2 aligned
        }
    }
    // completions: mb0 chunks {0,3,6}=3, mb1 {1,4,7}=3, mb2 {2,5}=2.
    // in-loop consumed mb0 #1,#2; mb1 #1,#2; mb2 #1.
    mbar_wait_parity(mb[0], 0u);   // #3 -> parity (3-1)&1 = 0
    mbar_wait_parity(mb[1], 0u);   // #3
    mbar_wait_parity(mb[2], 1u);   // #2 -> parity 1
    TC_FENCE_AFTER();

    // epilogue: warp w -> D tile (w>>2), rows (w&3)*32+lane
    {
        const int half = warp >> 2;
        const int rlocal = half*128 + (warp & 3)*32 + lane;
        const float* vrow = (rlocal < split) ? vs0 : vs1;
        const uint32_t tb = tmem + (uint32_t)(half ? 256 : 0);
        float s = 0.f;
        #pragma unroll
        for (int it = 0; it < 8; it++) {
            uint32_t d[32];
            LDTM_X32(d, tb + it*32);
            TC_WAIT_LD();
            #pragma unroll
            for (int cc = 0; cc < 32; cc++) {
                int n = it*32 + cc;
                float h = fmaxf(__uint_as_float(d[cc]) + bs[n], 0.f);
                s += h * vrow[n];
            }
        }
        float ce = (rlocal < split) ? ces[0] : ces[1];
        g_weit[row0 + rlocal] = sigmoidf_((s + ce) * SCALE_);
    }
    __syncthreads();
    if (tid == 0) { MBAR_INVAL(mb[0]); MBAR_INVAL(mb[1]); MBAR_INVAL(mb[2]); }
    if (warp == 0) TC_DEALLOC(tmem, 512);
#else
    (void)edge; (void)be1;
#endif
}

// ------------------------- K3b: edge GEMM via mma.sync (base-arch devices) --
#define BK_ 16
__global__ __launch_bounds__(512, 1) void edge_mma_kernel(
        const float* __restrict__ edge, const float* __restrict__ We1,
        const float* __restrict__ be1) {
#if !HAS_TC
    __shared__ unsigned As[128][20];
    __shared__ unsigned Bs[BK_][264];
    __shared__ float s_sh[128];
    __shared__ float bs[256], vs0[256], vs1[256];
    __shared__ float ces[2];

    const int tid  = threadIdx.x;
    const int warp = tid >> 5, lane = tid & 31;
    const int warpM = warp >> 2, warpN = warp & 3;
    const int g = lane >> 2, kq = lane & 3;
    const int row0 = blockIdx.x * 128;

    const int b0 = row0 / ROWS_PER_B;
    const int bn_ = (b0 + 1 < B_) ? b0 + 1 : b0;
    const int split = (b0 + 1) * ROWS_PER_B - row0;

    if (tid < 256) {
        bs[tid]  = be1[tid];
        vs0[tid] = g_v[b0  * H_ + tid];
        vs1[tid] = g_v[bn_ * H_ + tid];
    }
    if (tid < 128) s_sh[tid] = 0.f;
    if (tid == 0) { ces[0] = g_ce[b0]; ces[1] = g_ce[bn_]; }

    float acc[2][8][4];
    #pragma unroll
    for (int mt = 0; mt < 2; mt++)
        #pragma unroll
        for (int nt = 0; nt < 8; nt++)
            #pragma unroll
            for (int c = 0; c < 4; c++) acc[mt][nt][c] = 0.f;

    const int ra = tid >> 2, ca = tid & 3;
    const float* Abase = edge + (size_t)row0 * DE_;

    float4 pa;
    float4 pb[2];
    {
        pa = *(const float4*)(Abase + (size_t)ra * DE_ + ca*4);
        #pragma unroll
        for (int t = 0; t < 2; t++) {
            int i4 = tid + t*512; int kr = i4 >> 6, c4 = i4 & 63;
            pb[t] = *(const float4*)(We1 + (size_t)kr * 256 + c4*4);
        }
    }
    const int S = DE_ / BK_;
    for (int s = 0; s < S; s++) {
        *(uint4*)&As[ra][ca*4] = make_uint4(f2tf32(pa.x), f2tf32(pa.y), f2tf32(pa.z), f2tf32(pa.w));
        #pragma unroll
        for (int t = 0; t < 2; t++) {
            int i4 = tid + t*512; int kr = i4 >> 6, c4 = i4 & 63;
            *(uint4*)&Bs[kr][c4*4] = make_uint4(f2tf32(pb[t].x), f2tf32(pb[t].y), f2tf32(pb[t].z), f2tf32(pb[t].w));
        }
        __syncthreads();
        if (s + 1 < S) {
            int k0 = (s + 1) * BK_;
            pa = *(const float4*)(Abase + (size_t)ra * DE_ + k0 + ca*4);
            #pragma unroll
            for (int t = 0; t < 2; t++) {
                int i4 = tid + t*512; int kr = i4 >> 6, c4 = i4 & 63;
                pb[t] = *(const float4*)(We1 + (size_t)(k0 + kr) * 256 + c4*4);
            }
        }
        #pragma unroll
        for (int kk = 0; kk < 2; kk++) {
            unsigned af[2][4], bf[8][2];
            #pragma unroll
            for (int mt = 0; mt < 2; mt++) {
                int r = warpM*32 + mt*16 + g;
                af[mt][0] = As[r    ][kk*8 + kq];
                af[mt][1] = As[r + 8][kk*8 + kq];
                af[mt][2] = As[r    ][kk*8 + kq + 4];
                af[mt][3] = As[r + 8][kk*8 + kq + 4];
            }
            #pragma unroll
            for (int nt = 0; nt < 8; nt++) {
                int n = warpN*64 + nt*8 + g;
                bf[nt][0] = Bs[kk*8 + kq    ][n];
                bf[nt][1] = Bs[kk*8 + kq + 4][n];
            }
            #pragma unroll
            for (int mt = 0; mt < 2; mt++)
                #pragma unroll
                for (int nt = 0; nt < 8; nt++) mma_tf32(acc[mt][nt], af[mt], bf[nt]);
        }
        __syncthreads();
    }
    #pragma unroll
    for (int mt = 0; mt < 2; mt++) {
        int rA = warpM*32 + mt*16 + g;
        int rB = rA + 8;
        const float* vA = (rA < split) ? vs0 : vs1;
        const float* vB = (rB < split) ? vs0 : vs1;
        float pA = 0.f, pB = 0.f;
        #pragma unroll
        for (int nt = 0; nt < 8; nt++) {
            int n = warpN*64 + nt*8 + kq*2;
            float b0v = bs[n], b1v = bs[n+1];
            pA += fmaxf(acc[mt][nt][0] + b0v, 0.f) * vA[n]
                + fmaxf(acc[mt][nt][1] + b1v, 0.f) * vA[n+1];
            pB += fmaxf(acc[mt][nt][2] + b0v, 0.f) * vB[n]
                + fmaxf(acc[mt][nt][3] + b1v, 0.f) * vB[n+1];
        }
        pA += __shfl_xor_sync(0xffffffffu, pA, 1);
        pA += __shfl_xor_sync(0xffffffffu, pA, 2);
        pB += __shfl_xor_sync(0xffffffffu, pB, 1);
        pB += __shfl_xor_sync(0xffffffffu, pB, 2);
        if (kq == 0) {
            atomicAdd(&s_sh[rA], pA);
            atomicAdd(&s_sh[rB], pB);
        }
    }
    __syncthreads();
    if (tid < 128) {
        float ce = (tid < split) ? ces[0] : ces[1];
        g_weit[row0 + tid] = sigmoidf_((s_sh[tid] + ce) * SCALE_);
    }
#else
    (void)edge; (void)We1; (void)be1;
#endif
}

// ------------------------- K4a: node MLP1 via tcgen05 -----------------------
// M=128/CTA (36 CTAs), K=512 (16 chunks of 32), N=256. LDG->regs->(rna)STS,
// 2-buffer, register prefetch (proven).
#define NODE_SMEM_DYN (1024 + 2*49152)
__global__ __launch_bounds__(256, 1)
void node_tc_kernel(const float* __restrict__ node, const float* __restrict__ bn1) {
#if HAS_TC
    extern __shared__ char dsm[];
    __shared__ uint32_t sh_tmem;
    __shared__ uint64_t sh_mbar[2];
    __shared__ float bs[256];

    const int tid = threadIdx.x, warp = tid >> 5, lane = tid & 31;
    const int row0 = blockIdx.x * 128;

    uint32_t dbase = smem_u32(dsm);
    uint32_t aligned = (dbase + 1023u) & ~1023u;
    char* smbase = dsm + (aligned - dbase);

    if (warp == 0) { TC_ALLOC(smem_u32(&sh_tmem), 256); TC_RELINQ(); }
    if (tid == 0) {
        MBAR_INIT(smem_u32(&sh_mbar[0]), 1);
        MBAR_INIT(smem_u32(&sh_mbar[1]), 1);
    }
    bs[tid] = bn1[tid];
    __syncthreads();

    const uint32_t tmem = sh_tmem;
    uint32_t mb[2] = { smem_u32(&sh_mbar[0]), smem_u32(&sh_mbar[1]) };
    const float* Abase = node + (size_t)row0 * DF_;

    float4 pa[4], pb[8];
    const int rA = tid >> 3, cA = tid & 7;

    #pragma unroll
    for (int t = 0; t < 4; t++)
        pa[t] = *(const float4*)(Abase + (size_t)(rA + t*32) * DF_ + cA*4);
    #pragma unroll
    for (int t = 0; t < 8; t++)
        pb[t] = *(const float4*)(g_Wn1T + (size_t)(rA + t*32) * DF_ + cA*4);

    #pragma unroll 1
    for (int c = 0; c < 16; c++) {
        const int buf = c & 1;
        if (c >= 2) mbar_wait_parity(mb[buf], (uint32_t)((c - 2) >> 1) & 1u);
        {
            char* st = smbase + (size_t)buf * 49152u;
            #pragma unroll
            for (int t = 0; t < 4; t++) {
                int r = rA + t*32;
                uint32_t byte = (uint32_t)(r*128 + cA*16);
                *(uint4*)(st + (byte ^ ((byte>>3)&0x70u))) =
                    make_uint4(f2tf32(pa[t].x), f2tf32(pa[t].y), f2tf32(pa[t].z), f2tf32(pa[t].w));
            }
            #pragma unroll
            for (int t = 0; t < 8; t++) {
                int n = rA + t*32;
                uint32_t byte = (uint32_t)(n*128 + cA*16);
                *(uint4*)(st + 16384u + (byte ^ ((byte>>3)&0x70u))) =
                    make_uint4(__float_as_uint(pb[t].x), __float_as_uint(pb[t].y),
                               __float_as_uint(pb[t].z), __float_as_uint(pb[t].w));
            }
        }
        if (c + 1 < 16) {
            int k0 = (c + 1) * 32;
            #pragma unroll
            for (int t = 0; t < 4; t++)
                pa[t] = *(const float4*)(Abase + (size_t)(rA + t*32) * DF_ + k0 + cA*4);
            #pragma unroll
            for (int t = 0; t < 8; t++)
                pb[t] = *(const float4*)(g_Wn1T + (size_t)(rA + t*32) * DF_ + k0 + cA*4);
        }
        FENCE_PROXY_ASYNC();
        __syncthreads();
        if (warp == 0) {
            if (elect_one_pred()) {
                uint32_t st = aligned + (uint32_t)buf * 49152u;
                uint64_t ad = make_desc(st);
                uint64_t bd = make_desc(st + 16384u);
                #pragma unroll
                for (int s = 0; s < 4; s++)
                    tc_mma_tf32_ss(tmem, ad + 2*s, bd + 2*s, EDGE_IDESC, (c > 0) || (s > 0));
                TC_COMMIT(mb[buf]);
            }
        }
    }
    mbar_wait_parity(mb[0], 1u);
    mbar_wait_parity(mb[1], 1u);
    TC_FENCE_AFTER();

    {
        const int colbase = (warp >> 2) * 128;
        const int grow = row0 + (warp & 3) * 32 + lane;
        float* dst = g_hn + (size_t)grow * H_;
        #pragma unroll
        for (int it = 0; it < 4; it++) {
            uint32_t d[32];
            int cb = colbase + it*32;
            LDTM_X32(d, tmem + cb);
            TC_WAIT_LD();
            #pragma unroll
            for (int k = 0; k < 8; k++) {
                int n = cb + k*4;
                float4 o;
                o.x = fmaxf(__uint_as_float(d[k*4+0]) + bs[n+0], 0.f);
                o.y = fmaxf(__uint_as_float(d[k*4+1]) + bs[n+1], 0.f);
                o.z = fmaxf(__uint_as_float(d[k*4+2]) + bs[n+2], 0.f);
                o.w = fmaxf(__uint_as_float(d[k*4+3]) + bs[n+3], 0.f);
                *(float4*)(dst + n) = o;
            }
        }
    }
    __syncthreads();
    if (tid == 0) { MBAR_INVAL(mb[0]); MBAR_INVAL(mb[1]); }
    if (warp == 0) TC_DEALLOC(tmem, 256);
#else
    (void)node; (void)bn1;
#endif
}

// ------------------------- K4b: node MLP1 via mma.sync (base-arch devices) --
__global__ __launch_bounds__(512, 1) void node_mma_kernel(
        const float* __restrict__ node, const float* __restrict__ Wn1,
        const float* __restrict__ bn1) {
#if !HAS_TC
    __shared__ unsigned As[128][20];
    __shared__ unsigned Bs[BK_][264];
    __shared__ float bs[256];

    const int tid  = threadIdx.x;
    const int warp = tid >> 5, lane = tid & 31;
    const int warpM = warp >> 2, warpN = warp & 3;
    const int g = lane >> 2, kq = lane & 3;
    const int row0 = blockIdx.x * 128;

    if (tid < 256) bs[tid] = bn1[tid];

    float acc[2][8][4];
    #pragma unroll
    for (int mt = 0; mt < 2; mt++)
        #pragma unroll
        for (int nt = 0; nt < 8; nt++)
            #pragma unroll
            for (int c = 0; c < 4; c++) acc[mt][nt][c] = 0.f;

    const int ra = tid >> 2, ca = tid & 3;
    const float* Abase = node + (size_t)row0 * DF_;

    float4 pa;
    float4 pb[2];
    {
        pa = *(const float4*)(Abase + (size_t)ra * DF_ + ca*4);
        #pragma unroll
        for (int t = 0; t < 2; t++) {
            int i4 = tid + t*512; int kr = i4 >> 6, c4 = i4 & 63;
            pb[t] = *(const float4*)(Wn1 + (size_t)kr * H_ + c4*4);
        }
    }
    const int S = DF_ / BK_;
    for (int s = 0; s < S; s++) {
        *(uint4*)&As[ra][ca*4] = make_uint4(f2tf32(pa.x), f2tf32(pa.y), f2tf32(pa.z), f2tf32(pa.w));
        #pragma unroll
        for (int t = 0; t < 2; t++) {
            int i4 = tid + t*512; int kr = i4 >> 6, c4 = i4 & 63;
            *(uint4*)&Bs[kr][c4*4] = make_uint4(f2tf32(pb[t].x), f2tf32(pb[t].y), f2tf32(pb[t].z), f2tf32(pb[t].w));
        }
        __syncthreads();
        if (s + 1 < S) {
            int k0 = (s + 1) * BK_;
            pa = *(const float4*)(Abase + (size_t)ra * DF_ + k0 + ca*4);
            #pragma unroll
            for (int t = 0; t < 2; t++) {
                int i4 = tid + t*512; int kr = i4 >> 6, c4 = i4 & 63;
                pb[t] = *(const float4*)(Wn1 + (size_t)(k0 + kr) * H_ + c4*4);
            }
        }
        #pragma unroll
        for (int kk = 0; kk < 2; kk++) {
            unsigned af[2][4], bf[8][2];
            #pragma unroll
            for (int mt = 0; mt < 2; mt++) {
                int r = warpM*32 + mt*16 + g;
                af[mt][0] = As[r    ][kk*8 + kq];
                af[mt][1] = As[r + 8][kk*8 + kq];
                af[mt][2] = As[r    ][kk*8 + kq + 4];
                af[mt][3] = As[r + 8][kk*8 + kq + 4];
            }
            #pragma unroll
            for (int nt = 0; nt < 8; nt++) {
                int n = warpN*64 + nt*8 + g;
                bf[nt][0] = Bs[kk*8 + kq    ][n];
                bf[nt][1] = Bs[kk*8 + kq + 4][n];
            }
            #pragma unroll
            for (int mt = 0; mt < 2; mt++)
                #pragma unroll
                for (int nt = 0; nt < 8; nt++) mma_tf32(acc[mt][nt], af[mt], bf[nt]);
        }
        __syncthreads();
    }
    #pragma unroll
    for (int mt = 0; mt < 2; mt++) {
        int rA = row0 + warpM*32 + mt*16 + g;
        int rB = rA + 8;
        #pragma unroll
        for (int nt = 0; nt < 8; nt++) {
            int n = warpN*64 + nt*8 + kq*2;
            float b0v = bs[n], b1v = bs[n+1];
            float2 v0 = make_float2(fmaxf(acc[mt][nt][0] + b0v, 0.f), fmaxf(acc[mt][nt][1] + b1v, 0.f));
            float2 v1 = make_float2(fmaxf(acc[mt][nt][2] + b0v, 0.f), fmaxf(acc[mt][nt][3] + b1v, 0.f));
            *(float2*)&g_hn[(size_t)rA * H_ + n] = v0;
            *(float2*)&g_hn[(size_t)rB * H_ + n] = v1;
        }
    }
#else
    (void)node; (void)Wn1; (void)bn1;
#endif
}

// ------------------------- K5: filter scores --------------------------------
__global__ void score_kernel() {
    int gw = (blockIdx.x * 256 + threadIdx.x) >> 5;
    int lane = threadIdx.x & 31;
    if (gw >= NODE_ROWS) return;
    int b = gw / N_;
    const float* h  = g_hn + (size_t)gw * H_;
    const float* u3 = g_u3 + b * H_;
    const float* u1 = g_u1 + b * H_;
    float d3 = 0.f, d1 = 0.f;
    #pragma unroll
    for (int t = 0; t < 8; t++) {
        int d = lane + t*32;
        float hv = h[d];
        d3 += hv * u3[d];
        d1 += hv * u1[d];
    }
    #pragma unroll
    for (int o = 16; o > 0; o >>= 1) {
        d3 += __shfl_xor_sync(0xffffffffu, d3, o);
        d1 += __shfl_xor_sync(0xffffffffu, d1, o);
    }
    if (lane == 0) {
        g_a1[gw]   = sigmoidf_((d3 + g_c3[b]) * SCALE_);
        g_sig1[gw] = sigmoidf_((d1 + g_c1[b]) * SCALE_);
    }
}

// ------------------------- K6: attention chain + pooled hidden --------------
__global__ void combine_kernel() {
    int b = blockIdx.x;
    int tid = threadIdx.x;
    __shared__ float a1s[N_];
    __shared__ float a3s[N_];
    __shared__ float sInv, sS;
    if (tid < N_) a1s[tid] = g_a1[b * N_ + tid];
    __syncthreads();
    if (tid < N_) {
        int j = tid;
        float acc = 0.f;
        const float* w = g_weit + (size_t)b * ROWS_PER_B;
        #pragma unroll
        for (int i = 0; i < N_; i++) acc += a1s[i] * w[i * N_ + j];
        acc = fminf(fmaxf(acc, 0.f), 1.f);
        a3s[j] = acc * g_sig1[b * N_ + j];
    }
    __syncthreads();
    if (tid == 0) {
        float s0 = 0.f;
        #pragma unroll
        for (int j = 0; j < N_; j++) s0 += a3s[j];
        float inv = 1.f / (s0 + 1e-8f);
        sInv = inv;
        sS = s0 * inv;
    }
    __syncthreads();
    {
        int h = tid;
        float acc = 0.f;
        #pragma unroll
        for (int j = 0; j < N_; j++)
            acc += a3s[j] * g_hn[((size_t)(b * N_ + j)) * H_ + h];
        g_ph[b * H_ + h] = acc * sInv;
    }
    if (tid == 0) g_S[b] = sS;
}

// ------------------------- K7: final chain, 32x32 tiled GEMM stages ---------
__global__ __launch_bounds__(256) void final_mm_kernel(
        int stage, const float* __restrict__ W, const float* __restrict__ bias,
        float* __restrict__ outp) {
    __shared__ float As[32][36];
    __shared__ float Ws[32][32];

    const float* A; float* C; int N, K, mode;
    if (stage == 0)      { A = g_ph;   C = g_gbuf; N = DV_; K = H_;  mode = 1; }
    else if (stage == 1) { A = g_gbuf; C = g_obuf; N = DV_; K = DV_; mode = 0; }
    else if (stage == 2) { A = g_obuf; C = g_h2;   N = H_;  K = DV_; mode = 0; }
    else                 { A = g_h2;   C = outp;   N = NC_; K = H_;  mode = 2; }

    const int tid = threadIdx.x;
    const int m0 = blockIdx.x * 32, n0 = blockIdx.y * 32;
    const int r = tid >> 3, cg = tid & 7;
    float acc[4] = {0.f, 0.f, 0.f, 0.f};

    const int lrow = tid >> 3, lk4 = (tid & 7) * 4;
    for (int k0 = 0; k0 < K; k0 += 32) {
        float4 av = *(const float4*)(A + (size_t)(m0 + lrow) * K + k0 + lk4);
        *(float4*)&As[lrow][lk4] = av;
        #pragma unroll
        for (int u = 0; u < 4; u++) {
            int n = n0 + lk4 + u;
            Ws[lrow][lk4 + u] = (n < N) ? W[(size_t)(k0 + lrow) * N + n] : 0.f;
        }
        __syncthreads();
        #pragma unroll
        for (int k = 0; k < 32; k++) {
            float a = As[r][k];
            float4 w = *(const float4*)&Ws[k][cg*4];
            acc[0] += a * w.x; acc[1] += a * w.y; acc[2] += a * w.z; acc[3] += a * w.w;
        }
        __syncthreads();
    }
    const int row = m0 + r;
    #pragma unroll
    for (int u = 0; u < 4; u++) {
        int n = n0 + cg*4 + u;
        if (n >= N) continue;
        float x = acc[u];
        if (mode == 0)      x = fmaxf(x + bias[n], 0.f);
        else if (mode == 1) x = (x + g_S[row] * bias[n]) * g_q[((size_t)(row*4 + 0))*DV_ + n];
        else                x = x + bias[n];
        C[(size_t)row * N + n] = x;
    }
}

// ------------------------- launch ------------------------------------------
extern "C" void kernel_launch(void* const* d_in, const int* in_sizes, int n_in,
                              void* d_out, int out_size) {
    const float* node     = (const float*)d_in[0];
    const float* edge     = (const float*)d_in[1];
    const float* Wn1      = (const float*)d_in[2];
    const float* bn1      = (const float*)d_in[3];
    const float* Wn2      = (const float*)d_in[4];
    const float* bn2      = (const float*)d_in[5];
    const float* We1      = (const float*)d_in[6];
    const float* be1      = (const float*)d_in[7];
    const float* We2      = (const float*)d_in[8];
    const float* be2      = (const float*)d_in[9];
    const float* Wq       = (const float*)d_in[10];
    const float* bq       = (const float*)d_in[11];
    const float* Wc1      = (const float*)d_in[12];
    const float* bc1      = (const float*)d_in[13];
    const float* Wc2      = (const float*)d_in[14];
    const float* bc2      = (const float*)d_in[15];
    const float* word_emb = (const float*)d_in[16];
    const int* prog_in    = (const int*)d_in[18];
    float* out            = (float*)d_out;

    static int cc_major = -1;
    if (cc_major < 0) {
        int dev = 0;
        cudaGetDevice(&dev);
        cudaDeviceGetAttribute(&cc_major, cudaDevAttrComputeCapabilityMajor, dev);
        cudaFuncSetAttribute(edge_tc2_kernel,
                             cudaFuncAttributeMaxDynamicSharedMemorySize, EDGE_SMEM_DYN);
        cudaFuncSetAttribute(node_tc_kernel,
                             cudaFuncAttributeMaxDynamicSharedMemorySize, NODE_SMEM_DYN);
    }
    const bool tc = (cc_major >= 10);   // sm_10x: the 'a' cubin runs (proven via ncu tensor%)

    // 0..2: edge dependencies
    prep_kernel<<<192, dim3(32, 32)>>>(We1, Wn1);
    gather_q_kernel<<<(B_*4*DV_)/256, 256>>>(word_emb, prog_in);
    proj_mm_kernel<<<dim3(12, 8), 256>>>(Wn2, We2, bn2, be2);

    // 3: edge GEMM (index 3 so ncu profiles it)
    if (tc) {
        edge_tc2_kernel<<<EDGE_ROWS/256, 256, EDGE_SMEM_DYN>>>(edge, be1);
    } else {
        edge_mma_kernel<<<EDGE_ROWS/128, 512>>>(edge, We1, be1);
    }

    // node path
    if (tc) {
        node_tc_kernel<<<NODE_ROWS/128, 256, NODE_SMEM_DYN>>>(node, bn1);
    } else {
        node_mma_kernel<<<NODE_ROWS/128, 512>>>(node, Wn1, bn1);
    }

    score_kernel<<<NODE_ROWS/8, 256>>>();
    combine_kernel<<<B_, 256>>>();

    // final GEMV chain as tiled GEMMs (scratch selected in device code)
    final_mm_kernel<<<dim3(4, 16), 256>>>(0, Wn2, bn2, out);
    final_mm_kernel<<<dim3(4, 16), 256>>>(1, Wq,  bq,  out);
    final_mm_kernel<<<dim3(4, 8),  256>>>(2, Wc1, bc1, out);
    final_mm_kernel<<<dim3(4, 1),  256>>>(3, Wc2, bc2, out);
}

// round 16
// speedup vs baseline: 1.6630x; 1.0578x over previous
#include <cuda_runtime.h>
#include <math.h>
#include <stdint.h>

// Dims (CLEVR-scale, fixed)
#define B_   128
#define N_   36
#define DF_  512
#define DE_  256
#define DV_  512
#define H_   256
#define NC_  28
#define L_   5
#define ROWS_PER_B (N_*N_)          // 1296
#define NODE_ROWS  (B_*N_)          // 4608
#define EDGE_ROWS  (B_*ROWS_PER_B)  // 165888
#define SCALE_ 0.04419417382415922f // 1/sqrt(512)

// Feature gate: tcgen05 exists only in arch-specific (sm_103a / sm_100a) passes.
#if defined(__CUDA_ARCH_FEAT_SM103_ALL) || defined(__CUDA_ARCH_FEAT_SM100_ALL) || defined(__CUDA_ARCH_FEAT_SM101_ALL)
#define HAS_TC 1
#else
#define HAS_TC 0
#endif

// ------------------------- device scratch (no cudaMalloc allowed) -----------
// RULE (rounds 5-10 bug): these symbols are ONLY referenced inside device
// code. Never pass them as host-side kernel args.
__device__ float g_hn[NODE_ROWS * H_];
__device__ float g_u3[B_ * H_];
__device__ float g_u1[B_ * H_];
__device__ float g_v [B_ * H_];
__device__ float g_c3[B_];
__device__ float g_c1[B_];
__device__ float g_ce[B_];
__device__ float g_a1  [NODE_ROWS];
__device__ float g_sig1[NODE_ROWS];
__device__ float g_weit[EDGE_ROWS];
__device__ float g_ph[B_ * H_];
__device__ float g_S [B_];
__device__ float g_We1T[H_ * DE_];   // We1^T [n][k], rna tf32 (pre-rounded)
__device__ float g_Wn1T[H_ * DF_];   // Wn1^T [n][k], rna tf32 (pre-rounded)
__device__ float g_gbuf[B_ * DV_];
__device__ float g_obuf[B_ * DV_];
__device__ float g_h2  [B_ * H_];

__device__ __forceinline__ float sigmoidf_(float x) { return 1.0f / (1.0f + expf(-x)); }
__device__ __forceinline__ unsigned f2tf32(float x) {
    unsigned u; asm("cvt.rna.tf32.f32 %0, %1;" : "=r"(u) : "f"(x)); return u;
}
__device__ __forceinline__ void mma_tf32(float c[4], const unsigned a[4], const unsigned b[2]) {
    asm volatile("mma.sync.aligned.m16n8k8.row.col.f32.tf32.tf32.f32 "
        "{%0,%1,%2,%3}, {%4,%5,%6,%7}, {%8,%9}, {%0,%1,%2,%3};"
        : "+f"(c[0]), "+f"(c[1]), "+f"(c[2]), "+f"(c[3])
        : "r"(a[0]), "r"(a[1]), "r"(a[2]), "r"(a[3]), "r"(b[0]), "r"(b[1]));
}

// ------------------------- tcgen05 / async helpers --------------------------
__device__ __forceinline__ uint32_t smem_u32(const void* p) {
    uint32_t a;
    asm("{ .reg .u64 t; cvta.to.shared.u64 t, %1; cvt.u32.u64 %0, t; }" : "=r"(a) : "l"(p));
    return a;
}
__device__ __forceinline__ uint32_t elect_one_pred() {
    uint32_t pred;
    asm volatile("{\n\t.reg .pred p;\n\telect.sync _|p, 0xFFFFFFFF;\n\t"
                 "selp.b32 %0, 1, 0, p;\n\t}" : "=r"(pred));
    return pred;
}
__device__ __forceinline__ void cp16(uint32_t dst, const void* src) {
    asm volatile("cp.async.cg.shared.global [%0], [%1], 16;" :: "r"(dst), "l"(src) : "memory");
}
#define CP_COMMIT() asm volatile("cp.async.commit_group;" ::: "memory")
#define CP_WAIT1()  asm volatile("cp.async.wait_group 1;" ::: "memory")

static __device__ constexpr uint64_t SMEM_DESC_BASE_SW128 =
    (uint64_t(2)  << 61) | (uint64_t(1) << 46) | (uint64_t(64) << 32) | (uint64_t(1) << 16);
__device__ __forceinline__ uint64_t make_desc(uint32_t addr) {
    return SMEM_DESC_BASE_SW128 | ((uint64_t)(addr >> 4) & 0x3FFF);
}
// tf32 SS idesc: dtype=F32(1<<4), a/btype=TF32(2<<7,2<<10), N/8<<17, M/16<<24
#define EDGE_IDESC 0x8400910u

#if HAS_TC
__device__ __forceinline__ void tc_mma_tf32_ss(uint32_t d_tmem, uint64_t a_desc,
                                               uint64_t b_desc, uint32_t idesc, bool accum) {
    uint32_t en = accum ? 1u : 0u;
    asm volatile(
        "{\n\t.reg .pred p;\n\t"
        "setp.ne.u32 p, %5, 0;\n\t"
        "tcgen05.mma.cta_group::1.kind::tf32 [%0], %1, %2, %3, {%4, %4, %4, %4}, p;\n\t}"
        :: "r"(d_tmem), "l"(a_desc), "l"(b_desc), "r"(idesc), "r"(0u), "r"(en)
        : "memory");
}
#define TC_ALLOC(smem_addr, n) \
    asm volatile("tcgen05.alloc.cta_group::1.sync.aligned.shared::cta.b32 [%0], %1;" \
                 :: "r"((uint32_t)(smem_addr)), "r"((uint32_t)(n)) : "memory")
#define TC_DEALLOC(tmem, n) \
    asm volatile("tcgen05.dealloc.cta_group::1.sync.aligned.b32 %0, %1;" :: "r"(tmem), "r"((uint32_t)(n)))
#define TC_RELINQ() asm volatile("tcgen05.relinquish_alloc_permit.cta_group::1.sync.aligned;")
#define TC_COMMIT(mbar) \
    asm volatile("tcgen05.commit.cta_group::1.mbarrier::arrive::one.shared::cluster.b64 [%0];" \
                 :: "r"((uint32_t)(mbar)) : "memory")
#define TC_FENCE_AFTER()  asm volatile("tcgen05.fence::after_thread_sync;" ::: "memory")
#define TC_WAIT_LD()      asm volatile("tcgen05.wait::ld.sync.aligned;" ::: "memory")
#define MBAR_INIT(addr, cnt) \
    asm volatile("mbarrier.init.shared.b64 [%0], %1;" :: "r"((uint32_t)(addr)), "r"((uint32_t)(cnt)) : "memory")
#define MBAR_INVAL(addr) \
    asm volatile("mbarrier.inval.shared.b64 [%0];" :: "r"((uint32_t)(addr)) : "memory")
#define FENCE_PROXY_ASYNC() asm volatile("fence.proxy.async.shared::cta;" ::: "memory")
__device__ __forceinline__ void mbar_wait_parity(uint32_t addr, uint32_t parity) {
    asm volatile(
        "{\n\t.reg .pred P1;\n\t"
        "WAIT_%=:\n\t"
        "mbarrier.try_wait.parity.acquire.cta.shared::cta.b64 P1, [%0], %1, 0x989680;\n\t"
        "@P1 bra.uni DONE_%=;\n\t"
        "bra.uni WAIT_%=;\n\t"
        "DONE_%=:\n\t}"
        :: "r"(addr), "r"(parity) : "memory");
}
#define LDTM_X32(r, addr) \
    asm volatile( \
        "tcgen05.ld.sync.aligned.32x32b.x32.b32 " \
        "{%0, %1, %2, %3, %4, %5, %6, %7, " \
        " %8, %9, %10, %11, %12, %13, %14, %15, " \
        " %16, %17, %18, %19, %20, %21, %22, %23, " \
        " %24, %25, %26, %27, %28, %29, %30, %31}, [%32];" \
        : "=r"((r)[0]),  "=r"((r)[1]),  "=r"((r)[2]),  "=r"((r)[3]), \
          "=r"((r)[4]),  "=r"((r)[5]),  "=r"((r)[6]),  "=r"((r)[7]), \
          "=r"((r)[8]),  "=r"((r)[9]),  "=r"((r)[10]), "=r"((r)[11]), \
          "=r"((r)[12]), "=r"((r)[13]), "=r"((r)[14]), "=r"((r)[15]), \
          "=r"((r)[16]), "=r"((r)[17]), "=r"((r)[18]), "=r"((r)[19]), \
          "=r"((r)[20]), "=r"((r)[21]), "=r"((r)[22]), "=r"((r)[23]), \
          "=r"((r)[24]), "=r"((r)[25]), "=r"((r)[26]), "=r"((r)[27]), \
          "=r"((r)[28]), "=r"((r)[29]), "=r"((r)[30]), "=r"((r)[31]) \
        : "r"(addr))
#endif // HAS_TC

// ------------------------- K0: prep (both transposes, rna-rounded) ----------
__global__ void prep_kernel(const float* __restrict__ We1, const float* __restrict__ Wn1) {
    __shared__ float t[32][33];
    int bz = blockIdx.x;
    if (bz < 64) {
        int bx = (bz & 7) * 32, by = (bz >> 3) * 32;
        t[threadIdx.y][threadIdx.x] = We1[(size_t)(by + threadIdx.y) * H_ + bx + threadIdx.x];
        __syncthreads();
        g_We1T[(size_t)(bx + threadIdx.y) * DE_ + by + threadIdx.x] =
            __uint_as_float(f2tf32(t[threadIdx.x][threadIdx.y]));
    } else {
        int i = bz - 64;
        int bx = (i & 7) * 32, by = (i >> 3) * 32;
        t[threadIdx.y][threadIdx.x] = Wn1[(size_t)(by + threadIdx.y) * H_ + bx + threadIdx.x];
        __syncthreads();
        g_Wn1T[(size_t)(bx + threadIdx.y) * DF_ + by + threadIdx.x] =
            __uint_as_float(f2tf32(t[threadIdx.x][threadIdx.y]));
    }
}

// ------------------------- K1: proj GEMM + fused gather + scalar dots -------
// U[m][h] = sum_k q[m][k]*W[h][k]; q gathered inline from word_emb/prog_in.
// m 0-127 -> u3(l=3, Wn2); 128-255 -> u1(l=1, Wn2); 256-383 -> v(l=2, We2).
__global__ __launch_bounds__(256) void proj_mm_kernel(
        const float* __restrict__ Wn2, const float* __restrict__ We2,
        const float* __restrict__ bn2, const float* __restrict__ be2,
        const float* __restrict__ word_emb, const int* __restrict__ prog_in) {
    __shared__ float As[32][36];
    __shared__ float Ws[32][36];
    const int tid = threadIdx.x;
    const int m0 = blockIdx.x * 32, n0 = blockIdx.y * 32;
    const int r = tid >> 3, cg = tid & 7;
    const int lrow = tid >> 3, lk4 = (tid & 7) * 4;
    const int region = m0 >> 7;
    const float* W    = (region < 2) ? Wn2 : We2;
    const float* bias = (region < 2) ? bn2 : be2;
    const int lsel = (region == 0) ? 3 : (region == 1) ? 1 : 2;

    const int bq = (m0 + lrow) & 127;
    const float* qrow = word_emb + (size_t)prog_in[bq * L_ + lsel] * DV_;

    float acc[4] = {0.f, 0.f, 0.f, 0.f};
    float sacc = 0.f;

    for (int k0 = 0; k0 < DV_; k0 += 32) {
        float4 av = *(const float4*)(qrow + k0 + lk4);
        *(float4*)&As[lrow][lk4] = av;
        float4 wv = *(const float4*)(W + (size_t)(n0 + lrow) * DV_ + k0 + lk4);
        *(float4*)&Ws[lrow][lk4] = wv;
        if (n0 == 0) {
            float4 bv = *(const float4*)(bias + k0 + lk4);
            sacc += av.x*bv.x + av.y*bv.y + av.z*bv.z + av.w*bv.w;
        }
        __syncthreads();
        #pragma unroll
        for (int k = 0; k < 32; k++) {
            float a = As[r][k];
            acc[0] += a * Ws[cg*4+0][k];
            acc[1] += a * Ws[cg*4+1][k];
            acc[2] += a * Ws[cg*4+2][k];
            acc[3] += a * Ws[cg*4+3][k];
        }
        __syncthreads();
    }
    {
        int b = (m0 + r) & 127;
        float* U = (region == 0) ? g_u3 : (region == 1) ? g_u1 : g_v;
        #pragma unroll
        for (int u = 0; u < 4; u++) U[b * H_ + n0 + cg*4 + u] = acc[u];
    }
    if (n0 == 0) {
        sacc += __shfl_xor_sync(0xffffffffu, sacc, 1);
        sacc += __shfl_xor_sync(0xffffffffu, sacc, 2);
        sacc += __shfl_xor_sync(0xffffffffu, sacc, 4);
        if ((tid & 7) == 0) {
            float* cd = (region == 0) ? g_c3 : (region == 1) ? g_c1 : g_ce;
            cd[(m0 + lrow) & 127] = sacc;
        }
    }
}

// ------------------------- K2: edge GEMM, tcgen05 + cp.async (re-skewed) ----
// M=256/CTA, N=256, K=256 (8 chunks of 32), 3 buffers. Loads for chunk c+2
// are gated on MMA(c-1) (one iteration old) — MMA latency is OFF the
// critical path. CP_WAIT1 at top guarantees chunk c resident.
#define EDGE_SMEM_DYN (1024 + 3*65536)
__global__ __launch_bounds__(256, 1)
void edge_tc2_kernel(const float* __restrict__ edge, const float* __restrict__ be1) {
#if HAS_TC
    extern __shared__ char dsm[];
    __shared__ uint32_t sh_tmem;
    __shared__ uint64_t sh_mbar[3];
    __shared__ float bs[256], vs0[256], vs1[256];
    __shared__ float ces[2];

    const int tid = threadIdx.x, warp = tid >> 5, lane = tid & 31;
    const int row0 = blockIdx.x * 256;

    const int b0 = row0 / ROWS_PER_B;
    const int bn_ = (b0 + 1 < B_) ? b0 + 1 : b0;
    const int split = (b0 + 1) * ROWS_PER_B - row0;

    uint32_t dbase = smem_u32(dsm);
    uint32_t aligned = (dbase + 1023u) & ~1023u;

    if (warp == 0) { TC_ALLOC(smem_u32(&sh_tmem), 512); TC_RELINQ(); }
    if (tid == 0) {
        MBAR_INIT(smem_u32(&sh_mbar[0]), 1);
        MBAR_INIT(smem_u32(&sh_mbar[1]), 1);
        MBAR_INIT(smem_u32(&sh_mbar[2]), 1);
        ces[0] = g_ce[b0]; ces[1] = g_ce[bn_];
    }
    bs[tid]  = be1[tid];
    vs0[tid] = g_v[b0  * H_ + tid];
    vs1[tid] = g_v[bn_ * H_ + tid];
    __syncthreads();

    const uint32_t tmem = sh_tmem;
    uint32_t mb[3] = { smem_u32(&sh_mbar[0]), smem_u32(&sh_mbar[1]), smem_u32(&sh_mbar[2]) };
    const float* Abase = edge + (size_t)row0 * DE_;

    const int rA = tid >> 3, cA = tid & 7;

    auto load_chunk = [&](int j, int buf) {
        uint32_t st = aligned + (uint32_t)buf * 65536u;
        int k0 = j * 32;
        #pragma unroll
        for (int t = 0; t < 8; t++) {
            int r = rA + t*32;
            uint32_t byte = (uint32_t)((r & 127)*128 + cA*16);
            uint32_t off = ((uint32_t)(r >> 7) << 14) + (byte ^ ((byte>>3)&0x70u));
            cp16(st + off, Abase + (size_t)r*DE_ + k0 + cA*4);
        }
        #pragma unroll
        for (int t = 0; t < 8; t++) {
            int n = rA + t*32;
            uint32_t byte = (uint32_t)(n*128 + cA*16);
            cp16(st + 32768u + (byte ^ ((byte>>3)&0x70u)), g_We1T + (size_t)n*DE_ + k0 + cA*4);
        }
        CP_COMMIT();
    };

    load_chunk(0, 0); load_chunk(1, 1);

    #pragma unroll 1
    for (int c = 0; c < 8; c++) {
        CP_WAIT1();              // chunk c complete (only chunk c+1 newer)
        FENCE_PROXY_ASYNC();
        __syncthreads();
        if (warp == 0) {
            if (elect_one_pred()) {
                uint32_t st = aligned + (uint32_t)(c % 3) * 65536u;
                uint64_t ad0 = make_desc(st);
                uint64_t ad1 = make_desc(st + 16384u);
                uint64_t bd  = make_desc(st + 32768u);
                #pragma unroll
                for (int s = 0; s < 4; s++) {
                    bool acc = (c > 0) || (s > 0);
                    tc_mma_tf32_ss(tmem,        ad0 + 2*s, bd + 2*s, EDGE_IDESC, acc);
                    tc_mma_tf32_ss(tmem + 256u, ad1 + 2*s, bd + 2*s, EDGE_IDESC, acc);
                }
                TC_COMMIT(mb[c % 3]);
            }
        }
        if (c + 2 < 8) {
            // buf (c+2)%3 == (c-1)%3, last read by MMA(c-1) (issued LAST iter)
            if (c >= 1) mbar_wait_parity(mb[(c - 1) % 3], (uint32_t)((c - 1) / 3) & 1u);
            load_chunk(c + 2, (c + 2) % 3);
        } else {
            CP_COMMIT();        // empty group keeps CP_WAIT1 semantics
        }
    }
    // completions: mb0 {0,3,6}, mb1 {1,4,7}, mb2 {2,5}.
    // in-loop consumed: mb0 #1(c=1),#2(c=4); mb1 #1(c=2),#2(c=5); mb2 #1(c=3).
    mbar_wait_parity(mb[2], 1u);   // MMA5 = #2 -> parity 1
    mbar_wait_parity(mb[0], 0u);   // MMA6 = #3 -> parity 0
    mbar_wait_parity(mb[1], 0u);   // MMA7 = #3 -> parity 0
    TC_FENCE_AFTER();

    // epilogue
    {
        const int half = warp >> 2;
        const int rlocal = half*128 + (warp & 3)*32 + lane;
        const float* vrow = (rlocal < split) ? vs0 : vs1;
        const uint32_t tb = tmem + (uint32_t)(half ? 256 : 0);
        float s = 0.f;
        #pragma unroll
        for (int it = 0; it < 8; it++) {
            uint32_t d[32];
            LDTM_X32(d, tb + it*32);
            TC_WAIT_LD();
            #pragma unroll
            for (int cc = 0; cc < 32; cc++) {
                int n = it*32 + cc;
                float h = fmaxf(__uint_as_float(d[cc]) + bs[n], 0.f);
                s += h * vrow[n];
            }
        }
        float ce = (rlocal < split) ? ces[0] : ces[1];
        g_weit[row0 + rlocal] = sigmoidf_((s + ce) * SCALE_);
    }
    __syncthreads();
    if (tid == 0) { MBAR_INVAL(mb[0]); MBAR_INVAL(mb[1]); MBAR_INVAL(mb[2]); }
    if (warp == 0) TC_DEALLOC(tmem, 512);
#else
    (void)edge; (void)be1;
#endif
}

// ------------------------- K2b: edge GEMM via mma.sync (base-arch) ----------
#define BK_ 16
__global__ __launch_bounds__(512, 1) void edge_mma_kernel(
        const float* __restrict__ edge, const float* __restrict__ We1,
        const float* __restrict__ be1) {
#if !HAS_TC
    __shared__ unsigned As[128][20];
    __shared__ unsigned Bs[BK_][264];
    __shared__ float s_sh[128];
    __shared__ float bs[256], vs0[256], vs1[256];
    __shared__ float ces[2];

    const int tid  = threadIdx.x;
    const int warp = tid >> 5, lane = tid & 31;
    const int warpM = warp >> 2, warpN = warp & 3;
    const int g = lane >> 2, kq = lane & 3;
    const int row0 = blockIdx.x * 128;

    const int b0 = row0 / ROWS_PER_B;
    const int bn_ = (b0 + 1 < B_) ? b0 + 1 : b0;
    const int split = (b0 + 1) * ROWS_PER_B - row0;

    if (tid < 256) {
        bs[tid]  = be1[tid];
        vs0[tid] = g_v[b0  * H_ + tid];
        vs1[tid] = g_v[bn_ * H_ + tid];
    }
    if (tid < 128) s_sh[tid] = 0.f;
    if (tid == 0) { ces[0] = g_ce[b0]; ces[1] = g_ce[bn_]; }

    float acc[2][8][4];
    #pragma unroll
    for (int mt = 0; mt < 2; mt++)
        #pragma unroll
        for (int nt = 0; nt < 8; nt++)
            #pragma unroll
            for (int c = 0; c < 4; c++) acc[mt][nt][c] = 0.f;

    const int ra = tid >> 2, ca = tid & 3;
    const float* Abase = edge + (size_t)row0 * DE_;

    float4 pa;
    float4 pb[2];
    {
        pa = *(const float4*)(Abase + (size_t)ra * DE_ + ca*4);
        #pragma unroll
        for (int t = 0; t < 2; t++) {
            int i4 = tid + t*512; int kr = i4 >> 6, c4 = i4 & 63;
            pb[t] = *(const float4*)(We1 + (size_t)kr * 256 + c4*4);
        }
    }
    const int S = DE_ / BK_;
    for (int s = 0; s < S; s++) {
        *(uint4*)&As[ra][ca*4] = make_uint4(f2tf32(pa.x), f2tf32(pa.y), f2tf32(pa.z), f2tf32(pa.w));
        #pragma unroll
        for (int t = 0; t < 2; t++) {
            int i4 = tid + t*512; int kr = i4 >> 6, c4 = i4 & 63;
            *(uint4*)&Bs[kr][c4*4] = make_uint4(f2tf32(pb[t].x), f2tf32(pb[t].y), f2tf32(pb[t].z), f2tf32(pb[t].w));
        }
        __syncthreads();
        if (s + 1 < S) {
            int k0 = (s + 1) * BK_;
            pa = *(const float4*)(Abase + (size_t)ra * DE_ + k0 + ca*4);
            #pragma unroll
            for (int t = 0; t < 2; t++) {
                int i4 = tid + t*512; int kr = i4 >> 6, c4 = i4 & 63;
                pb[t] = *(const float4*)(We1 + (size_t)(k0 + kr) * 256 + c4*4);
            }
        }
        #pragma unroll
        for (int kk = 0; kk < 2; kk++) {
            unsigned af[2][4], bf[8][2];
            #pragma unroll
            for (int mt = 0; mt < 2; mt++) {
                int r = warpM*32 + mt*16 + g;
                af[mt][0] = As[r    ][kk*8 + kq];
                af[mt][1] = As[r + 8][kk*8 + kq];
                af[mt][2] = As[r    ][kk*8 + kq + 4];
                af[mt][3] = As[r + 8][kk*8 + kq + 4];
            }
            #pragma unroll
            for (int nt = 0; nt < 8; nt++) {
                int n = warpN*64 + nt*8 + g;
                bf[nt][0] = Bs[kk*8 + kq    ][n];
                bf[nt][1] = Bs[kk*8 + kq + 4][n];
            }
            #pragma unroll
            for (int mt = 0; mt < 2; mt++)
                #pragma unroll
                for (int nt = 0; nt < 8; nt++) mma_tf32(acc[mt][nt], af[mt], bf[nt]);
        }
        __syncthreads();
    }
    #pragma unroll
    for (int mt = 0; mt < 2; mt++) {
        int rA = warpM*32 + mt*16 + g;
        int rB = rA + 8;
        const float* vA = (rA < split) ? vs0 : vs1;
        const float* vB = (rB < split) ? vs0 : vs1;
        float pA = 0.f, pB = 0.f;
        #pragma unroll
        for (int nt = 0; nt < 8; nt++) {
            int n = warpN*64 + nt*8 + kq*2;
            float b0v = bs[n], b1v = bs[n+1];
            pA += fmaxf(acc[mt][nt][0] + b0v, 0.f) * vA[n]
                + fmaxf(acc[mt][nt][1] + b1v, 0.f) * vA[n+1];
            pB += fmaxf(acc[mt][nt][2] + b0v, 0.f) * vB[n]
                + fmaxf(acc[mt][nt][3] + b1v, 0.f) * vB[n+1];
        }
        pA += __shfl_xor_sync(0xffffffffu, pA, 1);
        pA += __shfl_xor_sync(0xffffffffu, pA, 2);
        pB += __shfl_xor_sync(0xffffffffu, pB, 1);
        pB += __shfl_xor_sync(0xffffffffu, pB, 2);
        if (kq == 0) {
            atomicAdd(&s_sh[rA], pA);
            atomicAdd(&s_sh[rB], pB);
        }
    }
    __syncthreads();
    if (tid < 128) {
        float ce = (tid < split) ? ces[0] : ces[1];
        g_weit[row0 + tid] = sigmoidf_((s_sh[tid] + ce) * SCALE_);
    }
#else
    (void)edge; (void)We1; (void)be1;
#endif
}

// ------------------------- K3: node MLP1 via tcgen05 + FUSED score ----------
// M=128/CTA (36 CTAs), K=512 (16 chunks of 32), N=256. LDG->regs->STS,
// 2-buffer, register prefetch (proven). Epilogue also computes the two
// filter-score dots (u3/u1) and writes g_a1/g_sig1 (score kernel fused).
#define NODE_SMEM_DYN (1024 + 2*49152)
__global__ __launch_bounds__(256, 1)
void node_tc_kernel(const float* __restrict__ node, const float* __restrict__ bn1) {
#if HAS_TC
    extern __shared__ char dsm[];
    __shared__ uint32_t sh_tmem;
    __shared__ uint64_t sh_mbar[2];
    __shared__ float bs[256];
    __shared__ float sd3[128], sd1[128];

    const int tid = threadIdx.x, warp = tid >> 5, lane = tid & 31;
    const int row0 = blockIdx.x * 128;

    uint32_t dbase = smem_u32(dsm);
    uint32_t aligned = (dbase + 1023u) & ~1023u;
    char* smbase = dsm + (aligned - dbase);

    if (warp == 0) { TC_ALLOC(smem_u32(&sh_tmem), 256); TC_RELINQ(); }
    if (tid == 0) {
        MBAR_INIT(smem_u32(&sh_mbar[0]), 1);
        MBAR_INIT(smem_u32(&sh_mbar[1]), 1);
    }
    bs[tid] = bn1[tid];
    __syncthreads();

    const uint32_t tmem = sh_tmem;
    uint32_t mb[2] = { smem_u32(&sh_mbar[0]), smem_u32(&sh_mbar[1]) };
    const float* Abase = node + (size_t)row0 * DF_;

    float4 pa[4], pb[8];
    const int rA = tid >> 3, cA = tid & 7;

    #pragma unroll
    for (int t = 0; t < 4; t++)
        pa[t] = *(const float4*)(Abase + (size_t)(rA + t*32) * DF_ + cA*4);
    #pragma unroll
    for (int t = 0; t < 8; t++)
        pb[t] = *(const float4*)(g_Wn1T + (size_t)(rA + t*32) * DF_ + cA*4);

    #pragma unroll 1
    for (int c = 0; c < 16; c++) {
        const int buf = c & 1;
        if (c >= 2) mbar_wait_parity(mb[buf], (uint32_t)((c - 2) >> 1) & 1u);
        {
            char* st = smbase + (size_t)buf * 49152u;
            #pragma unroll
            for (int t = 0; t < 4; t++) {
                int r = rA + t*32;
                uint32_t byte = (uint32_t)(r*128 + cA*16);
                *(uint4*)(st + (byte ^ ((byte>>3)&0x70u))) =
                    make_uint4(f2tf32(pa[t].x), f2tf32(pa[t].y), f2tf32(pa[t].z), f2tf32(pa[t].w));
            }
            #pragma unroll
            for (int t = 0; t < 8; t++) {
                int n = rA + t*32;
                uint32_t byte = (uint32_t)(n*128 + cA*16);
                *(uint4*)(st + 16384u + (byte ^ ((byte>>3)&0x70u))) =
                    make_uint4(__float_as_uint(pb[t].x), __float_as_uint(pb[t].y),
                               __float_as_uint(pb[t].z), __float_as_uint(pb[t].w));
            }
        }
        if (c + 1 < 16) {
            int k0 = (c + 1) * 32;
            #pragma unroll
            for (int t = 0; t < 4; t++)
                pa[t] = *(const float4*)(Abase + (size_t)(rA + t*32) * DF_ + k0 + cA*4);
            #pragma unroll
            for (int t = 0; t < 8; t++)
                pb[t] = *(const float4*)(g_Wn1T + (size_t)(rA + t*32) * DF_ + k0 + cA*4);
        }
        FENCE_PROXY_ASYNC();
        __syncthreads();
        if (warp == 0) {
            if (elect_one_pred()) {
                uint32_t st = aligned + (uint32_t)buf * 49152u;
                uint64_t ad = make_desc(st);
                uint64_t bd = make_desc(st + 16384u);
                #pragma unroll
                for (int s = 0; s < 4; s++)
                    tc_mma_tf32_ss(tmem, ad + 2*s, bd + 2*s, EDGE_IDESC, (c > 0) || (s > 0));
                TC_COMMIT(mb[buf]);
            }
        }
    }
    mbar_wait_parity(mb[0], 1u);
    mbar_wait_parity(mb[1], 1u);
    TC_FENCE_AFTER();

    // epilogue: store hn + fused score partial dots
    {
        const int half = warp >> 2;
        const int lr = (warp & 3) * 32 + lane;
        const int grow = row0 + lr;
        const int b = grow / N_;
        const int colbase = half * 128;
        float* dst = g_hn + (size_t)grow * H_;
        const float* u3r = g_u3 + b * H_;
        const float* u1r = g_u1 + b * H_;
        float d3 = 0.f, d1 = 0.f;
        #pragma unroll
        for (int it = 0; it < 4; it++) {
            uint32_t d[32];
            int cb = colbase + it*32;
            LDTM_X32(d, tmem + cb);
            TC_WAIT_LD();
            #pragma unroll
            for (int k = 0; k < 8; k++) {
                int n = cb + k*4;
                float4 o;
                o.x = fmaxf(__uint_as_float(d[k*4+0]) + bs[n+0], 0.f);
                o.y = fmaxf(__uint_as_float(d[k*4+1]) + bs[n+1], 0.f);
                o.z = fmaxf(__uint_as_float(d[k*4+2]) + bs[n+2], 0.f);
                o.w = fmaxf(__uint_as_float(d[k*4+3]) + bs[n+3], 0.f);
                *(float4*)(dst + n) = o;
                float4 u3v = *(const float4*)(u3r + n);
                float4 u1v = *(const float4*)(u1r + n);
                d3 += o.x*u3v.x + o.y*u3v.y + o.z*u3v.z + o.w*u3v.w;
                d1 += o.x*u1v.x + o.y*u1v.y + o.z*u1v.z + o.w*u1v.w;
            }
        }
        if (half == 0) { sd3[lr] = d3; sd1[lr] = d1; }
        __syncthreads();
        if (half == 1) {
            float t3 = sd3[lr] + d3, t1 = sd1[lr] + d1;
            g_a1[grow]   = sigmoidf_((t3 + g_c3[b]) * SCALE_);
            g_sig1[grow] = sigmoidf_((t1 + g_c1[b]) * SCALE_);
        }
    }
    __syncthreads();
    if (tid == 0) { MBAR_INVAL(mb[0]); MBAR_INVAL(mb[1]); }
    if (warp == 0) TC_DEALLOC(tmem, 256);
#else
    (void)node; (void)bn1;
#endif
}

// ------------------------- K3b: node MLP1 via mma.sync (base-arch) ----------
__global__ __launch_bounds__(512, 1) void node_mma_kernel(
        const float* __restrict__ node, const float* __restrict__ Wn1,
        const float* __restrict__ bn1) {
#if !HAS_TC
    __shared__ unsigned As[128][20];
    __shared__ unsigned Bs[BK_][264];
    __shared__ float bs[256];

    const int tid  = threadIdx.x;
    const int warp = tid >> 5, lane = tid & 31;
    const int warpM = warp >> 2, warpN = warp & 3;
    const int g = lane >> 2, kq = lane & 3;
    const int row0 = blockIdx.x * 128;

    if (tid < 256) bs[tid] = bn1[tid];

    float acc[2][8][4];
    #pragma unroll
    for (int mt = 0; mt < 2; mt++)
        #pragma unroll
        for (int nt = 0; nt < 8; nt++)
            #pragma unroll
            for (int c = 0; c < 4; c++) acc[mt][nt][c] = 0.f;

    const int ra = tid >> 2, ca = tid & 3;
    const float* Abase = node + (size_t)row0 * DF_;

    float4 pa;
    float4 pb[2];
    {
        pa = *(const float4*)(Abase + (size_t)ra * DF_ + ca*4);
        #pragma unroll
        for (int t = 0; t < 2; t++) {
            int i4 = tid + t*512; int kr = i4 >> 6, c4 = i4 & 63;
            pb[t] = *(const float4*)(Wn1 + (size_t)kr * H_ + c4*4);
        }
    }
    const int S = DF_ / BK_;
    for (int s = 0; s < S; s++) {
        *(uint4*)&As[ra][ca*4] = make_uint4(f2tf32(pa.x), f2tf32(pa.y), f2tf32(pa.z), f2tf32(pa.w));
        #pragma unroll
        for (int t = 0; t < 2; t++) {
            int i4 = tid + t*512; int kr = i4 >> 6, c4 = i4 & 63;
            *(uint4*)&Bs[kr][c4*4] = make_uint4(f2tf32(pb[t].x), f2tf32(pb[t].y), f2tf32(pb[t].z), f2tf32(pb[t].w));
        }
        __syncthreads();
        if (s + 1 < S) {
            int k0 = (s + 1) * BK_;
            pa = *(const float4*)(Abase + (size_t)ra * DF_ + k0 + ca*4);
            #pragma unroll
            for (int t = 0; t < 2; t++) {
                int i4 = tid + t*512; int kr = i4 >> 6, c4 = i4 & 63;
                pb[t] = *(const float4*)(Wn1 + (size_t)(k0 + kr) * H_ + c4*4);
            }
        }
        #pragma unroll
        for (int kk = 0; kk < 2; kk++) {
            unsigned af[2][4], bf[8][2];
            #pragma unroll
            for (int mt = 0; mt < 2; mt++) {
                int r = warpM*32 + mt*16 + g;
                af[mt][0] = As[r    ][kk*8 + kq];
                af[mt][1] = As[r + 8][kk*8 + kq];
                af[mt][2] = As[r    ][kk*8 + kq + 4];
                af[mt][3] = As[r + 8][kk*8 + kq + 4];
            }
            #pragma unroll
            for (int nt = 0; nt < 8; nt++) {
                int n = warpN*64 + nt*8 + g;
                bf[nt][0] = Bs[kk*8 + kq    ][n];
                bf[nt][1] = Bs[kk*8 + kq + 4][n];
            }
            #pragma unroll
            for (int mt = 0; mt < 2; mt++)
                #pragma unroll
                for (int nt = 0; nt < 8; nt++) mma_tf32(acc[mt][nt], af[mt], bf[nt]);
        }
        __syncthreads();
    }
    #pragma unroll
    for (int mt = 0; mt < 2; mt++) {
        int rA = row0 + warpM*32 + mt*16 + g;
        int rB = rA + 8;
        #pragma unroll
        for (int nt = 0; nt < 8; nt++) {
            int n = warpN*64 + nt*8 + kq*2;
            float b0v = bs[n], b1v = bs[n+1];
            float2 v0 = make_float2(fmaxf(acc[mt][nt][0] + b0v, 0.f), fmaxf(acc[mt][nt][1] + b1v, 0.f));
            float2 v1 = make_float2(fmaxf(acc[mt][nt][2] + b0v, 0.f), fmaxf(acc[mt][nt][3] + b1v, 0.f));
            *(float2*)&g_hn[(size_t)rA * H_ + n] = v0;
            *(float2*)&g_hn[(size_t)rB * H_ + n] = v1;
        }
    }
#else
    (void)node; (void)Wn1; (void)bn1;
#endif
}

// ------------------------- K4: filter scores (base path only) ---------------
__global__ void score_kernel() {
    int gw = (blockIdx.x * 256 + threadIdx.x) >> 5;
    int lane = threadIdx.x & 31;
    if (gw >= NODE_ROWS) return;
    int b = gw / N_;
    const float* h  = g_hn + (size_t)gw * H_;
    const float* u3 = g_u3 + b * H_;
    const float* u1 = g_u1 + b * H_;
    float d3 = 0.f, d1 = 0.f;
    #pragma unroll
    for (int t = 0; t < 8; t++) {
        int d = lane + t*32;
        float hv = h[d];
        d3 += hv * u3[d];
        d1 += hv * u1[d];
    }
    #pragma unroll
    for (int o = 16; o > 0; o >>= 1) {
        d3 += __shfl_xor_sync(0xffffffffu, d3, o);
        d1 += __shfl_xor_sync(0xffffffffu, d1, o);
    }
    if (lane == 0) {
        g_a1[gw]   = sigmoidf_((d3 + g_c3[b]) * SCALE_);
        g_sig1[gw] = sigmoidf_((d1 + g_c1[b]) * SCALE_);
    }
}

// ------------------------- K5: attention chain + pooled hidden --------------
__global__ void combine_kernel() {
    int b = blockIdx.x;
    int tid = threadIdx.x;
    __shared__ float a1s[N_];
    __shared__ float a3s[N_];
    __shared__ float sInv, sS;
    if (tid < N_) a1s[tid] = g_a1[b * N_ + tid];
    __syncthreads();
    if (tid < N_) {
        int j = tid;
        float acc = 0.f;
        const float* w = g_weit + (size_t)b * ROWS_PER_B;
        #pragma unroll
        for (int i = 0; i < N_; i++) acc += a1s[i] * w[i * N_ + j];
        acc = fminf(fmaxf(acc, 0.f), 1.f);
        a3s[j] = acc * g_sig1[b * N_ + j];
    }
    __syncthreads();
    if (tid == 0) {
        float s0 = 0.f;
        #pragma unroll
        for (int j = 0; j < N_; j++) s0 += a3s[j];
        float inv = 1.f / (s0 + 1e-8f);
        sInv = inv;
        sS = s0 * inv;
    }
    __syncthreads();
    {
        int h = tid;
        float acc = 0.f;
        #pragma unroll
        for (int j = 0; j < N_; j++)
            acc += a3s[j] * g_hn[((size_t)(b * N_ + j)) * H_ + h];
        g_ph[b * H_ + h] = acc * sInv;
    }
    if (tid == 0) g_S[b] = sS;
}

// ------------------------- K6: final chain, 32x32 tiled GEMM stages ---------
__global__ __launch_bounds__(256) void final_mm_kernel(
        int stage, const float* __restrict__ W, const float* __restrict__ bias,
        const float* __restrict__ word_emb, const int* __restrict__ prog_in,
        float* __restrict__ outp) {
    __shared__ float As[32][36];
    __shared__ float Ws[32][36];

    const float* A; float* C; int N, K, mode;
    if (stage == 0)      { A = g_ph;   C = g_gbuf; N = DV_; K = H_;  mode = 1; }
    else if (stage == 1) { A = g_gbuf; C = g_obuf; N = DV_; K = DV_; mode = 0; }
    else if (stage == 2) { A = g_obuf; C = g_h2;   N = H_;  K = DV_; mode = 0; }
    else                 { A = g_h2;   C = outp;   N = NC_; K = H_;  mode = 2; }

    const int tid = threadIdx.x;
    const int m0 = blockIdx.x * 32, n0 = blockIdx.y * 32;
    const int r = tid >> 3, cg = tid & 7;
    float acc[4] = {0.f, 0.f, 0.f, 0.f};

    const int lrow = tid >> 3, lk4 = (tid & 7) * 4;
    for (int k0 = 0; k0 < K; k0 += 32) {
        float4 av = *(const float4*)(A + (size_t)(m0 + lrow) * K + k0 + lk4);
        *(float4*)&As[lrow][lk4] = av;
        #pragma unroll
        for (int u = 0; u < 4; u++) {
            int n = n0 + lk4 + u;
            Ws[lrow][lk4 + u] = (n < N) ? W[(size_t)(k0 + lrow) * N + n] : 0.f;
        }
        __syncthreads();
        #pragma unroll
        for (int k = 0; k < 32; k++) {
            float a = As[r][k];
            acc[0] += a * Ws[k][cg*4+0]; acc[1] += a * Ws[k][cg*4+1];
            acc[2] += a * Ws[k][cg*4+2]; acc[3] += a * Ws[k][cg*4+3];
        }
        __syncthreads();
    }
    const int row = m0 + r;
    int w0 = (mode == 1) ? prog_in[row * L_ + 0] : 0;
    #pragma unroll
    for (int u = 0; u < 4; u++) {
        int n = n0 + cg*4 + u;
        if (n >= N) continue;
        float x = acc[u];
        if (mode == 0)      x = fmaxf(x + bias[n], 0.f);
        else if (mode == 1) x = (x + g_S[row] * bias[n]) * word_emb[(size_t)w0 * DV_ + n];
        else                x = x + bias[n];
        C[(size_t)row * N + n] = x;
    }
}

// ------------------------- launch ------------------------------------------
extern "C" void kernel_launch(void* const* d_in, const int* in_sizes, int n_in,
                              void* d_out, int out_size) {
    const float* node     = (const float*)d_in[0];
    const float* edge     = (const float*)d_in[1];
    const float* Wn1      = (const float*)d_in[2];
    const float* bn1      = (const float*)d_in[3];
    const float* Wn2      = (const float*)d_in[4];
    const float* bn2      = (const float*)d_in[5];
    const float* We1      = (const float*)d_in[6];
    const float* be1      = (const float*)d_in[7];
    const float* We2      = (const float*)d_in[8];
    const float* be2      = (const float*)d_in[9];
    const float* Wq       = (const float*)d_in[10];
    const float* bq       = (const float*)d_in[11];
    const float* Wc1      = (const float*)d_in[12];
    const float* bc1      = (const float*)d_in[13];
    const float* Wc2      = (const float*)d_in[14];
    const float* bc2      = (const float*)d_in[15];
    const float* word_emb = (const float*)d_in[16];
    const int* prog_in    = (const int*)d_in[18];
    float* out            = (float*)d_out;

    static int cc_major = -1;
    if (cc_major < 0) {
        int dev = 0;
        cudaGetDevice(&dev);
        cudaDeviceGetAttribute(&cc_major, cudaDevAttrComputeCapabilityMajor, dev);
        cudaFuncSetAttribute(edge_tc2_kernel,
                             cudaFuncAttributeMaxDynamicSharedMemorySize, EDGE_SMEM_DYN);
        cudaFuncSetAttribute(node_tc_kernel,
                             cudaFuncAttributeMaxDynamicSharedMemorySize, NODE_SMEM_DYN);
    }
    const bool tc = (cc_major >= 10);

    prep_kernel<<<192, dim3(32, 32)>>>(We1, Wn1);
    proj_mm_kernel<<<dim3(12, 8), 256>>>(Wn2, We2, bn2, be2, word_emb, prog_in);

    if (tc) {
        edge_tc2_kernel<<<EDGE_ROWS/256, 256, EDGE_SMEM_DYN>>>(edge, be1);
        node_tc_kernel<<<NODE_ROWS/128, 256, NODE_SMEM_DYN>>>(node, bn1);
    } else {
        edge_mma_kernel<<<EDGE_ROWS/128, 512>>>(edge, We1, be1);
        node_mma_kernel<<<NODE_ROWS/128, 512>>>(node, Wn1, bn1);
        score_kernel<<<NODE_ROWS/8, 256>>>();
    }

    combine_kernel<<<B_, 256>>>();

    final_mm_kernel<<<dim3(4, 16), 256>>>(0, Wn2, bn2, word_emb, prog_in, out);
    final_mm_kernel<<<dim3(4, 16), 256>>>(1, Wq,  bq,  word_emb, prog_in, out);
    final_mm_kernel<<<dim3(4, 8),  256>>>(2, Wc1, bc1, word_emb, prog_in, out);
    final_mm_kernel<<<dim3(4, 1),  256>>>(3, Wc2, bc2, word_emb, prog_in, out);
}

// round 17
// speedup vs baseline: 1.7174x; 1.0327x over previous
#include <cuda_runtime.h>
#include <math.h>
#include <stdint.h>

// Dims (CLEVR-scale, fixed)
#define B_   128
#define N_   36
#define DF_  512
#define DE_  256
#define DV_  512
#define H_   256
#define NC_  28
#define L_   5
#define ROWS_PER_B (N_*N_)          // 1296
#define NODE_ROWS  (B_*N_)          // 4608
#define EDGE_ROWS  (B_*ROWS_PER_B)  // 165888
#define SCALE_ 0.04419417382415922f // 1/sqrt(512)

// Feature gate: tcgen05 exists only in arch-specific (sm_103a / sm_100a) passes.
#if defined(__CUDA_ARCH_FEAT_SM103_ALL) || defined(__CUDA_ARCH_FEAT_SM100_ALL) || defined(__CUDA_ARCH_FEAT_SM101_ALL)
#define HAS_TC 1
#else
#define HAS_TC 0
#endif

// ------------------------- device scratch (no cudaMalloc allowed) -----------
// RULE (rounds 5-10 bug): these symbols are ONLY referenced inside device
// code. Never pass them as host-side kernel args.
__device__ float g_hn[NODE_ROWS * H_];
__device__ float g_u3[B_ * H_];
__device__ float g_u1[B_ * H_];
__device__ float g_v [B_ * H_];
__device__ float g_c3[B_];
__device__ float g_c1[B_];
__device__ float g_ce[B_];
__device__ float g_a1  [NODE_ROWS];
__device__ float g_sig1[NODE_ROWS];
__device__ float g_weit[EDGE_ROWS];
__device__ float g_ph[B_ * H_];
__device__ float g_S [B_];
__device__ float g_We1T[H_ * DE_];   // We1^T [n][k], rna tf32 (pre-rounded)
__device__ float g_Wn1T[H_ * DF_];   // Wn1^T [n][k], rna tf32 (pre-rounded)
__device__ float g_gbuf[B_ * DV_];
__device__ float g_obuf[B_ * DV_];
__device__ float g_h2  [B_ * H_];

__device__ __forceinline__ float sigmoidf_(float x) { return 1.0f / (1.0f + expf(-x)); }
__device__ __forceinline__ unsigned f2tf32(float x) {
    unsigned u; asm("cvt.rna.tf32.f32 %0, %1;" : "=r"(u) : "f"(x)); return u;
}
__device__ __forceinline__ void mma_tf32(float c[4], const unsigned a[4], const unsigned b[2]) {
    asm volatile("mma.sync.aligned.m16n8k8.row.col.f32.tf32.tf32.f32 "
        "{%0,%1,%2,%3}, {%4,%5,%6,%7}, {%8,%9}, {%0,%1,%2,%3};"
        : "+f"(c[0]), "+f"(c[1]), "+f"(c[2]), "+f"(c[3])
        : "r"(a[0]), "r"(a[1]), "r"(a[2]), "r"(a[3]), "r"(b[0]), "r"(b[1]));
}

// ------------------------- tcgen05 / async helpers --------------------------
__device__ __forceinline__ uint32_t smem_u32(const void* p) {
    uint32_t a;
    asm("{ .reg .u64 t; cvta.to.shared.u64 t, %1; cvt.u32.u64 %0, t; }" : "=r"(a) : "l"(p));
    return a;
}
__device__ __forceinline__ uint32_t elect_one_pred() {
    uint32_t pred;
    asm volatile("{\n\t.reg .pred p;\n\telect.sync _|p, 0xFFFFFFFF;\n\t"
                 "selp.b32 %0, 1, 0, p;\n\t}" : "=r"(pred));
    return pred;
}
__device__ __forceinline__ void cp16(uint32_t dst, const void* src) {
    asm volatile("cp.async.cg.shared.global [%0], [%1], 16;" :: "r"(dst), "l"(src) : "memory");
}
#define CP_COMMIT() asm volatile("cp.async.commit_group;" ::: "memory")
#define CP_WAIT1()  asm volatile("cp.async.wait_group 1;" ::: "memory")

static __device__ constexpr uint64_t SMEM_DESC_BASE_SW128 =
    (uint64_t(2)  << 61) | (uint64_t(1) << 46) | (uint64_t(64) << 32) | (uint64_t(1) << 16);
__device__ __forceinline__ uint64_t make_desc(uint32_t addr) {
    return SMEM_DESC_BASE_SW128 | ((uint64_t)(addr >> 4) & 0x3FFF);
}
// tf32 SS idesc: dtype=F32(1<<4), a/btype=TF32(2<<7,2<<10), N/8<<17, M/16<<24
#define EDGE_IDESC 0x8400910u

#if HAS_TC
__device__ __forceinline__ void tc_mma_tf32_ss(uint32_t d_tmem, uint64_t a_desc,
                                               uint64_t b_desc, uint32_t idesc, bool accum) {
    uint32_t en = accum ? 1u : 0u;
    asm volatile(
        "{\n\t.reg .pred p;\n\t"
        "setp.ne.u32 p, %5, 0;\n\t"
        "tcgen05.mma.cta_group::1.kind::tf32 [%0], %1, %2, %3, {%4, %4, %4, %4}, p;\n\t}"
        :: "r"(d_tmem), "l"(a_desc), "l"(b_desc), "r"(idesc), "r"(0u), "r"(en)
        : "memory");
}
#define TC_ALLOC(smem_addr, n) \
    asm volatile("tcgen05.alloc.cta_group::1.sync.aligned.shared::cta.b32 [%0], %1;" \
                 :: "r"((uint32_t)(smem_addr)), "r"((uint32_t)(n)) : "memory")
#define TC_DEALLOC(tmem, n) \
    asm volatile("tcgen05.dealloc.cta_group::1.sync.aligned.b32 %0, %1;" :: "r"(tmem), "r"((uint32_t)(n)))
#define TC_RELINQ() asm volatile("tcgen05.relinquish_alloc_permit.cta_group::1.sync.aligned;")
#define TC_COMMIT(mbar) \
    asm volatile("tcgen05.commit.cta_group::1.mbarrier::arrive::one.shared::cluster.b64 [%0];" \
                 :: "r"((uint32_t)(mbar)) : "memory")
#define TC_FENCE_AFTER()  asm volatile("tcgen05.fence::after_thread_sync;" ::: "memory")
#define TC_WAIT_LD()      asm volatile("tcgen05.wait::ld.sync.aligned;" ::: "memory")
#define MBAR_INIT(addr, cnt) \
    asm volatile("mbarrier.init.shared.b64 [%0], %1;" :: "r"((uint32_t)(addr)), "r"((uint32_t)(cnt)) : "memory")
#define MBAR_INVAL(addr) \
    asm volatile("mbarrier.inval.shared.b64 [%0];" :: "r"((uint32_t)(addr)) : "memory")
#define FENCE_PROXY_ASYNC() asm volatile("fence.proxy.async.shared::cta;" ::: "memory")
__device__ __forceinline__ void mbar_wait_parity(uint32_t addr, uint32_t parity) {
    asm volatile(
        "{\n\t.reg .pred P1;\n\t"
        "WAIT_%=:\n\t"
        "mbarrier.try_wait.parity.acquire.cta.shared::cta.b64 P1, [%0], %1, 0x989680;\n\t"
        "@P1 bra.uni DONE_%=;\n\t"
        "bra.uni WAIT_%=;\n\t"
        "DONE_%=:\n\t}"
        :: "r"(addr), "r"(parity) : "memory");
}
#define LDTM_X32(r, addr) \
    asm volatile( \
        "tcgen05.ld.sync.aligned.32x32b.x32.b32 " \
        "{%0, %1, %2, %3, %4, %5, %6, %7, " \
        " %8, %9, %10, %11, %12, %13, %14, %15, " \
        " %16, %17, %18, %19, %20, %21, %22, %23, " \
        " %24, %25, %26, %27, %28, %29, %30, %31}, [%32];" \
        : "=r"((r)[0]),  "=r"((r)[1]),  "=r"((r)[2]),  "=r"((r)[3]), \
          "=r"((r)[4]),  "=r"((r)[5]),  "=r"((r)[6]),  "=r"((r)[7]), \
          "=r"((r)[8]),  "=r"((r)[9]),  "=r"((r)[10]), "=r"((r)[11]), \
          "=r"((r)[12]), "=r"((r)[13]), "=r"((r)[14]), "=r"((r)[15]), \
          "=r"((r)[16]), "=r"((r)[17]), "=r"((r)[18]), "=r"((r)[19]), \
          "=r"((r)[20]), "=r"((r)[21]), "=r"((r)[22]), "=r"((r)[23]), \
          "=r"((r)[24]), "=r"((r)[25]), "=r"((r)[26]), "=r"((r)[27]), \
          "=r"((r)[28]), "=r"((r)[29]), "=r"((r)[30]), "=r"((r)[31]) \
        : "r"(addr))
#endif // HAS_TC

// ------------------------- K0: prep (both transposes, rna-rounded) ----------
__global__ void prep_kernel(const float* __restrict__ We1, const float* __restrict__ Wn1) {
    __shared__ float t[32][33];
    int bz = blockIdx.x;
    if (bz < 64) {
        int bx = (bz & 7) * 32, by = (bz >> 3) * 32;
        t[threadIdx.y][threadIdx.x] = We1[(size_t)(by + threadIdx.y) * H_ + bx + threadIdx.x];
        __syncthreads();
        g_We1T[(size_t)(bx + threadIdx.y) * DE_ + by + threadIdx.x] =
            __uint_as_float(f2tf32(t[threadIdx.x][threadIdx.y]));
    } else {
        int i = bz - 64;
        int bx = (i & 7) * 32, by = (i >> 3) * 32;
        t[threadIdx.y][threadIdx.x] = Wn1[(size_t)(by + threadIdx.y) * H_ + bx + threadIdx.x];
        __syncthreads();
        g_Wn1T[(size_t)(bx + threadIdx.y) * DF_ + by + threadIdx.x] =
            __uint_as_float(f2tf32(t[threadIdx.x][threadIdx.y]));
    }
}

// ------------------------- K1: proj GEMM + fused gather + scalar dots -------
__global__ __launch_bounds__(256) void proj_mm_kernel(
        const float* __restrict__ Wn2, const float* __restrict__ We2,
        const float* __restrict__ bn2, const float* __restrict__ be2,
        const float* __restrict__ word_emb, const int* __restrict__ prog_in) {
    __shared__ float As[32][36];
    __shared__ float Ws[32][36];
    const int tid = threadIdx.x;
    const int m0 = blockIdx.x * 32, n0 = blockIdx.y * 32;
    const int r = tid >> 3, cg = tid & 7;
    const int lrow = tid >> 3, lk4 = (tid & 7) * 4;
    const int region = m0 >> 7;
    const float* W    = (region < 2) ? Wn2 : We2;
    const float* bias = (region < 2) ? bn2 : be2;
    const int lsel = (region == 0) ? 3 : (region == 1) ? 1 : 2;

    const int bq = (m0 + lrow) & 127;
    const float* qrow = word_emb + (size_t)prog_in[bq * L_ + lsel] * DV_;

    float acc[4] = {0.f, 0.f, 0.f, 0.f};
    float sacc = 0.f;

    for (int k0 = 0; k0 < DV_; k0 += 32) {
        float4 av = *(const float4*)(qrow + k0 + lk4);
        *(float4*)&As[lrow][lk4] = av;
        float4 wv = *(const float4*)(W + (size_t)(n0 + lrow) * DV_ + k0 + lk4);
        *(float4*)&Ws[lrow][lk4] = wv;
        if (n0 == 0) {
            float4 bv = *(const float4*)(bias + k0 + lk4);
            sacc += av.x*bv.x + av.y*bv.y + av.z*bv.z + av.w*bv.w;
        }
        __syncthreads();
        #pragma unroll
        for (int k = 0; k < 32; k++) {
            float a = As[r][k];
            acc[0] += a * Ws[cg*4+0][k];
            acc[1] += a * Ws[cg*4+1][k];
            acc[2] += a * Ws[cg*4+2][k];
            acc[3] += a * Ws[cg*4+3][k];
        }
        __syncthreads();
    }
    {
        int b = (m0 + r) & 127;
        float* U = (region == 0) ? g_u3 : (region == 1) ? g_u1 : g_v;
        #pragma unroll
        for (int u = 0; u < 4; u++) U[b * H_ + n0 + cg*4 + u] = acc[u];
    }
    if (n0 == 0) {
        sacc += __shfl_xor_sync(0xffffffffu, sacc, 1);
        sacc += __shfl_xor_sync(0xffffffffu, sacc, 2);
        sacc += __shfl_xor_sync(0xffffffffu, sacc, 4);
        if ((tid & 7) == 0) {
            float* cd = (region == 0) ? g_c3 : (region == 1) ? g_c1 : g_ce;
            cd[(m0 + lrow) & 127] = sacc;
        }
    }
}

// ------------------------- K2: edge GEMM, M=128/CTA, 2 CTAs/SM --------------
// grid 1296. Chunk = A 16KB + B 32KB = 48KB; 2 stages = 97KB dyn smem ->
// occupancy 2. cp.async feed, CP_WAIT1 top, post-MMA recycle wait.
#define EDGE_SMEM_DYN (1024 + 2*49152)
__global__ __launch_bounds__(256, 2)
void edge_tc2_kernel(const float* __restrict__ edge, const float* __restrict__ be1) {
#if HAS_TC
    extern __shared__ char dsm[];
    __shared__ uint32_t sh_tmem;
    __shared__ uint64_t sh_mbar[2];
    __shared__ float bs[256], vs0[256], vs1[256];
    __shared__ float s_part[256];
    __shared__ float ces[2];

    const int tid = threadIdx.x, warp = tid >> 5, lane = tid & 31;
    const int row0 = blockIdx.x * 128;

    const int b0 = row0 / ROWS_PER_B;
    const int bn_ = (b0 + 1 < B_) ? b0 + 1 : b0;
    const int split = (b0 + 1) * ROWS_PER_B - row0;

    uint32_t dbase = smem_u32(dsm);
    uint32_t aligned = (dbase + 1023u) & ~1023u;

    if (warp == 0) { TC_ALLOC(smem_u32(&sh_tmem), 256); TC_RELINQ(); }
    if (tid == 0) {
        MBAR_INIT(smem_u32(&sh_mbar[0]), 1);
        MBAR_INIT(smem_u32(&sh_mbar[1]), 1);
        ces[0] = g_ce[b0]; ces[1] = g_ce[bn_];
    }
    bs[tid]  = be1[tid];
    vs0[tid] = g_v[b0  * H_ + tid];
    vs1[tid] = g_v[bn_ * H_ + tid];
    __syncthreads();

    const uint32_t tmem = sh_tmem;
    uint32_t mb[2] = { smem_u32(&sh_mbar[0]), smem_u32(&sh_mbar[1]) };
    const float* Abase = edge + (size_t)row0 * DE_;

    const int rA = tid >> 3, cA = tid & 7;   // rA 0..31, cA 0..7

    auto load_chunk = [&](int j, int buf) {
        uint32_t st = aligned + (uint32_t)buf * 49152u;
        int k0 = j * 32;
        #pragma unroll
        for (int t = 0; t < 4; t++) {
            int r = rA + t*32;                           // 0..127
            uint32_t byte = (uint32_t)(r*128 + cA*16);
            cp16(st + (byte ^ ((byte>>3)&0x70u)), Abase + (size_t)r*DE_ + k0 + cA*4);
        }
        #pragma unroll
        for (int t = 0; t < 8; t++) {
            int n = rA + t*32;                           // 0..255
            uint32_t byte = (uint32_t)(n*128 + cA*16);
            cp16(st + 16384u + (byte ^ ((byte>>3)&0x70u)), g_We1T + (size_t)n*DE_ + k0 + cA*4);
        }
        CP_COMMIT();
    };

    load_chunk(0, 0); load_chunk(1, 1);

    #pragma unroll 1
    for (int c = 0; c < 8; c++) {
        const int buf = c & 1;
        CP_WAIT1();              // chunk c resident (only c+1 pending)
        FENCE_PROXY_ASYNC();
        __syncthreads();
        if (warp == 0) {
            if (elect_one_pred()) {
                uint32_t st = aligned + (uint32_t)buf * 49152u;
                uint64_t ad = make_desc(st);
                uint64_t bd = make_desc(st + 16384u);
                #pragma unroll
                for (int s = 0; s < 4; s++)
                    tc_mma_tf32_ss(tmem, ad + 2*s, bd + 2*s, EDGE_IDESC, (c > 0) || (s > 0));
                TC_COMMIT(mb[buf]);
            }
        }
        if (c + 2 < 8) {
            // buf is reused by chunk c+2; wait MMA(c) done reading it.
            mbar_wait_parity(mb[buf], (uint32_t)(c >> 1) & 1u);   // completion #(c/2+1)
            load_chunk(c + 2, buf);
        } else {
            CP_COMMIT();        // empty group keeps CP_WAIT1 aligned
        }
    }
    // mb0/mb1: 4 completions each; in-loop consumed #1..#3; #4 -> parity 1
    mbar_wait_parity(mb[0], 1u);
    mbar_wait_parity(mb[1], 1u);
    TC_FENCE_AFTER();

    // epilogue: 8 warps; row = (warp&3)*32+lane, half = warp>>2 covers 128 cols
    {
        const int half = warp >> 2;
        const int r = (warp & 3) * 32 + lane;
        const float* vrow = (r < split) ? vs0 : vs1;
        float s = 0.f;
        #pragma unroll
        for (int j = 0; j < 4; j++) {
            uint32_t d[32];
            int cbase = half*128 + j*32;
            LDTM_X32(d, tmem + cbase);
            TC_WAIT_LD();
            #pragma unroll
            for (int cc = 0; cc < 32; cc++) {
                int col = cbase + cc;
                float h = fmaxf(__uint_as_float(d[cc]) + bs[col], 0.f);
                s += h * vrow[col];
            }
        }
        s_part[half*128 + r] = s;
    }
    __syncthreads();
    if (tid < 128) {
        float tot = s_part[tid] + s_part[128 + tid];
        float ce = (tid < split) ? ces[0] : ces[1];
        g_weit[row0 + tid] = sigmoidf_((tot + ce) * SCALE_);
    }
    __syncthreads();
    if (tid == 0) { MBAR_INVAL(mb[0]); MBAR_INVAL(mb[1]); }
    if (warp == 0) TC_DEALLOC(tmem, 256);
#else
    (void)edge; (void)be1;
#endif
}

// ------------------------- K2b: edge GEMM via mma.sync (base-arch) ----------
#define BK_ 16
__global__ __launch_bounds__(512, 1) void edge_mma_kernel(
        const float* __restrict__ edge, const float* __restrict__ We1,
        const float* __restrict__ be1) {
#if !HAS_TC
    __shared__ unsigned As[128][20];
    __shared__ unsigned Bs[BK_][264];
    __shared__ float s_sh[128];
    __shared__ float bs[256], vs0[256], vs1[256];
    __shared__ float ces[2];

    const int tid  = threadIdx.x;
    const int warp = tid >> 5, lane = tid & 31;
    const int warpM = warp >> 2, warpN = warp & 3;
    const int g = lane >> 2, kq = lane & 3;
    const int row0 = blockIdx.x * 128;

    const int b0 = row0 / ROWS_PER_B;
    const int bn_ = (b0 + 1 < B_) ? b0 + 1 : b0;
    const int split = (b0 + 1) * ROWS_PER_B - row0;

    if (tid < 256) {
        bs[tid]  = be1[tid];
        vs0[tid] = g_v[b0  * H_ + tid];
        vs1[tid] = g_v[bn_ * H_ + tid];
    }
    if (tid < 128) s_sh[tid] = 0.f;
    if (tid == 0) { ces[0] = g_ce[b0]; ces[1] = g_ce[bn_]; }

    float acc[2][8][4];
    #pragma unroll
    for (int mt = 0; mt < 2; mt++)
        #pragma unroll
        for (int nt = 0; nt < 8; nt++)
            #pragma unroll
            for (int c = 0; c < 4; c++) acc[mt][nt][c] = 0.f;

    const int ra = tid >> 2, ca = tid & 3;
    const float* Abase = edge + (size_t)row0 * DE_;

    float4 pa;
    float4 pb[2];
    {
        pa = *(const float4*)(Abase + (size_t)ra * DE_ + ca*4);
        #pragma unroll
        for (int t = 0; t < 2; t++) {
            int i4 = tid + t*512; int kr = i4 >> 6, c4 = i4 & 63;
            pb[t] = *(const float4*)(We1 + (size_t)kr * 256 + c4*4);
        }
    }
    const int S = DE_ / BK_;
    for (int s = 0; s < S; s++) {
        *(uint4*)&As[ra][ca*4] = make_uint4(f2tf32(pa.x), f2tf32(pa.y), f2tf32(pa.z), f2tf32(pa.w));
        #pragma unroll
        for (int t = 0; t < 2; t++) {
            int i4 = tid + t*512; int kr = i4 >> 6, c4 = i4 & 63;
            *(uint4*)&Bs[kr][c4*4] = make_uint4(f2tf32(pb[t].x), f2tf32(pb[t].y), f2tf32(pb[t].z), f2tf32(pb[t].w));
        }
        __syncthreads();
        if (s + 1 < S) {
            int k0 = (s + 1) * BK_;
            pa = *(const float4*)(Abase + (size_t)ra * DE_ + k0 + ca*4);
            #pragma unroll
            for (int t = 0; t < 2; t++) {
                int i4 = tid + t*512; int kr = i4 >> 6, c4 = i4 & 63;
                pb[t] = *(const float4*)(We1 + (size_t)(k0 + kr) * 256 + c4*4);
            }
        }
        #pragma unroll
        for (int kk = 0; kk < 2; kk++) {
            unsigned af[2][4], bf[8][2];
            #pragma unroll
            for (int mt = 0; mt < 2; mt++) {
                int r = warpM*32 + mt*16 + g;
                af[mt][0] = As[r    ][kk*8 + kq];
                af[mt][1] = As[r + 8][kk*8 + kq];
                af[mt][2] = As[r    ][kk*8 + kq + 4];
                af[mt][3] = As[r + 8][kk*8 + kq + 4];
            }
            #pragma unroll
            for (int nt = 0; nt < 8; nt++) {
                int n = warpN*64 + nt*8 + g;
                bf[nt][0] = Bs[kk*8 + kq    ][n];
                bf[nt][1] = Bs[kk*8 + kq + 4][n];
            }
            #pragma unroll
            for (int mt = 0; mt < 2; mt++)
                #pragma unroll
                for (int nt = 0; nt < 8; nt++) mma_tf32(acc[mt][nt], af[mt], bf[nt]);
        }
        __syncthreads();
    }
    #pragma unroll
    for (int mt = 0; mt < 2; mt++) {
        int rA = warpM*32 + mt*16 + g;
        int rB = rA + 8;
        const float* vA = (rA < split) ? vs0 : vs1;
        const float* vB = (rB < split) ? vs0 : vs1;
        float pA = 0.f, pB = 0.f;
        #pragma unroll
        for (int nt = 0; nt < 8; nt++) {
            int n = warpN*64 + nt*8 + kq*2;
            float b0v = bs[n], b1v = bs[n+1];
            pA += fmaxf(acc[mt][nt][0] + b0v, 0.f) * vA[n]
                + fmaxf(acc[mt][nt][1] + b1v, 0.f) * vA[n+1];
            pB += fmaxf(acc[mt][nt][2] + b0v, 0.f) * vB[n]
                + fmaxf(acc[mt][nt][3] + b1v, 0.f) * vB[n+1];
        }
        pA += __shfl_xor_sync(0xffffffffu, pA, 1);
        pA += __shfl_xor_sync(0xffffffffu, pA, 2);
        pB += __shfl_xor_sync(0xffffffffu, pB, 1);
        pB += __shfl_xor_sync(0xffffffffu, pB, 2);
        if (kq == 0) {
            atomicAdd(&s_sh[rA], pA);
            atomicAdd(&s_sh[rB], pB);
        }
    }
    __syncthreads();
    if (tid < 128) {
        float ce = (tid < split) ? ces[0] : ces[1];
        g_weit[row0 + tid] = sigmoidf_((s_sh[tid] + ce) * SCALE_);
    }
#else
    (void)edge; (void)We1; (void)be1;
#endif
}

// ------------------------- K3: node MLP1, cp.async 2-stage + FUSED score ----
// M=128/CTA (36 CTAs), K=512 (16 chunks of 32), N=256. Same pipeline as edge.
#define NODE_SMEM_DYN (1024 + 2*49152)
__global__ __launch_bounds__(256, 2)
void node_tc_kernel(const float* __restrict__ node, const float* __restrict__ bn1) {
#if HAS_TC
    extern __shared__ char dsm[];
    __shared__ uint32_t sh_tmem;
    __shared__ uint64_t sh_mbar[2];
    __shared__ float bs[256];
    __shared__ float sd3[128], sd1[128];

    const int tid = threadIdx.x, warp = tid >> 5, lane = tid & 31;
    const int row0 = blockIdx.x * 128;

    uint32_t dbase = smem_u32(dsm);
    uint32_t aligned = (dbase + 1023u) & ~1023u;

    if (warp == 0) { TC_ALLOC(smem_u32(&sh_tmem), 256); TC_RELINQ(); }
    if (tid == 0) {
        MBAR_INIT(smem_u32(&sh_mbar[0]), 1);
        MBAR_INIT(smem_u32(&sh_mbar[1]), 1);
    }
    bs[tid] = bn1[tid];
    __syncthreads();

    const uint32_t tmem = sh_tmem;
    uint32_t mb[2] = { smem_u32(&sh_mbar[0]), smem_u32(&sh_mbar[1]) };
    const float* Abase = node + (size_t)row0 * DF_;

    const int rA = tid >> 3, cA = tid & 7;

    auto load_chunk = [&](int j, int buf) {
        uint32_t st = aligned + (uint32_t)buf * 49152u;
        int k0 = j * 32;
        #pragma unroll
        for (int t = 0; t < 4; t++) {
            int r = rA + t*32;
            uint32_t byte = (uint32_t)(r*128 + cA*16);
            cp16(st + (byte ^ ((byte>>3)&0x70u)), Abase + (size_t)r*DF_ + k0 + cA*4);
        }
        #pragma unroll
        for (int t = 0; t < 8; t++) {
            int n = rA + t*32;
            uint32_t byte = (uint32_t)(n*128 + cA*16);
            cp16(st + 16384u + (byte ^ ((byte>>3)&0x70u)), g_Wn1T + (size_t)n*DF_ + k0 + cA*4);
        }
        CP_COMMIT();
    };

    load_chunk(0, 0); load_chunk(1, 1);

    #pragma unroll 1
    for (int c = 0; c < 16; c++) {
        const int buf = c & 1;
        CP_WAIT1();
        FENCE_PROXY_ASYNC();
        __syncthreads();
        if (warp == 0) {
            if (elect_one_pred()) {
                uint32_t st = aligned + (uint32_t)buf * 49152u;
                uint64_t ad = make_desc(st);
                uint64_t bd = make_desc(st + 16384u);
                #pragma unroll
                for (int s = 0; s < 4; s++)
                    tc_mma_tf32_ss(tmem, ad + 2*s, bd + 2*s, EDGE_IDESC, (c > 0) || (s > 0));
                TC_COMMIT(mb[buf]);
            }
        }
        if (c + 2 < 16) {
            mbar_wait_parity(mb[buf], (uint32_t)(c >> 1) & 1u);
            load_chunk(c + 2, buf);
        } else {
            CP_COMMIT();
        }
    }
    // mb0/mb1: 8 completions each; in-loop consumed #1..#7; #8 -> parity 1
    mbar_wait_parity(mb[0], 1u);
    mbar_wait_parity(mb[1], 1u);
    TC_FENCE_AFTER();

    // epilogue: store hn + fused score partial dots
    {
        const int half = warp >> 2;
        const int lr = (warp & 3) * 32 + lane;
        const int grow = row0 + lr;
        const int b = grow / N_;
        const int colbase = half * 128;
        float* dst = g_hn + (size_t)grow * H_;
        const float* u3r = g_u3 + b * H_;
        const float* u1r = g_u1 + b * H_;
        float d3 = 0.f, d1 = 0.f;
        #pragma unroll
        for (int it = 0; it < 4; it++) {
            uint32_t d[32];
            int cb = colbase + it*32;
            LDTM_X32(d, tmem + cb);
            TC_WAIT_LD();
            #pragma unroll
            for (int k = 0; k < 8; k++) {
                int n = cb + k*4;
                float4 o;
                o.x = fmaxf(__uint_as_float(d[k*4+0]) + bs[n+0], 0.f);
                o.y = fmaxf(__uint_as_float(d[k*4+1]) + bs[n+1], 0.f);
                o.z = fmaxf(__uint_as_float(d[k*4+2]) + bs[n+2], 0.f);
                o.w = fmaxf(__uint_as_float(d[k*4+3]) + bs[n+3], 0.f);
                *(float4*)(dst + n) = o;
                float4 u3v = *(const float4*)(u3r + n);
                float4 u1v = *(const float4*)(u1r + n);
                d3 += o.x*u3v.x + o.y*u3v.y + o.z*u3v.z + o.w*u3v.w;
                d1 += o.x*u1v.x + o.y*u1v.y + o.z*u1v.z + o.w*u1v.w;
            }
        }
        if (half == 0) { sd3[lr] = d3; sd1[lr] = d1; }
        __syncthreads();
        if (half == 1) {
            float t3 = sd3[lr] + d3, t1 = sd1[lr] + d1;
            g_a1[grow]   = sigmoidf_((t3 + g_c3[b]) * SCALE_);
            g_sig1[grow] = sigmoidf_((t1 + g_c1[b]) * SCALE_);
        }
    }
    __syncthreads();
    if (tid == 0) { MBAR_INVAL(mb[0]); MBAR_INVAL(mb[1]); }
    if (warp == 0) TC_DEALLOC(tmem, 256);
#else
    (void)node; (void)bn1;
#endif
}

// ------------------------- K3b: node MLP1 via mma.sync (base-arch) ----------
__global__ __launch_bounds__(512, 1) void node_mma_kernel(
        const float* __restrict__ node, const float* __restrict__ Wn1,
        const float* __restrict__ bn1) {
#if !HAS_TC
    __shared__ unsigned As[128][20];
    __shared__ unsigned Bs[BK_][264];
    __shared__ float bs[256];

    const int tid  = threadIdx.x;
    const int warp = tid >> 5, lane = tid & 31;
    const int warpM = warp >> 2, warpN = warp & 3;
    const int g = lane >> 2, kq = lane & 3;
    const int row0 = blockIdx.x * 128;

    if (tid < 256) bs[tid] = bn1[tid];

    float acc[2][8][4];
    #pragma unroll
    for (int mt = 0; mt < 2; mt++)
        #pragma unroll
        for (int nt = 0; nt < 8; nt++)
            #pragma unroll
            for (int c = 0; c < 4; c++) acc[mt][nt][c] = 0.f;

    const int ra = tid >> 2, ca = tid & 3;
    const float* Abase = node + (size_t)row0 * DF_;

    float4 pa;
    float4 pb[2];
    {
        pa = *(const float4*)(Abase + (size_t)ra * DF_ + ca*4);
        #pragma unroll
        for (int t = 0; t < 2; t++) {
            int i4 = tid + t*512; int kr = i4 >> 6, c4 = i4 & 63;
            pb[t] = *(const float4*)(Wn1 + (size_t)kr * H_ + c4*4);
        }
    }
    const int S = DF_ / BK_;
    for (int s = 0; s < S; s++) {
        *(uint4*)&As[ra][ca*4] = make_uint4(f2tf32(pa.x), f2tf32(pa.y), f2tf32(pa.z), f2tf32(pa.w));
        #pragma unroll
        for (int t = 0; t < 2; t++) {
            int i4 = tid + t*512; int kr = i4 >> 6, c4 = i4 & 63;
            *(uint4*)&Bs[kr][c4*4] = make_uint4(f2tf32(pb[t].x), f2tf32(pb[t].y), f2tf32(pb[t].z), f2tf32(pb[t].w));
        }
        __syncthreads();
        if (s + 1 < S) {
            int k0 = (s + 1) * BK_;
            pa = *(const float4*)(Abase + (size_t)ra * DF_ + k0 + ca*4);
            #pragma unroll
            for (int t = 0; t < 2; t++) {
                int i4 = tid + t*512; int kr = i4 >> 6, c4 = i4 & 63;
                pb[t] = *(const float4*)(Wn1 + (size_t)(k0 + kr) * H_ + c4*4);
            }
        }
        #pragma unroll
        for (int kk = 0; kk < 2; kk++) {
            unsigned af[2][4], bf[8][2];
            #pragma unroll
            for (int mt = 0; mt < 2; mt++) {
                int r = warpM*32 + mt*16 + g;
                af[mt][0] = As[r    ][kk*8 + kq];
                af[mt][1] = As[r + 8][kk*8 + kq];
                af[mt][2] = As[r    ][kk*8 + kq + 4];
                af[mt][3] = As[r + 8][kk*8 + kq + 4];
            }
            #pragma unroll
            for (int nt = 0; nt < 8; nt++) {
                int n = warpN*64 + nt*8 + g;
                bf[nt][0] = Bs[kk*8 + kq    ][n];
                bf[nt][1] = Bs[kk*8 + kq + 4][n];
            }
            #pragma unroll
            for (int mt = 0; mt < 2; mt++)
                #pragma unroll
                for (int nt = 0; nt < 8; nt++) mma_tf32(acc[mt][nt], af[mt], bf[nt]);
        }
        __syncthreads();
    }
    #pragma unroll
    for (int mt = 0; mt < 2; mt++) {
        int rA = row0 + warpM*32 + mt*16 + g;
        int rB = rA + 8;
        #pragma unroll
        for (int nt = 0; nt < 8; nt++) {
            int n = warpN*64 + nt*8 + kq*2;
            float b0v = bs[n], b1v = bs[n+1];
            float2 v0 = make_float2(fmaxf(acc[mt][nt][0] + b0v, 0.f), fmaxf(acc[mt][nt][1] + b1v, 0.f));
            float2 v1 = make_float2(fmaxf(acc[mt][nt][2] + b0v, 0.f), fmaxf(acc[mt][nt][3] + b1v, 0.f));
            *(float2*)&g_hn[(size_t)rA * H_ + n] = v0;
            *(float2*)&g_hn[(size_t)rB * H_ + n] = v1;
        }
    }
#else
    (void)node; (void)Wn1; (void)bn1;
#endif
}

// ------------------------- K4: filter scores (base path only) ---------------
__global__ void score_kernel() {
    int gw = (blockIdx.x * 256 + threadIdx.x) >> 5;
    int lane = threadIdx.x & 31;
    if (gw >= NODE_ROWS) return;
    int b = gw / N_;
    const float* h  = g_hn + (size_t)gw * H_;
    const float* u3 = g_u3 + b * H_;
    const float* u1 = g_u1 + b * H_;
    float d3 = 0.f, d1 = 0.f;
    #pragma unroll
    for (int t = 0; t < 8; t++) {
        int d = lane + t*32;
        float hv = h[d];
        d3 += hv * u3[d];
        d1 += hv * u1[d];
    }
    #pragma unroll
    for (int o = 16; o > 0; o >>= 1) {
        d3 += __shfl_xor_sync(0xffffffffu, d3, o);
        d1 += __shfl_xor_sync(0xffffffffu, d1, o);
    }
    if (lane == 0) {
        g_a1[gw]   = sigmoidf_((d3 + g_c3[b]) * SCALE_);
        g_sig1[gw] = sigmoidf_((d1 + g_c1[b]) * SCALE_);
    }
}

// ------------------------- K5: attention chain + pooled hidden --------------
__global__ void combine_kernel() {
    int b = blockIdx.x;
    int tid = threadIdx.x;
    __shared__ float a1s[N_];
    __shared__ float a3s[N_];
    __shared__ float sInv, sS;
    if (tid < N_) a1s[tid] = g_a1[b * N_ + tid];
    __syncthreads();
    if (tid < N_) {
        int j = tid;
        float acc = 0.f;
        const float* w = g_weit + (size_t)b * ROWS_PER_B;
        #pragma unroll
        for (int i = 0; i < N_; i++) acc += a1s[i] * w[i * N_ + j];
        acc = fminf(fmaxf(acc, 0.f), 1.f);
        a3s[j] = acc * g_sig1[b * N_ + j];
    }
    __syncthreads();
    if (tid == 0) {
        float s0 = 0.f;
        #pragma unroll
        for (int j = 0; j < N_; j++) s0 += a3s[j];
        float inv = 1.f / (s0 + 1e-8f);
        sInv = inv;
        sS = s0 * inv;
    }
    __syncthreads();
    {
        int h = tid;
        float acc = 0.f;
        #pragma unroll
        for (int j = 0; j < N_; j++)
            acc += a3s[j] * g_hn[((size_t)(b * N_ + j)) * H_ + h];
        g_ph[b * H_ + h] = acc * sInv;
    }
    if (tid == 0) g_S[b] = sS;
}

// ------------------------- K6: final chain, 32x32 tiled GEMM stages ---------
__global__ __launch_bounds__(256) void final_mm_kernel(
        int stage, const float* __restrict__ W, const float* __restrict__ bias,
        const float* __restrict__ word_emb, const int* __restrict__ prog_in,
        float* __restrict__ outp) {
    __shared__ float As[32][36];
    __shared__ float Ws[32][36];

    const float* A; float* C; int N, K, mode;
    if (stage == 0)      { A = g_ph;   C = g_gbuf; N = DV_; K = H_;  mode = 1; }
    else if (stage == 1) { A = g_gbuf; C = g_obuf; N = DV_; K = DV_; mode = 0; }
    else if (stage == 2) { A = g_obuf; C = g_h2;   N = H_;  K = DV_; mode = 0; }
    else                 { A = g_h2;   C = outp;   N = NC_; K = H_;  mode = 2; }

    const int tid = threadIdx.x;
    const int m0 = blockIdx.x * 32, n0 = blockIdx.y * 32;
    const int r = tid >> 3, cg = tid & 7;
    float acc[4] = {0.f, 0.f, 0.f, 0.f};

    const int lrow = tid >> 3, lk4 = (tid & 7) * 4;
    for (int k0 = 0; k0 < K; k0 += 32) {
        float4 av = *(const float4*)(A + (size_t)(m0 + lrow) * K + k0 + lk4);
        *(float4*)&As[lrow][lk4] = av;
        #pragma unroll
        for (int u = 0; u < 4; u++) {
            int n = n0 + lk4 + u;
            Ws[lrow][lk4 + u] = (n < N) ? W[(size_t)(k0 + lrow) * N + n] : 0.f;
        }
        __syncthreads();
        #pragma unroll
        for (int k = 0; k < 32; k++) {
            float a = As[r][k];
            acc[0] += a * Ws[k][cg*4+0]; acc[1] += a * Ws[k][cg*4+1];
            acc[2] += a * Ws[k][cg*4+2]; acc[3] += a * Ws[k][cg*4+3];
        }
        __syncthreads();
    }
    const int row = m0 + r;
    int w0 = (mode == 1) ? prog_in[row * L_ + 0] : 0;
    #pragma unroll
    for (int u = 0; u < 4; u++) {
        int n = n0 + cg*4 + u;
        if (n >= N) continue;
        float x = acc[u];
        if (mode == 0)      x = fmaxf(x + bias[n], 0.f);
        else if (mode == 1) x = (x + g_S[row] * bias[n]) * word_emb[(size_t)w0 * DV_ + n];
        else                x = x + bias[n];
        C[(size_t)row * N + n] = x;
    }
}

// ------------------------- launch ------------------------------------------
extern "C" void kernel_launch(void* const* d_in, const int* in_sizes, int n_in,
                              void* d_out, int out_size) {
    const float* node     = (const float*)d_in[0];
    const float* edge     = (const float*)d_in[1];
    const float* Wn1      = (const float*)d_in[2];
    const float* bn1      = (const float*)d_in[3];
    const float* Wn2      = (const float*)d_in[4];
    const float* bn2      = (const float*)d_in[5];
    const float* We1      = (const float*)d_in[6];
    const float* be1      = (const float*)d_in[7];
    const float* We2      = (const float*)d_in[8];
    const float* be2      = (const float*)d_in[9];
    const float* Wq       = (const float*)d_in[10];
    const float* bq       = (const float*)d_in[11];
    const float* Wc1      = (const float*)d_in[12];
    const float* bc1      = (const float*)d_in[13];
    const float* Wc2      = (const float*)d_in[14];
    const float* bc2      = (const float*)d_in[15];
    const float* word_emb = (const float*)d_in[16];
    const int* prog_in    = (const int*)d_in[18];
    float* out            = (float*)d_out;

    static int cc_major = -1;
    if (cc_major < 0) {
        int dev = 0;
        cudaGetDevice(&dev);
        cudaDeviceGetAttribute(&cc_major, cudaDevAttrComputeCapabilityMajor, dev);
        cudaFuncSetAttribute(edge_tc2_kernel,
                             cudaFuncAttributeMaxDynamicSharedMemorySize, EDGE_SMEM_DYN);
        cudaFuncSetAttribute(node_tc_kernel,
                             cudaFuncAttributeMaxDynamicSharedMemorySize, NODE_SMEM_DYN);
    }
    const bool tc = (cc_major >= 10);

    prep_kernel<<<192, dim3(32, 32)>>>(We1, Wn1);
    proj_mm_kernel<<<dim3(12, 8), 256>>>(Wn2, We2, bn2, be2, word_emb, prog_in);

    if (tc) {
        edge_tc2_kernel<<<EDGE_ROWS/128, 256, EDGE_SMEM_DYN>>>(edge, be1);
        node_tc_kernel<<<NODE_ROWS/128, 256, NODE_SMEM_DYN>>>(node, bn1);
    } else {
        edge_mma_kernel<<<EDGE_ROWS/128, 512>>>(edge, We1, be1);
        node_mma_kernel<<<NODE_ROWS/128, 512>>>(node, Wn1, bn1);
        score_kernel<<<NODE_ROWS/8, 256>>>();
    }

    combine_kernel<<<B_, 256>>>();

    final_mm_kernel<<<dim3(4, 16), 256>>>(0, Wn2, bn2, word_emb, prog_in, out);
    final_mm_kernel<<<dim3(4, 16), 256>>>(1, Wq,  bq,  word_emb, prog_in, out);
    final_mm_kernel<<<dim3(4, 8),  256>>>(2, Wc1, bc1, word_emb, prog_in, out);
    final_mm_kernel<<<dim3(4, 1),  256>>>(3, Wc2, bc2, word_emb, prog_in, out);
}